// round 4
// baseline (speedup 1.0000x reference)
#include <cuda_runtime.h>
#include <math.h>

#define N     8192
#define FIN   64
#define HID   64
#define HEADS 2
#define C     16

// ---------------- scratch (static device globals; no allocation) ----------------
__device__ float g_Wh[HEADS][N][HID];      // 4 MB   per-head Wh = x @ W_h
__device__ float g_u[HEADS][N], g_v[HEADS][N];
__device__ float g_A[HEADS][N], g_A5K[HEADS][N], g_B[HEADS][N], g_B5[HEADS][N];
__device__ float g_h[N][HEADS * HID];      // 4 MB   concat of layer-1 head outputs
__device__ float g_Wh2[N][C];
__device__ float g_u2[N], g_v2[N];
__device__ float g_A2[N], g_A5K2[N], g_B2[N], g_B52[N];
__device__ float g_max[8];                 // [0]=u1max [1]=v1max [2]=u2max [3]=v2max [4]=uo [5]=vo

// ---------------- K1: Wh_h = x @ W_h  (64-row tiles) ----------------
__global__ void k_gemm1(const float* __restrict__ x, const float* __restrict__ W_heads) {
    __shared__ float xs[64][FIN];    // 16 KB
    __shared__ float ws[FIN][HID];   // 16 KB
    const int h  = blockIdx.y;
    const int i0 = blockIdx.x * 64;
    const int tid = threadIdx.x;     // 256

    const float4* xg = (const float4*)(x + (size_t)i0 * FIN);
    const float4* wg = (const float4*)(W_heads + (size_t)h * FIN * HID);
#pragma unroll
    for (int it = 0; it < 4; it++) ((float4*)xs)[tid + it * 256] = xg[tid + it * 256];
#pragma unroll
    for (int it = 0; it < 4; it++) ((float4*)ws)[tid + it * 256] = wg[tid + it * 256];
    __syncthreads();

    const int f  = (tid & 15) * 4;
    const int ig = tid >> 4;         // 0..15 -> rows ig*4 ..
    float acc[4][4] = {};
#pragma unroll 4
    for (int k = 0; k < FIN; k++) {
        float4 wv = *(const float4*)&ws[k][f];
#pragma unroll
        for (int r = 0; r < 4; r++) {
            float xv = xs[ig * 4 + r][k];
            acc[r][0] = fmaf(xv, wv.x, acc[r][0]);
            acc[r][1] = fmaf(xv, wv.y, acc[r][1]);
            acc[r][2] = fmaf(xv, wv.z, acc[r][2]);
            acc[r][3] = fmaf(xv, wv.w, acc[r][3]);
        }
    }
#pragma unroll
    for (int r = 0; r < 4; r++)
        *(float4*)&g_Wh[h][i0 + ig * 4 + r][f] =
            make_float4(acc[r][0], acc[r][1], acc[r][2], acc[r][3]);
}

// ---------------- K2: u_i = Wh_i . a[:H], v_i = Wh_i . a[H:] ----------------
__global__ void k_uv1(const float* __restrict__ a_heads) {
    const int h    = blockIdx.y;
    const int wid  = threadIdx.x >> 5, lane = threadIdx.x & 31;
    const int i    = blockIdx.x * 8 + wid;
    const float* a   = a_heads + (size_t)h * 2 * HID;
    const float* whr = &g_Wh[h][i][0];
    float pu = fmaf(whr[lane], a[lane], whr[lane + 32] * a[lane + 32]);
    float pv = fmaf(whr[lane], a[HID + lane], whr[lane + 32] * a[HID + lane + 32]);
#pragma unroll
    for (int o = 16; o; o >>= 1) {
        pu += __shfl_xor_sync(0xffffffffu, pu, o);
        pv += __shfl_xor_sync(0xffffffffu, pv, o);
    }
    if (lane == 0) { g_u[h][i] = pu; g_v[h][i] = pv; }
}

// ---------------- K3: global max of u/v arrays ----------------
__global__ void k_max(int base) {
    const int which = base + blockIdx.x;
    const float* src =
        (which == 0) ? g_u[0] : (which == 1) ? g_v[0] :
        (which == 2) ? g_u[1] : (which == 3) ? g_v[1] :
        (which == 4) ? g_u2   : g_v2;
    __shared__ float red[32];
    float m = -3.0e38f;
    for (int i = threadIdx.x; i < N; i += blockDim.x) m = fmaxf(m, src[i]);
#pragma unroll
    for (int o = 16; o; o >>= 1) m = fmaxf(m, __shfl_xor_sync(0xffffffffu, m, o));
    if ((threadIdx.x & 31) == 0) red[threadIdx.x >> 5] = m;
    __syncthreads();
    if (threadIdx.x < 32) {
        float mm = red[threadIdx.x];
#pragma unroll
        for (int o = 16; o; o >>= 1) mm = fmaxf(mm, __shfl_xor_sync(0xffffffffu, mm, o));
        if (threadIdx.x == 0) g_max[which] = mm;
    }
}

// ---------------- K4: exp tables (layer 1) ----------------
__global__ void k_exp1() {
    const int i = blockIdx.x * 256 + threadIdx.x;
    const int h = blockIdx.y;
    const float um = g_max[h * 2 + 0], vm = g_max[h * 2 + 1];
    const float c = um + vm;
    const float u = g_u[h][i], v = g_v[h][i];
    g_A[h][i]   = expf(u - um);
    g_A5K[h][i] = expf(0.2f * (u - um) - 0.8f * c);
    g_B[h][i]   = expf(v - vm);
    g_B5[h][i]  = expf(0.2f * (v - vm));
}

// ---------------- K5: layer-1 attention (2 heads fused), 64 rows / block ----------------
__launch_bounds__(256, 1)
__global__ void k_attn1(const int* __restrict__ adj) {
    __shared__ float w1s[64][32];      // 8 KB
    __shared__ float w2s[64][32];      // 8 KB
    __shared__ float whs[32][128];     // 16 KB  (head-concat Wh tile)
    __shared__ float rowd[6][64];      // u1,A1,A5K1,u2,A2,A5K2

    const int tid = threadIdx.x;
    const int wb = tid >> 5, lane = tid & 31;
    const int i0 = blockIdx.x * 64;
    const int head = lane >> 4;        // lanes 0-15: head0 feats, 16-31: head1 feats

    if (tid < 64) {
        rowd[0][tid] = g_u[0][i0 + tid];
        rowd[1][tid] = g_A[0][i0 + tid];
        rowd[2][tid] = g_A5K[0][i0 + tid];
        rowd[3][tid] = g_u[1][i0 + tid];
        rowd[4][tid] = g_A[1][i0 + tid];
        rowd[5][tid] = g_A5K[1][i0 + tid];
    }

    float acc[8][4] = {};
    float Zp1[8] = {}, Zp2[8] = {};

    int   adjv[8];
    float4 whv[4];
    float v1j, B1j, B51j, v2j, B2j, B52j;

    const int rowbase = i0 + wb * 8;

    // prefetch tile 0
    {
        const int j0 = 0, jc = j0 + lane;
#pragma unroll
        for (int r = 0; r < 8; r++) adjv[r] = adj[(rowbase + r) * N + jc];
        v1j = g_v[0][jc]; B1j = g_B[0][jc]; B51j = g_B5[0][jc];
        v2j = g_v[1][jc]; B2j = g_B[1][jc]; B52j = g_B5[1][jc];
#pragma unroll
        for (int it = 0; it < 4; it++) {
            int idx = tid + it * 256;
            int jj = idx >> 5, ff = (idx & 31) * 4;
            const float* src = (ff < 64) ? &g_Wh[0][j0 + jj][ff] : &g_Wh[1][j0 + jj][ff - 64];
            whv[it] = *(const float4*)src;
        }
    }

    const float* wsel = head ? &w2s[0][0] : &w1s[0][0];
    const float* wrow = wsel + wb * 8 * 32;
    const float* whp  = &whs[0][0] + (lane << 2);

    const int T = N / 32;  // 256 tiles
    for (int t = 0; t < T; t++) {
        __syncthreads();   // prev phase-B done; SMEM free

        // ---- phase A: stage Wh tile + materialize w tiles ----
#pragma unroll
        for (int it = 0; it < 4; it++) {
            int idx = tid + it * 256;
            int jj = idx >> 5, ff = (idx & 31) * 4;
            *(float4*)&whs[jj][ff] = whv[it];
        }
#pragma unroll
        for (int r = 0; r < 8; r++) {
            const int r8 = wb * 8 + r;
            const bool m = (adjv[r] != 0);
            float w1 = 0.f, w2 = 0.f;
            if (m) {
                w1 = (rowd[0][r8] + v1j > 0.f) ? rowd[1][r8] * B1j : rowd[2][r8] * B51j;
                w2 = (rowd[3][r8] + v2j > 0.f) ? rowd[4][r8] * B2j : rowd[5][r8] * B52j;
            }
            w1s[r8][lane] = w1; Zp1[r] += w1;
            w2s[r8][lane] = w2; Zp2[r] += w2;
        }

        // ---- prefetch t+1 (overlaps phase B) ----
        if (t + 1 < T) {
            const int j0 = (t + 1) * 32, jc = j0 + lane;
#pragma unroll
            for (int r = 0; r < 8; r++) adjv[r] = adj[(rowbase + r) * N + jc];
            v1j = g_v[0][jc]; B1j = g_B[0][jc]; B51j = g_B5[0][jc];
            v2j = g_v[1][jc]; B2j = g_B[1][jc]; B52j = g_B5[1][jc];
#pragma unroll
            for (int it = 0; it < 4; it++) {
                int idx = tid + it * 256;
                int jj = idx >> 5, ff = (idx & 31) * 4;
                const float* src = (ff < 64) ? &g_Wh[0][j0 + jj][ff] : &g_Wh[1][j0 + jj][ff - 64];
                whv[it] = *(const float4*)src;
            }
        }

        __syncthreads();   // w/wh tiles ready

        // ---- phase B: acc[8 rows][4 feats] += w * Wh ----
#pragma unroll 8
        for (int jj = 0; jj < 32; jj++) {
            float4 wh = *(const float4*)(whp + (jj << 7));
#pragma unroll
            for (int r = 0; r < 8; r++) {
                float w = wrow[(r << 5) + jj];
                acc[r][0] = fmaf(w, wh.x, acc[r][0]);
                acc[r][1] = fmaf(w, wh.y, acc[r][1]);
                acc[r][2] = fmaf(w, wh.z, acc[r][2]);
                acc[r][3] = fmaf(w, wh.w, acc[r][3]);
            }
        }
    }

    // ---- epilogue: reduce Z, normalize, write h_cat ----
#pragma unroll
    for (int r = 0; r < 8; r++) {
#pragma unroll
        for (int o = 16; o; o >>= 1) {
            Zp1[r] += __shfl_xor_sync(0xffffffffu, Zp1[r], o);
            Zp2[r] += __shfl_xor_sync(0xffffffffu, Zp2[r], o);
        }
    }
#pragma unroll
    for (int r = 0; r < 8; r++) {
        float Z = head ? Zp2[r] : Zp1[r];
        float inv = 1.0f / Z;
        *(float4*)&g_h[rowbase + r][lane * 4] =
            make_float4(acc[r][0] * inv, acc[r][1] * inv, acc[r][2] * inv, acc[r][3] * inv);
    }
}

// ---------------- K6: Wh2 = h_cat @ W_out ----------------
__global__ void k_gemm2(const float* __restrict__ W_out) {
    __shared__ float hs[16][HEADS * HID];  // 8 KB
    __shared__ float ws[HEADS * HID][C];   // 8 KB
    const int tid = threadIdx.x;
    const int i0 = blockIdx.x * 16;
#pragma unroll
    for (int it = 0; it < 2; it++)
        ((float4*)hs)[tid + it * 256] = ((const float4*)&g_h[i0][0])[tid + it * 256];
#pragma unroll
    for (int it = 0; it < 2; it++)
        ((float4*)ws)[tid + it * 256] = ((const float4*)W_out)[tid + it * 256];
    __syncthreads();
    const int r = tid >> 4, f = tid & 15;
    float acc = 0.f;
#pragma unroll 8
    for (int k = 0; k < HEADS * HID; k++) acc = fmaf(hs[r][k], ws[k][f], acc);
    g_Wh2[i0 + r][f] = acc;
}

// ---------------- K7: u2/v2 ----------------
__global__ void k_uv2(const float* __restrict__ a_out) {
    const int wid = threadIdx.x >> 5, lane = threadIdx.x & 31;
    const int i = blockIdx.x * 8 + wid;
    float pu = 0.f, pv = 0.f;
    if (lane < C) {
        float wh = g_Wh2[i][lane];
        pu = wh * a_out[lane];
        pv = wh * a_out[C + lane];
    }
#pragma unroll
    for (int o = 16; o; o >>= 1) {
        pu += __shfl_xor_sync(0xffffffffu, pu, o);
        pv += __shfl_xor_sync(0xffffffffu, pv, o);
    }
    if (lane == 0) { g_u2[i] = pu; g_v2[i] = pv; }
}

// ---------------- K8: exp tables (output layer) ----------------
__global__ void k_exp2() {
    const int i = blockIdx.x * 256 + threadIdx.x;
    const float um = g_max[4], vm = g_max[5], c = um + vm;
    const float u = g_u2[i], v = g_v2[i];
    g_A2[i]   = expf(u - um);
    g_A5K2[i] = expf(0.2f * (u - um) - 0.8f * c);
    g_B2[i]   = expf(v - vm);
    g_B52[i]  = expf(0.2f * (v - vm));
}

// ---------------- K9: output attention + elu + log_softmax ----------------
__launch_bounds__(256, 1)
__global__ void k_attn2(const int* __restrict__ adj, float* __restrict__ out) {
    __shared__ float wS[64][64];     // 16 KB
    __shared__ float whs[64][C];     // 4 KB
    __shared__ float rowd[3][64];    // u2, A2, A5K2
    __shared__ float Zs[64];
    __shared__ float os[64][C + 1];
    __shared__ float lse[64];

    const int tid = threadIdx.x;
    const int wb = tid >> 5, lane = tid & 31;
    const int i0 = blockIdx.x * 64;
    const int fcol = tid & 15;
    const int ig = tid >> 4;           // 0..15 -> rows ig*4..
    const int rowbase = i0 + wb * 8;

    if (tid < 64) {
        rowd[0][tid] = g_u2[i0 + tid];
        rowd[1][tid] = g_A2[i0 + tid];
        rowd[2][tid] = g_A5K2[i0 + tid];
    }

    float acc[4] = {};
    float Zp[8] = {};

    int adjv[16];
    float vj[2], Bj[2], B5j[2];
    float4 whv;

    // prefetch tile 0
    {
        const int j0 = 0;
#pragma unroll
        for (int r = 0; r < 8; r++) {
            adjv[r * 2 + 0] = adj[(rowbase + r) * N + j0 + lane];
            adjv[r * 2 + 1] = adj[(rowbase + r) * N + j0 + 32 + lane];
        }
        int jc0 = j0 + lane, jc1 = j0 + 32 + lane;
        vj[0] = g_v2[jc0]; Bj[0] = g_B2[jc0]; B5j[0] = g_B52[jc0];
        vj[1] = g_v2[jc1]; Bj[1] = g_B2[jc1]; B5j[1] = g_B52[jc1];
        int jj = tid >> 2, ff = (tid & 3) * 4;
        whv = *(const float4*)&g_Wh2[j0 + jj][ff];
    }

    const int T = N / 64;  // 128 tiles
    for (int t = 0; t < T; t++) {
        __syncthreads();

        // phase A
        {
            int jj = tid >> 2, ff = (tid & 3) * 4;
            *(float4*)&whs[jj][ff] = whv;
        }
#pragma unroll
        for (int half = 0; half < 2; half++) {
            const int l2 = lane + half * 32;
            const float vv = vj[half], bb = Bj[half], b5 = B5j[half];
#pragma unroll
            for (int r = 0; r < 8; r++) {
                const int r8 = wb * 8 + r;
                float w = 0.f;
                if (adjv[r * 2 + half] != 0)
                    w = (rowd[0][r8] + vv > 0.f) ? rowd[1][r8] * bb : rowd[2][r8] * b5;
                wS[r8][l2] = w;
                Zp[r] += w;
            }
        }

        if (t + 1 < T) {
            const int j0 = (t + 1) * 64;
#pragma unroll
            for (int r = 0; r < 8; r++) {
                adjv[r * 2 + 0] = adj[(rowbase + r) * N + j0 + lane];
                adjv[r * 2 + 1] = adj[(rowbase + r) * N + j0 + 32 + lane];
            }
            int jc0 = j0 + lane, jc1 = j0 + 32 + lane;
            vj[0] = g_v2[jc0]; Bj[0] = g_B2[jc0]; B5j[0] = g_B52[jc0];
            vj[1] = g_v2[jc1]; Bj[1] = g_B2[jc1]; B5j[1] = g_B52[jc1];
            int jj = tid >> 2, ff = (tid & 3) * 4;
            whv = *(const float4*)&g_Wh2[j0 + jj][ff];
        }

        __syncthreads();

        // phase B: acc[4 rows] for feature fcol
        const float* wrow = &wS[ig * 4][0];
#pragma unroll 8
        for (int jj = 0; jj < 64; jj++) {
            float wh = whs[jj][fcol];
#pragma unroll
            for (int r = 0; r < 4; r++)
                acc[r] = fmaf(wrow[(r << 6) + jj], wh, acc[r]);
        }
    }

    // reduce Z across lanes (warp wb owns rows wb*8..wb*8+7)
#pragma unroll
    for (int r = 0; r < 8; r++) {
#pragma unroll
        for (int o = 16; o; o >>= 1) Zp[r] += __shfl_xor_sync(0xffffffffu, Zp[r], o);
    }
    if (lane == 0) {
        Zs[wb * 8 + 0] = Zp[0]; Zs[wb * 8 + 1] = Zp[1];
        Zs[wb * 8 + 2] = Zp[2]; Zs[wb * 8 + 3] = Zp[3];
        Zs[wb * 8 + 4] = Zp[4]; Zs[wb * 8 + 5] = Zp[5];
        Zs[wb * 8 + 6] = Zp[6]; Zs[wb * 8 + 7] = Zp[7];
    }
    __syncthreads();

    // normalize + elu
#pragma unroll
    for (int r = 0; r < 4; r++) {
        const int row = ig * 4 + r;
        float o = acc[r] / Zs[row];
        o = (o > 0.f) ? o : expm1f(o);
        os[row][fcol] = o;
    }
    __syncthreads();

    // per-row log-sum-exp
    if (tid < 64) {
        float m = -3.0e38f;
#pragma unroll
        for (int k = 0; k < C; k++) m = fmaxf(m, os[tid][k]);
        float s = 0.f;
#pragma unroll
        for (int k = 0; k < C; k++) s += expf(os[tid][k] - m);
        lse[tid] = m + logf(s);
    }
    __syncthreads();

#pragma unroll
    for (int r = 0; r < 4; r++) {
        const int row = ig * 4 + r;
        out[(i0 + row) * C + fcol] = os[row][fcol] - lse[row];
    }
}

// ---------------- launch ----------------
extern "C" void kernel_launch(void* const* d_in, const int* in_sizes, int n_in,
                              void* d_out, int out_size) {
    const float* x       = (const float*)d_in[0];
    const int*   adj     = (const int*)  d_in[1];
    const float* W_heads = (const float*)d_in[2];
    const float* a_heads = (const float*)d_in[3];
    const float* W_out   = (const float*)d_in[4];
    const float* a_out   = (const float*)d_in[5];
    float* out = (float*)d_out;

    k_gemm1<<<dim3(N / 64, HEADS), 256>>>(x, W_heads);
    k_uv1<<<dim3(N / 8, HEADS), 256>>>(a_heads);
    k_max<<<4, 1024>>>(0);
    k_exp1<<<dim3(N / 256, HEADS), 256>>>();
    k_attn1<<<N / 64, 256>>>(adj);
    k_gemm2<<<N / 16, 256>>>(W_out);
    k_uv2<<<N / 8, 256>>>(a_out);
    k_max<<<2, 1024>>>(4);
    k_exp2<<<N / 256, 256>>>();
    k_attn2<<<N / 64, 256>>>(adj, out);
}

// round 6
// speedup vs baseline: 1.9367x; 1.9367x over previous
#include <cuda_runtime.h>
#include <math.h>
#include <stdint.h>

#define N8   8192
#define FIN  64
#define HID  64

// ---------------- device scratch ----------------
__device__ float g_Wh[2][N8][HID];
__device__ float g_u[2][N8], g_v[2][N8];
__device__ float g_A[2][N8], g_A5K[2][N8], g_B[2][N8], g_B5[2][N8];
__device__ float g_h[N8][128];
__device__ float g_Wh2[N8][16];
__device__ float g_u2[N8], g_v2[N8];
__device__ float g_A2[N8], g_A5K2[N8], g_B2t[N8], g_B52t[N8];
__device__ uint32_t g_mask[N8 * 256];   // 8 MB packed adjacency
__device__ float g_max[8];

// ---------------- helpers ----------------
__device__ __forceinline__ float totf(float x) {
    uint32_t r; asm("cvt.rna.tf32.f32 %0, %1;" : "=r"(r) : "f"(x));
    return __uint_as_float(r);
}
__device__ __forceinline__ uint32_t fb(float x) { return __float_as_uint(x); }

__device__ __forceinline__ void mma8(float* d, const uint32_t* a, uint32_t b0, uint32_t b1) {
    asm volatile("mma.sync.aligned.m16n8k8.row.col.f32.tf32.tf32.f32 "
                 "{%0,%1,%2,%3}, {%4,%5,%6,%7}, {%8,%9}, {%0,%1,%2,%3};"
                 : "+f"(d[0]), "+f"(d[1]), "+f"(d[2]), "+f"(d[3])
                 : "r"(a[0]), "r"(a[1]), "r"(a[2]), "r"(a[3]), "r"(b0), "r"(b1));
}

// ---------------- K1: Wh = x @ W_h ----------------
__global__ void k_gemm1(const float* __restrict__ x, const float* __restrict__ W_heads) {
    __shared__ float xs[64][FIN];
    __shared__ float ws[FIN][HID];
    const int h = blockIdx.y, i0 = blockIdx.x * 64, tid = threadIdx.x;
    const float4* xg = (const float4*)(x + (size_t)i0 * FIN);
    const float4* wg = (const float4*)(W_heads + (size_t)h * FIN * HID);
#pragma unroll
    for (int it = 0; it < 4; it++) ((float4*)xs)[tid + it * 256] = xg[tid + it * 256];
#pragma unroll
    for (int it = 0; it < 4; it++) ((float4*)ws)[tid + it * 256] = wg[tid + it * 256];
    __syncthreads();
    const int f = (tid & 15) * 4, ig = tid >> 4;
    float acc[4][4] = {};
#pragma unroll 4
    for (int k = 0; k < FIN; k++) {
        float4 wv = *(const float4*)&ws[k][f];
#pragma unroll
        for (int r = 0; r < 4; r++) {
            float xv = xs[ig * 4 + r][k];
            acc[r][0] = fmaf(xv, wv.x, acc[r][0]);
            acc[r][1] = fmaf(xv, wv.y, acc[r][1]);
            acc[r][2] = fmaf(xv, wv.z, acc[r][2]);
            acc[r][3] = fmaf(xv, wv.w, acc[r][3]);
        }
    }
#pragma unroll
    for (int r = 0; r < 4; r++)
        *(float4*)&g_Wh[h][i0 + ig * 4 + r][f] =
            make_float4(acc[r][0], acc[r][1], acc[r][2], acc[r][3]);
}

// ---------------- K2: u, v ----------------
__global__ void k_uv1(const float* __restrict__ a_heads) {
    const int h = blockIdx.y, wid = threadIdx.x >> 5, lane = threadIdx.x & 31;
    const int i = blockIdx.x * 8 + wid;
    const float* a = a_heads + (size_t)h * 2 * HID;
    const float* w = &g_Wh[h][i][0];
    float pu = fmaf(w[lane], a[lane], w[lane + 32] * a[lane + 32]);
    float pv = fmaf(w[lane], a[HID + lane], w[lane + 32] * a[HID + lane + 32]);
#pragma unroll
    for (int o = 16; o; o >>= 1) {
        pu += __shfl_xor_sync(0xffffffffu, pu, o);
        pv += __shfl_xor_sync(0xffffffffu, pv, o);
    }
    if (lane == 0) { g_u[h][i] = pu; g_v[h][i] = pv; }
}

// ---------------- K3: global max ----------------
__global__ void k_max(int base) {
    const int which = base + blockIdx.x;
    const float* src = (which == 0) ? g_u[0] : (which == 1) ? g_v[0] :
                       (which == 2) ? g_u[1] : (which == 3) ? g_v[1] :
                       (which == 4) ? g_u2 : g_v2;
    __shared__ float red[32];
    float m = -3.0e38f;
    for (int i = threadIdx.x; i < N8; i += blockDim.x) m = fmaxf(m, src[i]);
#pragma unroll
    for (int o = 16; o; o >>= 1) m = fmaxf(m, __shfl_xor_sync(0xffffffffu, m, o));
    if ((threadIdx.x & 31) == 0) red[threadIdx.x >> 5] = m;
    __syncthreads();
    if (threadIdx.x < 32) {
        float mm = red[threadIdx.x];
#pragma unroll
        for (int o = 16; o; o >>= 1) mm = fmaxf(mm, __shfl_xor_sync(0xffffffffu, mm, o));
        if (threadIdx.x == 0) g_max[which] = mm;
    }
}

// ---------------- K4: exp tables ----------------
__global__ void k_exp1() {
    const int i = blockIdx.x * 256 + threadIdx.x, h = blockIdx.y;
    const float um = g_max[h * 2], vm = g_max[h * 2 + 1], c = um + vm;
    const float u = g_u[h][i], v = g_v[h][i];
    g_A[h][i]   = expf(u - um);
    g_A5K[h][i] = expf(0.2f * (u - um) - 0.8f * c);
    g_B[h][i]   = expf(v - vm);
    g_B5[h][i]  = expf(0.2f * (v - vm));
}
__global__ void k_exp2() {
    const int i = blockIdx.x * 256 + threadIdx.x;
    const float um = g_max[4], vm = g_max[5], c = um + vm;
    const float u = g_u2[i], v = g_v2[i];
    g_A2[i]   = expf(u - um);
    g_A5K2[i] = expf(0.2f * (u - um) - 0.8f * c);
    g_B2t[i]  = expf(v - vm);
    g_B52t[i] = expf(0.2f * (v - vm));
}

// ---------------- K5: layer-1 attention via mma.sync tf32 ----------------
// CTA = 64 rows, 8 warps. warp w: head = w>>2, rowblock = w&3 (16 rows).
// Per tile (Kt=32 j's): producers build A = w-tile [2][64][36] and
// B = tf32(Wh) tile [2][32][68]; each warp runs 4 kslices x 8 colblocks MMAs.
__global__ __launch_bounds__(256) void k_attn1(const int* __restrict__ adj) {
    __shared__ float As[2][64][36];
    __shared__ float Bs[2][32][68];
    __shared__ float Zs[2][64];

    const int tid = threadIdx.x, lane = tid & 31, warp = tid >> 5;
    const int i0 = blockIdx.x * 64;
    const int r = tid >> 2, q = tid & 3;            // producer: row, j-quarter
    const int grow = i0 + r;
    const float rA1 = g_A[0][grow], rK1 = g_A5K[0][grow];
    const float rA2 = g_A[1][grow], rK2 = g_A5K[1][grow];
    const int h = warp >> 2, rb = warp & 3;         // MMA role
    const int la = lane >> 2, lb = lane & 3;

    float Z1 = 0.f, Z2 = 0.f;
    float acc[8][4] = {};

    // ---- prefetch tile 0 ----
    int4 aj0, aj1;
    float4 pb1[2], ps1[2], pb2[2], ps2[2], whv[4];
    {
        const int jq = q * 8;
        const int* ap = adj + (size_t)grow * N8 + jq;
        aj0 = *(const int4*)ap; aj1 = *(const int4*)(ap + 4);
        pb1[0] = *(const float4*)&g_B[0][jq];      pb1[1] = *(const float4*)&g_B[0][jq + 4];
        ps1[0] = *(const float4*)&g_B5[0][jq];     ps1[1] = *(const float4*)&g_B5[0][jq + 4];
        pb2[0] = *(const float4*)&g_B[1][jq];      pb2[1] = *(const float4*)&g_B[1][jq + 4];
        ps2[0] = *(const float4*)&g_B5[1][jq];     ps2[1] = *(const float4*)&g_B5[1][jq + 4];
#pragma unroll
        for (int it = 0; it < 4; it++) {
            int idx = tid + it * 256;
            int hh = idx >> 9, rem = idx & 511, k = rem >> 4, f4 = (rem & 15) << 2;
            whv[it] = *(const float4*)&g_Wh[hh][k][f4];
        }
    }

    for (int t = 0; t < 256; t++) {
        // ---- stage B tile (tf32-rounded Wh) ----
#pragma unroll
        for (int it = 0; it < 4; it++) {
            int idx = tid + it * 256;
            int hh = idx >> 9, rem = idx & 511, k = rem >> 4, f4 = (rem & 15) << 2;
            float* dst = &Bs[hh][k][f4];
            dst[0] = totf(whv[it].x); dst[1] = totf(whv[it].y);
            dst[2] = totf(whv[it].z); dst[3] = totf(whv[it].w);
        }
        // ---- w-gen: 8 j's x 2 heads per thread ----
        {
            const int ab[8] = {aj0.x, aj0.y, aj0.z, aj0.w, aj1.x, aj1.y, aj1.z, aj1.w};
            const float b1a[8] = {pb1[0].x, pb1[0].y, pb1[0].z, pb1[0].w,
                                  pb1[1].x, pb1[1].y, pb1[1].z, pb1[1].w};
            const float s1a[8] = {ps1[0].x, ps1[0].y, ps1[0].z, ps1[0].w,
                                  ps1[1].x, ps1[1].y, ps1[1].z, ps1[1].w};
            const float b2a[8] = {pb2[0].x, pb2[0].y, pb2[0].z, pb2[0].w,
                                  pb2[1].x, pb2[1].y, pb2[1].z, pb2[1].w};
            const float s2a[8] = {ps2[0].x, ps2[0].y, ps2[0].z, ps2[0].w,
                                  ps2[1].x, ps2[1].y, ps2[1].z, ps2[1].w};
            float w1v[8], w2v[8];
            uint32_t mbits = 0;
#pragma unroll
            for (int c = 0; c < 8; c++) {
                const bool m = (ab[c] != 0);
                float w1 = m ? totf(fmaxf(rA1 * b1a[c], rK1 * s1a[c])) : 0.f;
                float w2 = m ? totf(fmaxf(rA2 * b2a[c], rK2 * s2a[c])) : 0.f;
                Z1 += w1; Z2 += w2;
                w1v[c] = w1; w2v[c] = w2;
                mbits |= (m ? 1u : 0u) << (q * 8 + c);
            }
            *(float4*)&As[0][r][q * 8]     = make_float4(w1v[0], w1v[1], w1v[2], w1v[3]);
            *(float4*)&As[0][r][q * 8 + 4] = make_float4(w1v[4], w1v[5], w1v[6], w1v[7]);
            *(float4*)&As[1][r][q * 8]     = make_float4(w2v[0], w2v[1], w2v[2], w2v[3]);
            *(float4*)&As[1][r][q * 8 + 4] = make_float4(w2v[4], w2v[5], w2v[6], w2v[7]);
            mbits |= __shfl_xor_sync(0xffffffffu, mbits, 1);
            mbits |= __shfl_xor_sync(0xffffffffu, mbits, 2);
            if (q == 0) g_mask[grow * 256 + t] = mbits;
        }
        // ---- prefetch tile t+1 ----
        if (t + 1 < 256) {
            const int j0n = (t + 1) * 32, jq = j0n + q * 8;
            const int* ap = adj + (size_t)grow * N8 + jq;
            aj0 = *(const int4*)ap; aj1 = *(const int4*)(ap + 4);
            pb1[0] = *(const float4*)&g_B[0][jq];      pb1[1] = *(const float4*)&g_B[0][jq + 4];
            ps1[0] = *(const float4*)&g_B5[0][jq];     ps1[1] = *(const float4*)&g_B5[0][jq + 4];
            pb2[0] = *(const float4*)&g_B[1][jq];      pb2[1] = *(const float4*)&g_B[1][jq + 4];
            ps2[0] = *(const float4*)&g_B5[1][jq];     ps2[1] = *(const float4*)&g_B5[1][jq + 4];
#pragma unroll
            for (int it = 0; it < 4; it++) {
                int idx = tid + it * 256;
                int hh = idx >> 9, rem = idx & 511, k = rem >> 4, f4 = (rem & 15) << 2;
                whv[it] = *(const float4*)&g_Wh[hh][j0n + k][f4];
            }
        }
        __syncthreads();

        // ---- MMA phase: 4 kslices x 8 colblocks ----
#pragma unroll
        for (int ks = 0; ks < 4; ks++) {
            const int k0 = ks * 8;
            uint32_t a[4];
            a[0] = fb(As[h][rb * 16 + la][k0 + lb]);
            a[1] = fb(As[h][rb * 16 + la + 8][k0 + lb]);
            a[2] = fb(As[h][rb * 16 + la][k0 + lb + 4]);
            a[3] = fb(As[h][rb * 16 + la + 8][k0 + lb + 4]);
#pragma unroll
            for (int cb = 0; cb < 8; cb++) {
                uint32_t b0 = fb(Bs[h][k0 + lb][cb * 8 + la]);
                uint32_t b1 = fb(Bs[h][k0 + lb + 4][cb * 8 + la]);
                mma8(acc[cb], a, b0, b1);
            }
        }
        __syncthreads();
    }

    // ---- epilogue: Z reduce (quad), normalize, write ----
    Z1 += __shfl_xor_sync(0xffffffffu, Z1, 1);
    Z1 += __shfl_xor_sync(0xffffffffu, Z1, 2);
    Z2 += __shfl_xor_sync(0xffffffffu, Z2, 1);
    Z2 += __shfl_xor_sync(0xffffffffu, Z2, 2);
    if (q == 0) { Zs[0][r] = Z1; Zs[1][r] = Z2; }
    __syncthreads();

    const int rlo = rb * 16 + la, rhi = rlo + 8;
    const float invLo = 1.0f / Zs[h][rlo];
    const float invHi = 1.0f / Zs[h][rhi];
#pragma unroll
    for (int cb = 0; cb < 8; cb++) {
        *(float2*)&g_h[i0 + rlo][h * 64 + cb * 8 + 2 * lb] =
            make_float2(acc[cb][0] * invLo, acc[cb][1] * invLo);
        *(float2*)&g_h[i0 + rhi][h * 64 + cb * 8 + 2 * lb] =
            make_float2(acc[cb][2] * invHi, acc[cb][3] * invHi);
    }
}

// ---------------- K6: Wh2 = h @ W_out ----------------
__global__ void k_gemm2(const float* __restrict__ W_out) {
    __shared__ float hs[16][128];
    __shared__ float ws[128][16];
    const int tid = threadIdx.x, i0 = blockIdx.x * 16;
#pragma unroll
    for (int it = 0; it < 2; it++)
        ((float4*)hs)[tid + it * 256] = ((const float4*)&g_h[i0][0])[tid + it * 256];
#pragma unroll
    for (int it = 0; it < 2; it++)
        ((float4*)ws)[tid + it * 256] = ((const float4*)W_out)[tid + it * 256];
    __syncthreads();
    const int r = tid >> 4, f = tid & 15;
    float acc = 0.f;
#pragma unroll 8
    for (int k = 0; k < 128; k++) acc = fmaf(hs[r][k], ws[k][f], acc);
    g_Wh2[i0 + r][f] = acc;
}

// ---------------- K7: u2/v2 ----------------
__global__ void k_uv2(const float* __restrict__ a_out) {
    const int wid = threadIdx.x >> 5, lane = threadIdx.x & 31;
    const int i = blockIdx.x * 8 + wid;
    float pu = 0.f, pv = 0.f;
    if (lane < 16) {
        float wh = g_Wh2[i][lane];
        pu = wh * a_out[lane];
        pv = wh * a_out[16 + lane];
    }
#pragma unroll
    for (int o = 16; o; o >>= 1) {
        pu += __shfl_xor_sync(0xffffffffu, pu, o);
        pv += __shfl_xor_sync(0xffffffffu, pv, o);
    }
    if (lane == 0) { g_u2[i] = pu; g_v2[i] = pv; }
}

// ---------------- K9: output attention + elu + log_softmax ----------------
// CTA = 64 rows, 8 warps. warp w: rowblock = w&3, k-half = w>>2.
__global__ __launch_bounds__(256) void k_attn2(float* __restrict__ out) {
    __shared__ float As2[64][36];
    __shared__ float Bs2[32][20];
    __shared__ float Zs2[64];
    __shared__ float psum[4][32][8];
    __shared__ float os[64][17];

    const int tid = threadIdx.x, lane = tid & 31, warp = tid >> 5;
    const int i0 = blockIdx.x * 64;
    const int r = tid >> 2, q = tid & 3;
    const int grow = i0 + r;
    const float rA = g_A2[grow], rK = g_A5K2[grow];
    const int rb = warp & 3, kh = warp >> 2;
    const int la = lane >> 2, lb = lane & 3;
    const bool ldb = (tid < 128);

    float Z = 0.f;
    float acc[2][4] = {};

    // prefetch tile 0
    uint32_t mw = g_mask[grow * 256 + 0];
    float4 pb[2], ps_[2], whv;
    {
        const int jq = q * 8;
        pb[0]  = *(const float4*)&g_B2t[jq];  pb[1]  = *(const float4*)&g_B2t[jq + 4];
        ps_[0] = *(const float4*)&g_B52t[jq]; ps_[1] = *(const float4*)&g_B52t[jq + 4];
        if (ldb) whv = *(const float4*)&g_Wh2[tid >> 2][(tid & 3) * 4];
    }

    for (int t = 0; t < 256; t++) {
        // stage B tile
        if (ldb) {
            const int k = tid >> 2, f4 = (tid & 3) * 4;
            float* dst = &Bs2[k][f4];
            dst[0] = totf(whv.x); dst[1] = totf(whv.y);
            dst[2] = totf(whv.z); dst[3] = totf(whv.w);
        }
        // w-gen
        {
            const float ba[8] = {pb[0].x, pb[0].y, pb[0].z, pb[0].w,
                                 pb[1].x, pb[1].y, pb[1].z, pb[1].w};
            const float sa[8] = {ps_[0].x, ps_[0].y, ps_[0].z, ps_[0].w,
                                 ps_[1].x, ps_[1].y, ps_[1].z, ps_[1].w};
            float wv[8];
#pragma unroll
            for (int c = 0; c < 8; c++) {
                const bool m = (mw >> (q * 8 + c)) & 1u;
                float w = m ? totf(fmaxf(rA * ba[c], rK * sa[c])) : 0.f;
                Z += w; wv[c] = w;
            }
            *(float4*)&As2[r][q * 8]     = make_float4(wv[0], wv[1], wv[2], wv[3]);
            *(float4*)&As2[r][q * 8 + 4] = make_float4(wv[4], wv[5], wv[6], wv[7]);
        }
        // prefetch t+1
        if (t + 1 < 256) {
            const int j0n = (t + 1) * 32, jq = j0n + q * 8;
            mw = g_mask[grow * 256 + t + 1];
            pb[0]  = *(const float4*)&g_B2t[jq];  pb[1]  = *(const float4*)&g_B2t[jq + 4];
            ps_[0] = *(const float4*)&g_B52t[jq]; ps_[1] = *(const float4*)&g_B52t[jq + 4];
            if (ldb) whv = *(const float4*)&g_Wh2[j0n + (tid >> 2)][(tid & 3) * 4];
        }
        __syncthreads();

        // MMA: this warp's 2 kslices x 2 colblocks
#pragma unroll
        for (int ki = 0; ki < 2; ki++) {
            const int k0 = (kh * 2 + ki) * 8;
            uint32_t a[4];
            a[0] = fb(As2[rb * 16 + la][k0 + lb]);
            a[1] = fb(As2[rb * 16 + la + 8][k0 + lb]);
            a[2] = fb(As2[rb * 16 + la][k0 + lb + 4]);
            a[3] = fb(As2[rb * 16 + la + 8][k0 + lb + 4]);
#pragma unroll
            for (int cb = 0; cb < 2; cb++) {
                uint32_t b0 = fb(Bs2[k0 + lb][cb * 8 + la]);
                uint32_t b1 = fb(Bs2[k0 + lb + 4][cb * 8 + la]);
                mma8(acc[cb], a, b0, b1);
            }
        }
        __syncthreads();
    }

    // Z reduce
    Z += __shfl_xor_sync(0xffffffffu, Z, 1);
    Z += __shfl_xor_sync(0xffffffffu, Z, 2);
    if (q == 0) Zs2[r] = Z;
    // partial accum handoff
    if (kh == 1) {
#pragma unroll
        for (int cb = 0; cb < 2; cb++)
#pragma unroll
            for (int i = 0; i < 4; i++) psum[rb][lane][cb * 4 + i] = acc[cb][i];
    }
    __syncthreads();

    if (kh == 0) {
        const int rlo = rb * 16 + la, rhi = rlo + 8;
        const float invLo = 1.0f / Zs2[rlo];
        const float invHi = 1.0f / Zs2[rhi];
#pragma unroll
        for (int cb = 0; cb < 2; cb++) {
            float v0 = (acc[cb][0] + psum[rb][lane][cb * 4 + 0]) * invLo;
            float v1 = (acc[cb][1] + psum[rb][lane][cb * 4 + 1]) * invLo;
            float v2 = (acc[cb][2] + psum[rb][lane][cb * 4 + 2]) * invHi;
            float v3 = (acc[cb][3] + psum[rb][lane][cb * 4 + 3]) * invHi;
            v0 = (v0 > 0.f) ? v0 : expm1f(v0);
            v1 = (v1 > 0.f) ? v1 : expm1f(v1);
            v2 = (v2 > 0.f) ? v2 : expm1f(v2);
            v3 = (v3 > 0.f) ? v3 : expm1f(v3);
            os[rlo][cb * 8 + 2 * lb]     = v0;
            os[rlo][cb * 8 + 2 * lb + 1] = v1;
            os[rhi][cb * 8 + 2 * lb]     = v2;
            os[rhi][cb * 8 + 2 * lb + 1] = v3;
        }
    }
    __syncthreads();

    if (tid < 64) {
        float o[16], mx = -3.0e38f;
#pragma unroll
        for (int c = 0; c < 16; c++) { o[c] = os[tid][c]; mx = fmaxf(mx, o[c]); }
        float s = 0.f;
#pragma unroll
        for (int c = 0; c < 16; c++) s += expf(o[c] - mx);
        const float lse = mx + logf(s);
        const int orow = i0 + tid;
#pragma unroll
        for (int qq = 0; qq < 4; qq++)
            *(float4*)&out[(size_t)orow * 16 + qq * 4] =
                make_float4(o[qq * 4] - lse, o[qq * 4 + 1] - lse,
                            o[qq * 4 + 2] - lse, o[qq * 4 + 3] - lse);
    }
}

// ---------------- launch ----------------
extern "C" void kernel_launch(void* const* d_in, const int* in_sizes, int n_in,
                              void* d_out, int out_size) {
    const float* x       = (const float*)d_in[0];
    const int*   adj     = (const int*)  d_in[1];
    const float* W_heads = (const float*)d_in[2];
    const float* a_heads = (const float*)d_in[3];
    const float* W_out   = (const float*)d_in[4];
    const float* a_out   = (const float*)d_in[5];
    float* out = (float*)d_out;

    k_gemm1<<<dim3(N8 / 64, 2), 256>>>(x, W_heads);
    k_uv1<<<dim3(N8 / 8, 2), 256>>>(a_heads);
    k_max<<<4, 1024>>>(0);
    k_exp1<<<dim3(N8 / 256, 2), 256>>>();
    k_attn1<<<N8 / 64, 256>>>(adj);
    k_gemm2<<<N8 / 16, 256>>>(W_out);
    k_uv2<<<N8 / 8, 256>>>(a_out);
    k_max<<<2, 1024>>>(4);
    k_exp2<<<N8 / 256, 256>>>();
    k_attn2<<<N8 / 64, 256>>>(out);
}

// round 9
// speedup vs baseline: 3.6480x; 1.8836x over previous
#include <cuda_runtime.h>
#include <cuda_bf16.h>
#include <math.h>
#include <stdint.h>

#define N8   8192
#define FIN  64
#define HID  64

// ---------------- device scratch ----------------
__device__ float g_Wh[2][N8][HID];                    // fp32 Wh (for u/v dots)
__device__ __nv_bfloat16 g_WhT_bf[2][HID][N8];        // bf16 transposed Wh (B operand)
__device__ float g_u[2][N8], g_v[2][N8];
__device__ float g_A[2][N8], g_A5K[2][N8];
__device__ uint32_t g_T1[2][N8];                      // packed bf16: hi=B, lo=B5
__device__ float g_h[N8][128];
__device__ float g_Wh2[N8][16];
__device__ __nv_bfloat16 g_Wh2T_bf[16][N8];
__device__ float g_u2[N8], g_v2[N8];
__device__ float g_A2[N8], g_A5K2[N8];
__device__ uint32_t g_T2[N8];
__device__ unsigned char g_maskb[N8][2048];           // 16 MB: [row][tile*8+q] 4-bit masks
__device__ float g_max[8];

// ---------------- helpers ----------------
__device__ __forceinline__ uint32_t pack_bf(float hi, float lo) {
    uint32_t d; asm("cvt.rn.bf16x2.f32 %0, %1, %2;" : "=r"(d) : "f"(hi), "f"(lo));
    return d;
}
__device__ __forceinline__ void mma16(float* d, uint32_t a0, uint32_t a1, uint32_t a2,
                                      uint32_t a3, uint32_t b0, uint32_t b1) {
    asm volatile("mma.sync.aligned.m16n8k16.row.col.f32.bf16.bf16.f32 "
                 "{%0,%1,%2,%3}, {%4,%5,%6,%7}, {%8,%9}, {%0,%1,%2,%3};"
                 : "+f"(d[0]), "+f"(d[1]), "+f"(d[2]), "+f"(d[3])
                 : "r"(a0), "r"(a1), "r"(a2), "r"(a3), "r"(b0), "r"(b1));
}
__device__ __forceinline__ int4 ldcs4(const int* p) {
    int4 v;
    asm volatile("ld.global.cs.v4.s32 {%0,%1,%2,%3}, [%4];"
                 : "=r"(v.x), "=r"(v.y), "=r"(v.z), "=r"(v.w) : "l"(p));
    return v;
}

// ---------------- K1: Wh = x @ W_h (+ bf16 transposed copy) ----------------
__global__ void k_gemm1(const float* __restrict__ x, const float* __restrict__ W_heads) {
    __shared__ float xs[64][FIN];
    __shared__ float ws[FIN][HID];
    const int h = blockIdx.y, i0 = blockIdx.x * 64, tid = threadIdx.x;
    const float4* xg = (const float4*)(x + (size_t)i0 * FIN);
    const float4* wg = (const float4*)(W_heads + (size_t)h * FIN * HID);
#pragma unroll
    for (int it = 0; it < 4; it++) ((float4*)xs)[tid + it * 256] = xg[tid + it * 256];
#pragma unroll
    for (int it = 0; it < 4; it++) ((float4*)ws)[tid + it * 256] = wg[tid + it * 256];
    __syncthreads();
    const int f = (tid & 15) * 4, ig = tid >> 4;
    float acc[4][4] = {};
#pragma unroll 4
    for (int k = 0; k < FIN; k++) {
        float4 wv = *(const float4*)&ws[k][f];
#pragma unroll
        for (int r = 0; r < 4; r++) {
            float xv = xs[ig * 4 + r][k];
            acc[r][0] = fmaf(xv, wv.x, acc[r][0]);
            acc[r][1] = fmaf(xv, wv.y, acc[r][1]);
            acc[r][2] = fmaf(xv, wv.z, acc[r][2]);
            acc[r][3] = fmaf(xv, wv.w, acc[r][3]);
        }
    }
#pragma unroll
    for (int r = 0; r < 4; r++) {
        const int row = i0 + ig * 4 + r;
        *(float4*)&g_Wh[h][row][f] = make_float4(acc[r][0], acc[r][1], acc[r][2], acc[r][3]);
#pragma unroll
        for (int c = 0; c < 4; c++) g_WhT_bf[h][f + c][row] = __float2bfloat16(acc[r][c]);
    }
}

// ---------------- K2: u, v ----------------
__global__ void k_uv1(const float* __restrict__ a_heads) {
    const int h = blockIdx.y, wid = threadIdx.x >> 5, lane = threadIdx.x & 31;
    const int i = blockIdx.x * 8 + wid;
    const float* a = a_heads + (size_t)h * 2 * HID;
    const float* w = &g_Wh[h][i][0];
    float pu = fmaf(w[lane], a[lane], w[lane + 32] * a[lane + 32]);
    float pv = fmaf(w[lane], a[HID + lane], w[lane + 32] * a[HID + lane + 32]);
#pragma unroll
    for (int o = 16; o; o >>= 1) {
        pu += __shfl_xor_sync(0xffffffffu, pu, o);
        pv += __shfl_xor_sync(0xffffffffu, pv, o);
    }
    if (lane == 0) { g_u[h][i] = pu; g_v[h][i] = pv; }
}

// ---------------- K3: global max ----------------
__global__ void k_max(int base) {
    const int which = base + blockIdx.x;
    const float* src = (which == 0) ? g_u[0] : (which == 1) ? g_v[0] :
                       (which == 2) ? g_u[1] : (which == 3) ? g_v[1] :
                       (which == 4) ? g_u2 : g_v2;
    __shared__ float red[32];
    float m = -3.0e38f;
    for (int i = threadIdx.x; i < N8; i += blockDim.x) m = fmaxf(m, src[i]);
#pragma unroll
    for (int o = 16; o; o >>= 1) m = fmaxf(m, __shfl_xor_sync(0xffffffffu, m, o));
    if ((threadIdx.x & 31) == 0) red[threadIdx.x >> 5] = m;
    __syncthreads();
    if (threadIdx.x < 32) {
        float mm = red[threadIdx.x];
#pragma unroll
        for (int o = 16; o; o >>= 1) mm = fmaxf(mm, __shfl_xor_sync(0xffffffffu, mm, o));
        if (threadIdx.x == 0) g_max[which] = mm;
    }
}

// ---------------- K4: exp tables ----------------
__global__ void k_exp1() {
    const int i = blockIdx.x * 256 + threadIdx.x, h = blockIdx.y;
    const float um = g_max[h * 2], vm = g_max[h * 2 + 1], c = um + vm;
    const float u = g_u[h][i], v = g_v[h][i];
    g_A[h][i]   = expf(u - um);
    g_A5K[h][i] = expf(0.2f * (u - um) - 0.8f * c);
    g_T1[h][i]  = pack_bf(expf(v - vm), expf(0.2f * (v - vm)));
}
__global__ void k_exp2() {
    const int i = blockIdx.x * 256 + threadIdx.x;
    const float um = g_max[4], vm = g_max[5], c = um + vm;
    const float u = g_u2[i], v = g_v2[i];
    g_A2[i]   = expf(u - um);
    g_A5K2[i] = expf(0.2f * (u - um) - 0.8f * c);
    g_T2[i]   = pack_bf(expf(v - vm), expf(0.2f * (v - vm)));
}

// ---------------- K5: layer-1 attention, bf16 mma.m16n8k16 ----------------
// CTA = 64 rows, 256 threads, 256 tiles of 32 j.
// Producer: thread (r2 = tid>>3 -> rows 2r2,2r2+1; q = tid&7 -> j q*4..q*4+3).
// MMA: warp w: h = w>>2, rb = w&3; la = lane>>2, lb = lane&3.
__global__ __launch_bounds__(256) void k_attn1(const int* __restrict__ adj) {
    __shared__ __align__(16) unsigned short As[2][2][64][40];  // [buf][h][row][k] bf16, 80B rows
    __shared__ __align__(16) unsigned short Bs[2][2][64][40];  // [buf][h][feat][k]
    __shared__ float Zs[2][64];

    const int tid = threadIdx.x, lane = tid & 31, warp = tid >> 5;
    const int i0 = blockIdx.x * 64;
    const int r2 = tid >> 3, q = tid & 7;
    const int grow0 = i0 + 2 * r2, grow1 = grow0 + 1;
    const int h = warp >> 2, rb = warp & 3;
    const int la = lane >> 2, lb = lane & 3;

    float rA[2][2], rK[2][2];
#pragma unroll
    for (int hh = 0; hh < 2; hh++) {
        rA[hh][0] = g_A[hh][grow0];   rA[hh][1] = g_A[hh][grow1];
        rK[hh][0] = g_A5K[hh][grow0]; rK[hh][1] = g_A5K[hh][grow1];
    }

    float Zl[2][2] = {};
    float acc[8][4] = {};

    int4  p_adj[2][2];
    uint4 p_tw[2][2];
    uint4 p_wh[2][2];

    // prefetch tile 0
    {
        const int jq = q * 4;
        p_adj[0][0] = ldcs4(adj + (size_t)grow0 * N8 + jq);
        p_adj[0][1] = ldcs4(adj + (size_t)grow1 * N8 + jq);
        p_tw[0][0] = *(const uint4*)&g_T1[0][jq];
        p_tw[0][1] = *(const uint4*)&g_T1[1][jq];
#pragma unroll
        for (int it = 0; it < 2; it++) {
            int g = tid + it * 256;
            int cc = g & 3, ff = (g >> 2) & 63, hh = g >> 8;
            p_wh[0][it] = *(const uint4*)&g_WhT_bf[hh][ff][cc * 8];
        }
    }

#pragma unroll 2
    for (int t = 0; t < 256; t++) {
        const int par = t & 1;
        // ---- prefetch t+1 ----
        if (t + 1 < 256) {
            const int j0n = (t + 1) * 32, jq = j0n + q * 4;
            p_adj[par ^ 1][0] = ldcs4(adj + (size_t)grow0 * N8 + jq);
            p_adj[par ^ 1][1] = ldcs4(adj + (size_t)grow1 * N8 + jq);
            p_tw[par ^ 1][0] = *(const uint4*)&g_T1[0][jq];
            p_tw[par ^ 1][1] = *(const uint4*)&g_T1[1][jq];
#pragma unroll
            for (int it = 0; it < 2; it++) {
                int g = tid + it * 256;
                int cc = g & 3, ff = (g >> 2) & 63, hh = g >> 8;
                p_wh[par ^ 1][it] = *(const uint4*)&g_WhT_bf[hh][ff][j0n + cc * 8];
            }
        }
        // ---- stage B tile ----
#pragma unroll
        for (int it = 0; it < 2; it++) {
            int g = tid + it * 256;
            int cc = g & 3, ff = (g >> 2) & 63, hh = g >> 8;
            *(uint4*)&Bs[par][hh][ff][cc * 8] = p_wh[par][it];
        }
        // ---- w-gen ----
        {
            const int av0[4] = {p_adj[par][0].x, p_adj[par][0].y, p_adj[par][0].z, p_adj[par][0].w};
            const int av1[4] = {p_adj[par][1].x, p_adj[par][1].y, p_adj[par][1].z, p_adj[par][1].w};
            unsigned mb0 = 0, mb1 = 0;
#pragma unroll
            for (int c = 0; c < 4; c++) {
                mb0 |= (av0[c] != 0) << c;
                mb1 |= (av1[c] != 0) << c;
            }
#pragma unroll
            for (int hh = 0; hh < 2; hh++) {
                const uint32_t twa[4] = {p_tw[par][hh].x, p_tw[par][hh].y,
                                         p_tw[par][hh].z, p_tw[par][hh].w};
                float Bv[4], B5v[4];
#pragma unroll
                for (int c = 0; c < 4; c++) {
                    Bv[c]  = __uint_as_float(twa[c] & 0xFFFF0000u);
                    B5v[c] = __uint_as_float(twa[c] << 16);
                }
#pragma unroll
                for (int rr = 0; rr < 2; rr++) {
                    const int* av = rr ? av1 : av0;
                    const float a_ = rA[hh][rr], k_ = rK[hh][rr];
                    float w[4];
#pragma unroll
                    for (int c = 0; c < 4; c++) {
                        w[c] = av[c] ? fmaxf(a_ * Bv[c], k_ * B5v[c]) : 0.f;
                        Zl[hh][rr] += w[c];
                    }
                    uint2 pk = make_uint2(pack_bf(w[1], w[0]), pack_bf(w[3], w[2]));
                    *(uint2*)&As[par][hh][2 * r2 + rr][q * 4] = pk;
                }
            }
            g_maskb[grow0][t * 8 + q] = (unsigned char)mb0;
            g_maskb[grow1][t * 8 + q] = (unsigned char)mb1;
        }
        __syncthreads();

        // ---- MMA phase: 2 kslices x 8 colblocks ----
#pragma unroll
        for (int ks = 0; ks < 2; ks++) {
            const int k0 = ks * 16;
            const uint32_t a0 = *(const uint32_t*)&As[par][h][rb * 16 + la][k0 + 2 * lb];
            const uint32_t a1 = *(const uint32_t*)&As[par][h][rb * 16 + la + 8][k0 + 2 * lb];
            const uint32_t a2 = *(const uint32_t*)&As[par][h][rb * 16 + la][k0 + 2 * lb + 8];
            const uint32_t a3 = *(const uint32_t*)&As[par][h][rb * 16 + la + 8][k0 + 2 * lb + 8];
#pragma unroll
            for (int cb = 0; cb < 8; cb++) {
                const uint32_t b0 = *(const uint32_t*)&Bs[par][h][cb * 8 + la][k0 + 2 * lb];
                const uint32_t b1 = *(const uint32_t*)&Bs[par][h][cb * 8 + la][k0 + 2 * lb + 8];
                mma16(acc[cb], a0, a1, a2, a3, b0, b1);
            }
        }
    }

    // ---- Z reduce within 8-lane q-groups ----
#pragma unroll
    for (int hh = 0; hh < 2; hh++)
#pragma unroll
        for (int rr = 0; rr < 2; rr++) {
            float z = Zl[hh][rr];
            z += __shfl_xor_sync(0xffffffffu, z, 1);
            z += __shfl_xor_sync(0xffffffffu, z, 2);
            z += __shfl_xor_sync(0xffffffffu, z, 4);
            if (q == 0) Zs[hh][2 * r2 + rr] = z;
        }
    __syncthreads();

    const int rlo = rb * 16 + la, rhi = rlo + 8;
    const float invLo = 1.0f / Zs[h][rlo];
    const float invHi = 1.0f / Zs[h][rhi];
#pragma unroll
    for (int cb = 0; cb < 8; cb++) {
        *(float2*)&g_h[i0 + rlo][h * 64 + cb * 8 + 2 * lb] =
            make_float2(acc[cb][0] * invLo, acc[cb][1] * invLo);
        *(float2*)&g_h[i0 + rhi][h * 64 + cb * 8 + 2 * lb] =
            make_float2(acc[cb][2] * invHi, acc[cb][3] * invHi);
    }
}

// ---------------- K6: Wh2 = h @ W_out (+ bf16 transposed) ----------------
__global__ void k_gemm2(const float* __restrict__ W_out) {
    __shared__ float hs[16][128];
    __shared__ float ws[128][16];
    const int tid = threadIdx.x, i0 = blockIdx.x * 16;
#pragma unroll
    for (int it = 0; it < 2; it++)
        ((float4*)hs)[tid + it * 256] = ((const float4*)&g_h[i0][0])[tid + it * 256];
#pragma unroll
    for (int it = 0; it < 2; it++)
        ((float4*)ws)[tid + it * 256] = ((const float4*)W_out)[tid + it * 256];
    __syncthreads();
    const int r = tid >> 4, f = tid & 15;
    float acc = 0.f;
#pragma unroll 8
    for (int k = 0; k < 128; k++) acc = fmaf(hs[r][k], ws[k][f], acc);
    g_Wh2[i0 + r][f] = acc;
    g_Wh2T_bf[f][i0 + r] = __float2bfloat16(acc);
}

// ---------------- K7: u2/v2 ----------------
__global__ void k_uv2(const float* __restrict__ a_out) {
    const int wid = threadIdx.x >> 5, lane = threadIdx.x & 31;
    const int i = blockIdx.x * 8 + wid;
    float pu = 0.f, pv = 0.f;
    if (lane < 16) {
        float wh = g_Wh2[i][lane];
        pu = wh * a_out[lane];
        pv = wh * a_out[16 + lane];
    }
#pragma unroll
    for (int o = 16; o; o >>= 1) {
        pu += __shfl_xor_sync(0xffffffffu, pu, o);
        pv += __shfl_xor_sync(0xffffffffu, pv, o);
    }
    if (lane == 0) { g_u2[i] = pu; g_v2[i] = pv; }
}

// ---------------- K9: output attention + elu + log_softmax ----------------
__global__ __launch_bounds__(256) void k_attn2(float* __restrict__ out) {
    __shared__ __align__(16) unsigned short As2[2][64][40];
    __shared__ __align__(16) unsigned short Bs2[2][16][40];
    __shared__ float Zs2[64];
    __shared__ float psum[4][32][8];
    __shared__ float os[64][17];

    const int tid = threadIdx.x, lane = tid & 31, warp = tid >> 5;
    const int i0 = blockIdx.x * 64;
    const int r2 = tid >> 3, q = tid & 7;
    const int grow0 = i0 + 2 * r2, grow1 = grow0 + 1;
    const int rb = warp & 3, kh = warp >> 2;
    const int la = lane >> 2, lb = lane & 3;

    const float rA0 = g_A2[grow0], rK0 = g_A5K2[grow0];
    const float rA1 = g_A2[grow1], rK1 = g_A5K2[grow1];

    float Zl[2] = {};
    float acc[2][4] = {};

    unsigned p_mb[2][2];
    uint4 p_tw[2];
    uint4 p_wh[2];
    const bool ldb = (tid < 64);

    {
        const int jq = q * 4;
        p_mb[0][0] = g_maskb[grow0][q];
        p_mb[0][1] = g_maskb[grow1][q];
        p_tw[0] = *(const uint4*)&g_T2[jq];
        if (ldb) {
            int ff = tid >> 2, cc = tid & 3;
            p_wh[0] = *(const uint4*)&g_Wh2T_bf[ff][cc * 8];
        }
    }

#pragma unroll 2
    for (int t = 0; t < 256; t++) {
        const int par = t & 1;
        if (t + 1 < 256) {
            const int j0n = (t + 1) * 32, jq = j0n + q * 4;
            p_mb[par ^ 1][0] = g_maskb[grow0][(t + 1) * 8 + q];
            p_mb[par ^ 1][1] = g_maskb[grow1][(t + 1) * 8 + q];
            p_tw[par ^ 1] = *(const uint4*)&g_T2[jq];
            if (ldb) {
                int ff = tid >> 2, cc = tid & 3;
                p_wh[par ^ 1] = *(const uint4*)&g_Wh2T_bf[ff][j0n + cc * 8];
            }
        }
        if (ldb) {
            int ff = tid >> 2, cc = tid & 3;
            *(uint4*)&Bs2[par][ff][cc * 8] = p_wh[par];
        }
        {
            const uint32_t twa[4] = {p_tw[par].x, p_tw[par].y, p_tw[par].z, p_tw[par].w};
            float Bv[4], B5v[4];
#pragma unroll
            for (int c = 0; c < 4; c++) {
                Bv[c]  = __uint_as_float(twa[c] & 0xFFFF0000u);
                B5v[c] = __uint_as_float(twa[c] << 16);
            }
#pragma unroll
            for (int rr = 0; rr < 2; rr++) {
                const unsigned mb = p_mb[par][rr];
                const float a_ = rr ? rA1 : rA0, k_ = rr ? rK1 : rK0;
                float w[4];
#pragma unroll
                for (int c = 0; c < 4; c++) {
                    w[c] = (mb >> c) & 1u ? fmaxf(a_ * Bv[c], k_ * B5v[c]) : 0.f;
                    Zl[rr] += w[c];
                }
                uint2 pk = make_uint2(pack_bf(w[1], w[0]), pack_bf(w[3], w[2]));
                *(uint2*)&As2[par][2 * r2 + rr][q * 4] = pk;
            }
        }
        __syncthreads();

        // MMA: this warp's kslice (kh) x 2 colblocks
        {
            const int k0 = kh * 16;
            const uint32_t a0 = *(const uint32_t*)&As2[par][rb * 16 + la][k0 + 2 * lb];
            const uint32_t a1 = *(const uint32_t*)&As2[par][rb * 16 + la + 8][k0 + 2 * lb];
            const uint32_t a2 = *(const uint32_t*)&As2[par][rb * 16 + la][k0 + 2 * lb + 8];
            const uint32_t a3 = *(const uint32_t*)&As2[par][rb * 16 + la + 8][k0 + 2 * lb + 8];
#pragma unroll
            for (int cb = 0; cb < 2; cb++) {
                const uint32_t b0 = *(const uint32_t*)&Bs2[par][cb * 8 + la][k0 + 2 * lb];
                const uint32_t b1 = *(const uint32_t*)&Bs2[par][cb * 8 + la][k0 + 2 * lb + 8];
                mma16(acc[cb], a0, a1, a2, a3, b0, b1);
            }
        }
    }

    // Z reduce
#pragma unroll
    for (int rr = 0; rr < 2; rr++) {
        float z = Zl[rr];
        z += __shfl_xor_sync(0xffffffffu, z, 1);
        z += __shfl_xor_sync(0xffffffffu, z, 2);
        z += __shfl_xor_sync(0xffffffffu, z, 4);
        if (q == 0) Zs2[2 * r2 + rr] = z;
    }
    if (kh == 1) {
#pragma unroll
        for (int cb = 0; cb < 2; cb++)
#pragma unroll
            for (int i = 0; i < 4; i++) psum[rb][lane][cb * 4 + i] = acc[cb][i];
    }
    __syncthreads();

    if (kh == 0) {
        const int rlo = rb * 16 + la, rhi = rlo + 8;
        const float invLo = 1.0f / Zs2[rlo];
        const float invHi = 1.0f / Zs2[rhi];
#pragma unroll
        for (int cb = 0; cb < 2; cb++) {
            float v0 = (acc[cb][0] + psum[rb][lane][cb * 4 + 0]) * invLo;
            float v1 = (acc[cb][1] + psum[rb][lane][cb * 4 + 1]) * invLo;
            float v2 = (acc[cb][2] + psum[rb][lane][cb * 4 + 2]) * invHi;
            float v3 = (acc[cb][3] + psum[rb][lane][cb * 4 + 3]) * invHi;
            v0 = (v0 > 0.f) ? v0 : expm1f(v0);
            v1 = (v1 > 0.f) ? v1 : expm1f(v1);
            v2 = (v2 > 0.f) ? v2 : expm1f(v2);
            v3 = (v3 > 0.f) ? v3 : expm1f(v3);
            os[rlo][cb * 8 + 2 * lb]     = v0;
            os[rlo][cb * 8 + 2 * lb + 1] = v1;
            os[rhi][cb * 8 + 2 * lb]     = v2;
            os[rhi][cb * 8 + 2 * lb + 1] = v3;
        }
    }
    __syncthreads();

    if (tid < 64) {
        float o[16], mx = -3.0e38f;
#pragma unroll
        for (int c = 0; c < 16; c++) { o[c] = os[tid][c]; mx = fmaxf(mx, o[c]); }
        float s = 0.f;
#pragma unroll
        for (int c = 0; c < 16; c++) s += expf(o[c] - mx);
        const float lse = mx + logf(s);
        const int orow = i0 + tid;
#pragma unroll
        for (int qq = 0; qq < 4; qq++)
            *(float4*)&out[(size_t)orow * 16 + qq * 4] =
                make_float4(o[qq * 4] - lse, o[qq * 4 + 1] - lse,
                            o[qq * 4 + 2] - lse, o[qq * 4 + 3] - lse);
    }
}

// ---------------- launch ----------------
extern "C" void kernel_launch(void* const* d_in, const int* in_sizes, int n_in,
                              void* d_out, int out_size) {
    const float* x       = (const float*)d_in[0];
    const int*   adj     = (const int*)  d_in[1];
    const float* W_heads = (const float*)d_in[2];
    const float* a_heads = (const float*)d_in[3];
    const float* W_out   = (const float*)d_in[4];
    const float* a_out   = (const float*)d_in[5];
    float* out = (float*)d_out;

    k_gemm1<<<dim3(N8 / 64, 2), 256>>>(x, W_heads);
    k_uv1<<<dim3(N8 / 8, 2), 256>>>(a_heads);
    k_max<<<4, 1024>>>(0);
    k_exp1<<<dim3(N8 / 256, 2), 256>>>();
    k_attn1<<<N8 / 64, 256>>>(adj);
    k_gemm2<<<N8 / 16, 256>>>(W_out);
    k_uv2<<<N8 / 8, 256>>>(a_out);
    k_max<<<2, 1024>>>(4);
    k_exp2<<<N8 / 256, 256>>>();
    k_attn2<<<N8 / 64, 256>>>(out);
}

// round 11
// speedup vs baseline: 3.7385x; 1.0248x over previous
#include <cuda_runtime.h>
#include <cuda_bf16.h>
#include <math.h>
#include <stdint.h>

#define N8   8192
#define FIN  64
#define HID  64

// ---------------- device scratch ----------------
__device__ float g_Wh[2][N8][HID];                          // fp32 Wh (for u/v dots)
__device__ __align__(16) __nv_bfloat16 g_WhT_bf[2][HID][N8];// bf16 transposed Wh (B operand)
__device__ float g_u[2][N8], g_v[2][N8];
__device__ float g_A[2][N8], g_A5K[2][N8];
__device__ __align__(16) __nv_bfloat16 g_Bbf[2][N8];        // bf16 exp tables
__device__ __align__(16) __nv_bfloat16 g_B5bf[2][N8];
__device__ float g_h[N8][128];
__device__ float g_Wh2[N8][16];
__device__ __align__(16) __nv_bfloat16 g_Wh2T_bf[16][N8];
__device__ float g_u2[N8], g_v2[N8];
__device__ float g_A2[N8], g_A5K2[N8];
__device__ __align__(16) __nv_bfloat16 g_B2bf[N8];
__device__ __align__(16) __nv_bfloat16 g_B52bf[N8];
__device__ __align__(16) uint32_t g_mask32[N8][256];        // 8 MB packed adjacency
__device__ float g_max[8];

// ---------------- helpers ----------------
__device__ __forceinline__ uint32_t pack_bf(float hi, float lo) {
    uint32_t d; asm("cvt.rn.bf16x2.f32 %0, %1, %2;" : "=r"(d) : "f"(hi), "f"(lo));
    return d;
}
__device__ __forceinline__ uint32_t bfmul(uint32_t a, uint32_t b) {
    uint32_t d; asm("mul.rn.bf16x2 %0, %1, %2;" : "=r"(d) : "r"(a), "r"(b)); return d;
}
__device__ __forceinline__ uint32_t bfmax(uint32_t a, uint32_t b) {
    uint32_t d; asm("max.bf16x2 %0, %1, %2;" : "=r"(d) : "r"(a), "r"(b)); return d;
}
__device__ __forceinline__ void mma16(float* d, uint32_t a0, uint32_t a1, uint32_t a2,
                                      uint32_t a3, uint32_t b0, uint32_t b1) {
    asm volatile("mma.sync.aligned.m16n8k16.row.col.f32.bf16.bf16.f32 "
                 "{%0,%1,%2,%3}, {%4,%5,%6,%7}, {%8,%9}, {%0,%1,%2,%3};"
                 : "+f"(d[0]), "+f"(d[1]), "+f"(d[2]), "+f"(d[3])
                 : "r"(a0), "r"(a1), "r"(a2), "r"(a3), "r"(b0), "r"(b1));
}
__device__ __forceinline__ int4 ldcs4(const int* p) {
    int4 v;
    asm volatile("ld.global.cs.v4.s32 {%0,%1,%2,%3}, [%4];"
                 : "=r"(v.x), "=r"(v.y), "=r"(v.z), "=r"(v.w) : "l"(p));
    return v;
}

// ---------------- K0: pack adj -> bitmask (the only reader of adj) ----------------
__global__ void k_pack(const int* __restrict__ adj) {
    const size_t g = (size_t)blockIdx.x * 256 + threadIdx.x;  // one int4 per thread
    const int lane = threadIdx.x & 31;
    int4 a = ldcs4(adj + g * 4);
    unsigned nib = (unsigned)(a.x != 0) | ((unsigned)(a.y != 0) << 1) |
                   ((unsigned)(a.z != 0) << 2) | ((unsigned)(a.w != 0) << 3);
    unsigned w = nib << ((lane & 7) * 4);
    w |= __shfl_xor_sync(0xffffffffu, w, 1);
    w |= __shfl_xor_sync(0xffffffffu, w, 2);
    w |= __shfl_xor_sync(0xffffffffu, w, 4);
    if ((lane & 7) == 0) ((uint32_t*)g_mask32)[g >> 3] = w;
}

// ---------------- K1: Wh = x @ W_h (+ bf16 transposed copy) ----------------
__global__ void k_gemm1(const float* __restrict__ x, const float* __restrict__ W_heads) {
    __shared__ float xs[64][FIN];
    __shared__ float ws[FIN][HID];
    const int h = blockIdx.y, i0 = blockIdx.x * 64, tid = threadIdx.x;
    const float4* xg = (const float4*)(x + (size_t)i0 * FIN);
    const float4* wg = (const float4*)(W_heads + (size_t)h * FIN * HID);
#pragma unroll
    for (int it = 0; it < 4; it++) ((float4*)xs)[tid + it * 256] = xg[tid + it * 256];
#pragma unroll
    for (int it = 0; it < 4; it++) ((float4*)ws)[tid + it * 256] = wg[tid + it * 256];
    __syncthreads();
    const int f = (tid & 15) * 4, ig = tid >> 4;
    float acc[4][4] = {};
#pragma unroll 4
    for (int k = 0; k < FIN; k++) {
        float4 wv = *(const float4*)&ws[k][f];
#pragma unroll
        for (int r = 0; r < 4; r++) {
            float xv = xs[ig * 4 + r][k];
            acc[r][0] = fmaf(xv, wv.x, acc[r][0]);
            acc[r][1] = fmaf(xv, wv.y, acc[r][1]);
            acc[r][2] = fmaf(xv, wv.z, acc[r][2]);
            acc[r][3] = fmaf(xv, wv.w, acc[r][3]);
        }
    }
#pragma unroll
    for (int r = 0; r < 4; r++) {
        const int row = i0 + ig * 4 + r;
        *(float4*)&g_Wh[h][row][f] = make_float4(acc[r][0], acc[r][1], acc[r][2], acc[r][3]);
#pragma unroll
        for (int c = 0; c < 4; c++) g_WhT_bf[h][f + c][row] = __float2bfloat16(acc[r][c]);
    }
}

// ---------------- K2: u, v ----------------
__global__ void k_uv1(const float* __restrict__ a_heads) {
    const int h = blockIdx.y, wid = threadIdx.x >> 5, lane = threadIdx.x & 31;
    const int i = blockIdx.x * 8 + wid;
    const float* a = a_heads + (size_t)h * 2 * HID;
    const float* w = &g_Wh[h][i][0];
    float pu = fmaf(w[lane], a[lane], w[lane + 32] * a[lane + 32]);
    float pv = fmaf(w[lane], a[HID + lane], w[lane + 32] * a[HID + lane + 32]);
#pragma unroll
    for (int o = 16; o; o >>= 1) {
        pu += __shfl_xor_sync(0xffffffffu, pu, o);
        pv += __shfl_xor_sync(0xffffffffu, pv, o);
    }
    if (lane == 0) { g_u[h][i] = pu; g_v[h][i] = pv; }
}

// ---------------- K3: global max ----------------
__global__ void k_max(int base) {
    const int which = base + blockIdx.x;
    const float* src = (which == 0) ? g_u[0] : (which == 1) ? g_v[0] :
                       (which == 2) ? g_u[1] : (which == 3) ? g_v[1] :
                       (which == 4) ? g_u2 : g_v2;
    __shared__ float red[32];
    float m = -3.0e38f;
    for (int i = threadIdx.x; i < N8; i += blockDim.x) m = fmaxf(m, src[i]);
#pragma unroll
    for (int o = 16; o; o >>= 1) m = fmaxf(m, __shfl_xor_sync(0xffffffffu, m, o));
    if ((threadIdx.x & 31) == 0) red[threadIdx.x >> 5] = m;
    __syncthreads();
    if (threadIdx.x < 32) {
        float mm = red[threadIdx.x];
#pragma unroll
        for (int o = 16; o; o >>= 1) mm = fmaxf(mm, __shfl_xor_sync(0xffffffffu, mm, o));
        if (threadIdx.x == 0) g_max[which] = mm;
    }
}

// ---------------- K4: exp tables ----------------
__global__ void k_exp1() {
    const int i = blockIdx.x * 256 + threadIdx.x, h = blockIdx.y;
    const float um = g_max[h * 2], vm = g_max[h * 2 + 1], c = um + vm;
    const float u = g_u[h][i], v = g_v[h][i];
    g_A[h][i]    = expf(u - um);
    g_A5K[h][i]  = expf(0.2f * (u - um) - 0.8f * c);
    g_Bbf[h][i]  = __float2bfloat16(expf(v - vm));
    g_B5bf[h][i] = __float2bfloat16(expf(0.2f * (v - vm)));
}
__global__ void k_exp2() {
    const int i = blockIdx.x * 256 + threadIdx.x;
    const float um = g_max[4], vm = g_max[5], c = um + vm;
    const float u = g_u2[i], v = g_v2[i];
    g_A2[i]    = expf(u - um);
    g_A5K2[i]  = expf(0.2f * (u - um) - 0.8f * c);
    g_B2bf[i]  = __float2bfloat16(expf(v - vm));
    g_B52bf[i] = __float2bfloat16(expf(0.2f * (v - vm)));
}

// ---------------- K5: layer-1 attention, bf16 mma + ones-column Z ----------------
// CTA = 64 rows, 256 threads, 256 tiles of 32 j.
__global__ __launch_bounds__(256) void k_attn1() {
    __shared__ __align__(16) unsigned short As[2][2][64][40];  // [buf][h][row][k]
    __shared__ __align__(16) unsigned short Bs[2][2][72][40];  // [buf][h][feat][k], 64=ones

    const int tid = threadIdx.x, lane = tid & 31, warp = tid >> 5;
    const int i0 = blockIdx.x * 64;
    const int r2 = tid >> 3, q = tid & 7;
    const int grow0 = i0 + 2 * r2, grow1 = grow0 + 1;
    const int h = warp >> 2, rb = warp & 3;
    const int la = lane >> 2, lb = lane & 3;

    uint32_t rA2[2][2], rK2[2][2];
#pragma unroll
    for (int hh = 0; hh < 2; hh++) {
        float a0 = g_A[hh][grow0], a1 = g_A[hh][grow1];
        float k0 = g_A5K[hh][grow0], k1 = g_A5K[hh][grow1];
        rA2[hh][0] = pack_bf(a0, a0); rA2[hh][1] = pack_bf(a1, a1);
        rK2[hh][0] = pack_bf(k0, k0); rK2[hh][1] = pack_bf(k1, k1);
    }

    // init ones (row 64) / zero (65..71) rows of Bs, both buffers & heads
    for (int i = tid; i < 2 * 2 * 8 * 20; i += 256) {
        int b = i / 320, rem = i % 320, hh = rem / 160, rr = (rem % 160) / 20, wi = rem % 20;
        ((uint32_t*)&Bs[b][hh][64 + rr][0])[wi] = (rr == 0) ? 0x3F803F80u : 0u;
    }

    float acc[9][4] = {};

    uint32_t p_mw[2][2];
    uint2 p_tb[2][2], p_t5[2][2];
    uint4 p_wh[2][2];

    // prefetch tile 0
    {
        const int jq = q * 4;
        p_mw[0][0] = g_mask32[grow0][0];
        p_mw[0][1] = g_mask32[grow1][0];
        p_tb[0][0] = *(const uint2*)&g_Bbf[0][jq];  p_tb[0][1] = *(const uint2*)&g_Bbf[1][jq];
        p_t5[0][0] = *(const uint2*)&g_B5bf[0][jq]; p_t5[0][1] = *(const uint2*)&g_B5bf[1][jq];
#pragma unroll
        for (int it = 0; it < 2; it++) {
            int g = tid + it * 256;
            int cc = g & 3, ff = (g >> 2) & 63, hh = g >> 8;
            p_wh[0][it] = *(const uint4*)&g_WhT_bf[hh][ff][cc * 8];
        }
    }
    __syncthreads();  // Bs const rows ready

#pragma unroll 2
    for (int t = 0; t < 256; t++) {
        const int par = t & 1;
        // ---- prefetch t+1 ----
        if (t + 1 < 256) {
            const int j0n = (t + 1) * 32, jq = j0n + q * 4;
            p_mw[par ^ 1][0] = g_mask32[grow0][t + 1];
            p_mw[par ^ 1][1] = g_mask32[grow1][t + 1];
            p_tb[par ^ 1][0] = *(const uint2*)&g_Bbf[0][jq];
            p_tb[par ^ 1][1] = *(const uint2*)&g_Bbf[1][jq];
            p_t5[par ^ 1][0] = *(const uint2*)&g_B5bf[0][jq];
            p_t5[par ^ 1][1] = *(const uint2*)&g_B5bf[1][jq];
#pragma unroll
            for (int it = 0; it < 2; it++) {
                int g = tid + it * 256;
                int cc = g & 3, ff = (g >> 2) & 63, hh = g >> 8;
                p_wh[par ^ 1][it] = *(const uint4*)&g_WhT_bf[hh][ff][j0n + cc * 8];
            }
        }
        // ---- stage B tile ----
#pragma unroll
        for (int it = 0; it < 2; it++) {
            int g = tid + it * 256;
            int cc = g & 3, ff = (g >> 2) & 63, hh = g >> 8;
            *(uint4*)&Bs[par][hh][ff][cc * 8] = p_wh[par][it];
        }
        // ---- w-gen (bf16x2 SIMD) ----
#pragma unroll
        for (int rr = 0; rr < 2; rr++) {
            const unsigned nib = (p_mw[par][rr] >> (q * 4)) & 0xFu;
            const uint32_t m01 = ((nib & 1u) ? 0x0000FFFFu : 0u) | ((nib & 2u) ? 0xFFFF0000u : 0u);
            const uint32_t m23 = ((nib & 4u) ? 0x0000FFFFu : 0u) | ((nib & 8u) ? 0xFFFF0000u : 0u);
#pragma unroll
            for (int hh = 0; hh < 2; hh++) {
                uint32_t w01 = bfmax(bfmul(rA2[hh][rr], p_tb[par][hh].x),
                                     bfmul(rK2[hh][rr], p_t5[par][hh].x)) & m01;
                uint32_t w23 = bfmax(bfmul(rA2[hh][rr], p_tb[par][hh].y),
                                     bfmul(rK2[hh][rr], p_t5[par][hh].y)) & m23;
                *(uint2*)&As[par][hh][2 * r2 + rr][q * 4] = make_uint2(w01, w23);
            }
        }
        __syncthreads();

        // ---- MMA: 2 kslices x 9 colblocks (cb 8 = ones column -> Z) ----
#pragma unroll
        for (int ks = 0; ks < 2; ks++) {
            const int k0 = ks * 16;
            const uint32_t a0 = *(const uint32_t*)&As[par][h][rb * 16 + la][k0 + 2 * lb];
            const uint32_t a1 = *(const uint32_t*)&As[par][h][rb * 16 + la + 8][k0 + 2 * lb];
            const uint32_t a2 = *(const uint32_t*)&As[par][h][rb * 16 + la][k0 + 2 * lb + 8];
            const uint32_t a3 = *(const uint32_t*)&As[par][h][rb * 16 + la + 8][k0 + 2 * lb + 8];
#pragma unroll
            for (int cb = 0; cb < 9; cb++) {
                const uint32_t b0 = *(const uint32_t*)&Bs[par][h][cb * 8 + la][k0 + 2 * lb];
                const uint32_t b1 = *(const uint32_t*)&Bs[par][h][cb * 8 + la][k0 + 2 * lb + 8];
                mma16(acc[cb], a0, a1, a2, a3, b0, b1);
            }
        }
    }

    // ---- epilogue: Z from ones column (col 64 = cb8 elem0/2 at lb==0) ----
    const float Zlo = __shfl_sync(0xffffffffu, acc[8][0], la * 4);
    const float Zhi = __shfl_sync(0xffffffffu, acc[8][2], la * 4);
    const float invLo = 1.0f / Zlo, invHi = 1.0f / Zhi;
    const int rlo = rb * 16 + la, rhi = rlo + 8;
#pragma unroll
    for (int cb = 0; cb < 8; cb++) {
        *(float2*)&g_h[i0 + rlo][h * 64 + cb * 8 + 2 * lb] =
            make_float2(acc[cb][0] * invLo, acc[cb][1] * invLo);
        *(float2*)&g_h[i0 + rhi][h * 64 + cb * 8 + 2 * lb] =
            make_float2(acc[cb][2] * invHi, acc[cb][3] * invHi);
    }
}

// ---------------- K6: Wh2 = h @ W_out (+ bf16 transposed) ----------------
__global__ void k_gemm2(const float* __restrict__ W_out) {
    __shared__ float hs[16][128];
    __shared__ float ws[128][16];
    const int tid = threadIdx.x, i0 = blockIdx.x * 16;
#pragma unroll
    for (int it = 0; it < 2; it++)
        ((float4*)hs)[tid + it * 256] = ((const float4*)&g_h[i0][0])[tid + it * 256];
#pragma unroll
    for (int it = 0; it < 2; it++)
        ((float4*)ws)[tid + it * 256] = ((const float4*)W_out)[tid + it * 256];
    __syncthreads();
    const int r = tid >> 4, f = tid & 15;
    float acc = 0.f;
#pragma unroll 8
    for (int k = 0; k < 128; k++) acc = fmaf(hs[r][k], ws[k][f], acc);
    g_Wh2[i0 + r][f] = acc;
    g_Wh2T_bf[f][i0 + r] = __float2bfloat16(acc);
}

// ---------------- K7: u2/v2 ----------------
__global__ void k_uv2(const float* __restrict__ a_out) {
    const int wid = threadIdx.x >> 5, lane = threadIdx.x & 31;
    const int i = blockIdx.x * 8 + wid;
    float pu = 0.f, pv = 0.f;
    if (lane < 16) {
        float wh = g_Wh2[i][lane];
        pu = wh * a_out[lane];
        pv = wh * a_out[16 + lane];
    }
#pragma unroll
    for (int o = 16; o; o >>= 1) {
        pu += __shfl_xor_sync(0xffffffffu, pu, o);
        pv += __shfl_xor_sync(0xffffffffu, pv, o);
    }
    if (lane == 0) { g_u2[i] = pu; g_v2[i] = pv; }
}

// ---------------- K9: output attention + elu + log_softmax ----------------
__global__ __launch_bounds__(256) void k_attn2(float* __restrict__ out) {
    __shared__ __align__(16) unsigned short As2[2][64][40];
    __shared__ __align__(16) unsigned short Bs2[2][24][40];  // row 16 = ones
    __shared__ float psum[4][32][12];
    __shared__ float os[64][17];

    const int tid = threadIdx.x, lane = tid & 31, warp = tid >> 5;
    const int i0 = blockIdx.x * 64;
    const int r2 = tid >> 3, q = tid & 7;
    const int grow0 = i0 + 2 * r2, grow1 = grow0 + 1;
    const int rb = warp & 3, kh = warp >> 2;
    const int la = lane >> 2, lb = lane & 3;
    const bool ldb = (tid < 64);

    uint32_t rA2[2], rK2[2];
    {
        float a0 = g_A2[grow0], a1 = g_A2[grow1];
        float k0 = g_A5K2[grow0], k1 = g_A5K2[grow1];
        rA2[0] = pack_bf(a0, a0); rA2[1] = pack_bf(a1, a1);
        rK2[0] = pack_bf(k0, k0); rK2[1] = pack_bf(k1, k1);
    }
    for (int i = tid; i < 2 * 8 * 20; i += 256) {
        int b = i / 160, rr = (i % 160) / 20, wi = i % 20;
        ((uint32_t*)&Bs2[b][16 + rr][0])[wi] = (rr == 0) ? 0x3F803F80u : 0u;
    }

    float acc[3][4] = {};

    uint32_t p_mw[2][2];
    uint2 p_tb[2], p_t5[2];
    uint4 p_wh[2];

    {
        const int jq = q * 4;
        p_mw[0][0] = g_mask32[grow0][0];
        p_mw[0][1] = g_mask32[grow1][0];
        p_tb[0] = *(const uint2*)&g_B2bf[jq];
        p_t5[0] = *(const uint2*)&g_B52bf[jq];
        if (ldb) p_wh[0] = *(const uint4*)&g_Wh2T_bf[tid >> 2][(tid & 3) * 8];
    }
    __syncthreads();

#pragma unroll 2
    for (int t = 0; t < 256; t++) {
        const int par = t & 1;
        if (t + 1 < 256) {
            const int j0n = (t + 1) * 32, jq = j0n + q * 4;
            p_mw[par ^ 1][0] = g_mask32[grow0][t + 1];
            p_mw[par ^ 1][1] = g_mask32[grow1][t + 1];
            p_tb[par ^ 1] = *(const uint2*)&g_B2bf[jq];
            p_t5[par ^ 1] = *(const uint2*)&g_B52bf[jq];
            if (ldb) p_wh[par ^ 1] = *(const uint4*)&g_Wh2T_bf[tid >> 2][j0n + (tid & 3) * 8];
        }
        if (ldb) *(uint4*)&Bs2[par][tid >> 2][(tid & 3) * 8] = p_wh[par];
#pragma unroll
        for (int rr = 0; rr < 2; rr++) {
            const unsigned nib = (p_mw[par][rr] >> (q * 4)) & 0xFu;
            const uint32_t m01 = ((nib & 1u) ? 0x0000FFFFu : 0u) | ((nib & 2u) ? 0xFFFF0000u : 0u);
            const uint32_t m23 = ((nib & 4u) ? 0x0000FFFFu : 0u) | ((nib & 8u) ? 0xFFFF0000u : 0u);
            uint32_t w01 = bfmax(bfmul(rA2[rr], p_tb[par].x), bfmul(rK2[rr], p_t5[par].x)) & m01;
            uint32_t w23 = bfmax(bfmul(rA2[rr], p_tb[par].y), bfmul(rK2[rr], p_t5[par].y)) & m23;
            *(uint2*)&As2[par][2 * r2 + rr][q * 4] = make_uint2(w01, w23);
        }
        __syncthreads();

        // MMA: this warp's kslice (kh) x 3 colblocks (cb2 = ones -> Z)
        {
            const int k0 = kh * 16;
            const uint32_t a0 = *(const uint32_t*)&As2[par][rb * 16 + la][k0 + 2 * lb];
            const uint32_t a1 = *(const uint32_t*)&As2[par][rb * 16 + la + 8][k0 + 2 * lb];
            const uint32_t a2 = *(const uint32_t*)&As2[par][rb * 16 + la][k0 + 2 * lb + 8];
            const uint32_t a3 = *(const uint32_t*)&As2[par][rb * 16 + la + 8][k0 + 2 * lb + 8];
#pragma unroll
            for (int cb = 0; cb < 3; cb++) {
                const uint32_t b0 = *(const uint32_t*)&Bs2[par][cb * 8 + la][k0 + 2 * lb];
                const uint32_t b1 = *(const uint32_t*)&Bs2[par][cb * 8 + la][k0 + 2 * lb + 8];
                mma16(acc[cb], a0, a1, a2, a3, b0, b1);
            }
        }
    }

    // k-half handoff
    if (kh == 1) {
#pragma unroll
        for (int cb = 0; cb < 3; cb++)
#pragma unroll
            for (int i = 0; i < 4; i++) psum[rb][lane][cb * 4 + i] = acc[cb][i];
    }
    __syncthreads();

    if (kh == 0) {
        float c[3][4];
#pragma unroll
        for (int cb = 0; cb < 3; cb++)
#pragma unroll
            for (int i = 0; i < 4; i++) c[cb][i] = acc[cb][i] + psum[rb][lane][cb * 4 + i];
        const float Zlo = __shfl_sync(0xffffffffu, c[2][0], la * 4);
        const float Zhi = __shfl_sync(0xffffffffu, c[2][2], la * 4);
        const float invLo = 1.0f / Zlo, invHi = 1.0f / Zhi;
        const int rlo = rb * 16 + la, rhi = rlo + 8;
#pragma unroll
        for (int cb = 0; cb < 2; cb++) {
            float v0 = c[cb][0] * invLo, v1 = c[cb][1] * invLo;
            float v2 = c[cb][2] * invHi, v3 = c[cb][3] * invHi;
            v0 = (v0 > 0.f) ? v0 : expm1f(v0);
            v1 = (v1 > 0.f) ? v1 : expm1f(v1);
            v2 = (v2 > 0.f) ? v2 : expm1f(v2);
            v3 = (v3 > 0.f) ? v3 : expm1f(v3);
            os[rlo][cb * 8 + 2 * lb]     = v0;
            os[rlo][cb * 8 + 2 * lb + 1] = v1;
            os[rhi][cb * 8 + 2 * lb]     = v2;
            os[rhi][cb * 8 + 2 * lb + 1] = v3;
        }
    }
    __syncthreads();

    if (tid < 64) {
        float o[16], mx = -3.0e38f;
#pragma unroll
        for (int c = 0; c < 16; c++) { o[c] = os[tid][c]; mx = fmaxf(mx, o[c]); }
        float s = 0.f;
#pragma unroll
        for (int c = 0; c < 16; c++) s += expf(o[c] - mx);
        const float lse = mx + logf(s);
        const int orow = i0 + tid;
#pragma unroll
        for (int qq = 0; qq < 4; qq++)
            *(float4*)&out[(size_t)orow * 16 + qq * 4] =
                make_float4(o[qq * 4] - lse, o[qq * 4 + 1] - lse,
                            o[qq * 4 + 2] - lse, o[qq * 4 + 3] - lse);
    }
}

// ---------------- launch ----------------
extern "C" void kernel_launch(void* const* d_in, const int* in_sizes, int n_in,
                              void* d_out, int out_size) {
    const float* x       = (const float*)d_in[0];
    const int*   adj     = (const int*)  d_in[1];
    const float* W_heads = (const float*)d_in[2];
    const float* a_heads = (const float*)d_in[3];
    const float* W_out   = (const float*)d_in[4];
    const float* a_out   = (const float*)d_in[5];
    float* out = (float*)d_out;

    k_pack<<<65536, 256>>>(adj);
    k_gemm1<<<dim3(N8 / 64, 2), 256>>>(x, W_heads);
    k_uv1<<<dim3(N8 / 8, 2), 256>>>(a_heads);
    k_max<<<4, 1024>>>(0);
    k_exp1<<<dim3(N8 / 256, 2), 256>>>();
    k_attn1<<<N8 / 64, 256>>>();
    k_gemm2<<<N8 / 16, 256>>>(W_out);
    k_uv2<<<N8 / 8, 256>>>(a_out);
    k_max<<<2, 1024>>>(4);
    k_exp2<<<N8 / 256, 256>>>();
    k_attn2<<<N8 / 64, 256>>>(out);
}

// round 12
// speedup vs baseline: 4.1931x; 1.1216x over previous
#include <cuda_runtime.h>
#include <cuda_bf16.h>
#include <math.h>
#include <stdint.h>

#define N8   8192
#define FIN  64
#define HID  64

// ---------------- device scratch ----------------
__device__ float g_Wh[2][N8][HID];
__device__ __align__(16) __nv_bfloat16 g_WhT_bf[2][HID][N8];
__device__ float g_u[2][N8], g_v[2][N8];
__device__ float g_A[2][N8], g_A5K[2][N8];
__device__ __align__(16) __nv_bfloat16 g_Bbf[2][N8];
__device__ __align__(16) __nv_bfloat16 g_B5bf[2][N8];
__device__ __align__(16) float g_p1[2][2][N8][72];   // [jh][h][row][0..63 acc, 64 Z]
__device__ float g_h[N8][128];
__device__ float g_Wh2[N8][16];
__device__ __align__(16) __nv_bfloat16 g_Wh2T_bf[16][N8];
__device__ float g_u2[N8], g_v2[N8];
__device__ float g_A2[N8], g_A5K2[N8];
__device__ __align__(16) __nv_bfloat16 g_B2bf[N8];
__device__ __align__(16) __nv_bfloat16 g_B52bf[N8];
__device__ __align__(16) float g_p2[2][N8][20];      // [jh][row][0..15 acc, 16 Z]
__device__ __align__(16) uint32_t g_mask32[N8][256];
__device__ float g_max[8];

// ---------------- helpers ----------------
__device__ __forceinline__ uint32_t pack_bf(float hi, float lo) {
    uint32_t d; asm("cvt.rn.bf16x2.f32 %0, %1, %2;" : "=r"(d) : "f"(hi), "f"(lo));
    return d;
}
__device__ __forceinline__ uint32_t bfmul(uint32_t a, uint32_t b) {
    uint32_t d; asm("mul.rn.bf16x2 %0, %1, %2;" : "=r"(d) : "r"(a), "r"(b)); return d;
}
__device__ __forceinline__ uint32_t bfmax(uint32_t a, uint32_t b) {
    uint32_t d; asm("max.bf16x2 %0, %1, %2;" : "=r"(d) : "r"(a), "r"(b)); return d;
}
__device__ __forceinline__ void mma16(float* d, uint32_t a0, uint32_t a1, uint32_t a2,
                                      uint32_t a3, uint32_t b0, uint32_t b1) {
    asm volatile("mma.sync.aligned.m16n8k16.row.col.f32.bf16.bf16.f32 "
                 "{%0,%1,%2,%3}, {%4,%5,%6,%7}, {%8,%9}, {%0,%1,%2,%3};"
                 : "+f"(d[0]), "+f"(d[1]), "+f"(d[2]), "+f"(d[3])
                 : "r"(a0), "r"(a1), "r"(a2), "r"(a3), "r"(b0), "r"(b1));
}
__device__ __forceinline__ int4 ldcs4(const int* p) {
    int4 v;
    asm volatile("ld.global.cs.v4.s32 {%0,%1,%2,%3}, [%4];"
                 : "=r"(v.x), "=r"(v.y), "=r"(v.z), "=r"(v.w) : "l"(p));
    return v;
}

// ---------------- K0: pack adj -> bitmask ----------------
__global__ void k_pack(const int* __restrict__ adj) {
    const size_t g = (size_t)blockIdx.x * 256 + threadIdx.x;
    const int lane = threadIdx.x & 31;
    int4 a = ldcs4(adj + g * 4);
    unsigned nib = (unsigned)(a.x != 0) | ((unsigned)(a.y != 0) << 1) |
                   ((unsigned)(a.z != 0) << 2) | ((unsigned)(a.w != 0) << 3);
    unsigned w = nib << ((lane & 7) * 4);
    w |= __shfl_xor_sync(0xffffffffu, w, 1);
    w |= __shfl_xor_sync(0xffffffffu, w, 2);
    w |= __shfl_xor_sync(0xffffffffu, w, 4);
    if ((lane & 7) == 0) ((uint32_t*)g_mask32)[g >> 3] = w;
}

// ---------------- K1: Wh = x @ W_h (+ bf16 transposed copy) ----------------
__global__ void k_gemm1(const float* __restrict__ x, const float* __restrict__ W_heads) {
    __shared__ float xs[64][FIN];
    __shared__ float ws[FIN][HID];
    const int h = blockIdx.y, i0 = blockIdx.x * 64, tid = threadIdx.x;
    const float4* xg = (const float4*)(x + (size_t)i0 * FIN);
    const float4* wg = (const float4*)(W_heads + (size_t)h * FIN * HID);
#pragma unroll
    for (int it = 0; it < 4; it++) ((float4*)xs)[tid + it * 256] = xg[tid + it * 256];
#pragma unroll
    for (int it = 0; it < 4; it++) ((float4*)ws)[tid + it * 256] = wg[tid + it * 256];
    __syncthreads();
    const int f = (tid & 15) * 4, ig = tid >> 4;
    float acc[4][4] = {};
#pragma unroll 4
    for (int k = 0; k < FIN; k++) {
        float4 wv = *(const float4*)&ws[k][f];
#pragma unroll
        for (int r = 0; r < 4; r++) {
            float xv = xs[ig * 4 + r][k];
            acc[r][0] = fmaf(xv, wv.x, acc[r][0]);
            acc[r][1] = fmaf(xv, wv.y, acc[r][1]);
            acc[r][2] = fmaf(xv, wv.z, acc[r][2]);
            acc[r][3] = fmaf(xv, wv.w, acc[r][3]);
        }
    }
#pragma unroll
    for (int r = 0; r < 4; r++) {
        const int row = i0 + ig * 4 + r;
        *(float4*)&g_Wh[h][row][f] = make_float4(acc[r][0], acc[r][1], acc[r][2], acc[r][3]);
#pragma unroll
        for (int c = 0; c < 4; c++) g_WhT_bf[h][f + c][row] = __float2bfloat16(acc[r][c]);
    }
}

// ---------------- K2: u, v ----------------
__global__ void k_uv1(const float* __restrict__ a_heads) {
    const int h = blockIdx.y, wid = threadIdx.x >> 5, lane = threadIdx.x & 31;
    const int i = blockIdx.x * 8 + wid;
    const float* a = a_heads + (size_t)h * 2 * HID;
    const float* w = &g_Wh[h][i][0];
    float pu = fmaf(w[lane], a[lane], w[lane + 32] * a[lane + 32]);
    float pv = fmaf(w[lane], a[HID + lane], w[lane + 32] * a[HID + lane + 32]);
#pragma unroll
    for (int o = 16; o; o >>= 1) {
        pu += __shfl_xor_sync(0xffffffffu, pu, o);
        pv += __shfl_xor_sync(0xffffffffu, pv, o);
    }
    if (lane == 0) { g_u[h][i] = pu; g_v[h][i] = pv; }
}

// ---------------- K3: global max ----------------
__global__ void k_max(int base) {
    const int which = base + blockIdx.x;
    const float* src = (which == 0) ? g_u[0] : (which == 1) ? g_v[0] :
                       (which == 2) ? g_u[1] : (which == 3) ? g_v[1] :
                       (which == 4) ? g_u2 : g_v2;
    __shared__ float red[32];
    float m = -3.0e38f;
    for (int i = threadIdx.x; i < N8; i += blockDim.x) m = fmaxf(m, src[i]);
#pragma unroll
    for (int o = 16; o; o >>= 1) m = fmaxf(m, __shfl_xor_sync(0xffffffffu, m, o));
    if ((threadIdx.x & 31) == 0) red[threadIdx.x >> 5] = m;
    __syncthreads();
    if (threadIdx.x < 32) {
        float mm = red[threadIdx.x];
#pragma unroll
        for (int o = 16; o; o >>= 1) mm = fmaxf(mm, __shfl_xor_sync(0xffffffffu, mm, o));
        if (threadIdx.x == 0) g_max[which] = mm;
    }
}

// ---------------- K4: exp tables ----------------
__global__ void k_exp1() {
    const int i = blockIdx.x * 256 + threadIdx.x, h = blockIdx.y;
    const float um = g_max[h * 2], vm = g_max[h * 2 + 1], c = um + vm;
    const float u = g_u[h][i], v = g_v[h][i];
    g_A[h][i]    = expf(u - um);
    g_A5K[h][i]  = expf(0.2f * (u - um) - 0.8f * c);
    g_Bbf[h][i]  = __float2bfloat16(expf(v - vm));
    g_B5bf[h][i] = __float2bfloat16(expf(0.2f * (v - vm)));
}
__global__ void k_exp2() {
    const int i = blockIdx.x * 256 + threadIdx.x;
    const float um = g_max[4], vm = g_max[5], c = um + vm;
    const float u = g_u2[i], v = g_v2[i];
    g_A2[i]    = expf(u - um);
    g_A5K2[i]  = expf(0.2f * (u - um) - 0.8f * c);
    g_B2bf[i]  = __float2bfloat16(expf(v - vm));
    g_B52bf[i] = __float2bfloat16(expf(0.2f * (v - vm)));
}

// ---------------- K5: layer-1 attention, j-split x2, partial output ----------------
__global__ __launch_bounds__(256, 2) void k_attn1() {
    __shared__ __align__(16) unsigned short As[2][2][64][40];
    __shared__ __align__(16) unsigned short Bs[2][2][72][40];

    const int tid = threadIdx.x, lane = tid & 31, warp = tid >> 5;
    const int i0 = blockIdx.x * 64;
    const int jh = blockIdx.y;            // j-half: tiles jh*128 .. jh*128+127
    const int r2 = tid >> 3, q = tid & 7;
    const int grow0 = i0 + 2 * r2, grow1 = grow0 + 1;
    const int h = warp >> 2, rb = warp & 3;
    const int la = lane >> 2, lb = lane & 3;

    uint32_t rA2[2][2], rK2[2][2];
#pragma unroll
    for (int hh = 0; hh < 2; hh++) {
        float a0 = g_A[hh][grow0], a1 = g_A[hh][grow1];
        float k0 = g_A5K[hh][grow0], k1 = g_A5K[hh][grow1];
        rA2[hh][0] = pack_bf(a0, a0); rA2[hh][1] = pack_bf(a1, a1);
        rK2[hh][0] = pack_bf(k0, k0); rK2[hh][1] = pack_bf(k1, k1);
    }

    for (int i = tid; i < 2 * 2 * 8 * 20; i += 256) {
        int b = i / 320, rem = i % 320, hh = rem / 160, rr = (rem % 160) / 20, wi = rem % 20;
        ((uint32_t*)&Bs[b][hh][64 + rr][0])[wi] = (rr == 0) ? 0x3F803F80u : 0u;
    }

    float acc[9][4] = {};

    uint32_t p_mw[2][2];
    uint2 p_tb[2][2], p_t5[2][2];
    uint4 p_wh[2][2];

    {
        const int tt0 = jh * 128, jq = tt0 * 32 + q * 4;
        p_mw[0][0] = g_mask32[grow0][tt0];
        p_mw[0][1] = g_mask32[grow1][tt0];
        p_tb[0][0] = *(const uint2*)&g_Bbf[0][jq];  p_tb[0][1] = *(const uint2*)&g_Bbf[1][jq];
        p_t5[0][0] = *(const uint2*)&g_B5bf[0][jq]; p_t5[0][1] = *(const uint2*)&g_B5bf[1][jq];
#pragma unroll
        for (int it = 0; it < 2; it++) {
            int g = tid + it * 256;
            int cc = g & 3, ff = (g >> 2) & 63, hh = g >> 8;
            p_wh[0][it] = *(const uint4*)&g_WhT_bf[hh][ff][tt0 * 32 + cc * 8];
        }
    }
    __syncthreads();

#pragma unroll 2
    for (int t = 0; t < 128; t++) {
        const int par = t & 1;
        if (t + 1 < 128) {
            const int ttn = jh * 128 + t + 1, j0n = ttn * 32, jq = j0n + q * 4;
            p_mw[par ^ 1][0] = g_mask32[grow0][ttn];
            p_mw[par ^ 1][1] = g_mask32[grow1][ttn];
            p_tb[par ^ 1][0] = *(const uint2*)&g_Bbf[0][jq];
            p_tb[par ^ 1][1] = *(const uint2*)&g_Bbf[1][jq];
            p_t5[par ^ 1][0] = *(const uint2*)&g_B5bf[0][jq];
            p_t5[par ^ 1][1] = *(const uint2*)&g_B5bf[1][jq];
#pragma unroll
            for (int it = 0; it < 2; it++) {
                int g = tid + it * 256;
                int cc = g & 3, ff = (g >> 2) & 63, hh = g >> 8;
                p_wh[par ^ 1][it] = *(const uint4*)&g_WhT_bf[hh][ff][j0n + cc * 8];
            }
        }
#pragma unroll
        for (int it = 0; it < 2; it++) {
            int g = tid + it * 256;
            int cc = g & 3, ff = (g >> 2) & 63, hh = g >> 8;
            *(uint4*)&Bs[par][hh][ff][cc * 8] = p_wh[par][it];
        }
#pragma unroll
        for (int rr = 0; rr < 2; rr++) {
            const unsigned nib = (p_mw[par][rr] >> (q * 4)) & 0xFu;
            const uint32_t m01 = ((nib & 1u) ? 0x0000FFFFu : 0u) | ((nib & 2u) ? 0xFFFF0000u : 0u);
            const uint32_t m23 = ((nib & 4u) ? 0x0000FFFFu : 0u) | ((nib & 8u) ? 0xFFFF0000u : 0u);
#pragma unroll
            for (int hh = 0; hh < 2; hh++) {
                uint32_t w01 = bfmax(bfmul(rA2[hh][rr], p_tb[par][hh].x),
                                     bfmul(rK2[hh][rr], p_t5[par][hh].x)) & m01;
                uint32_t w23 = bfmax(bfmul(rA2[hh][rr], p_tb[par][hh].y),
                                     bfmul(rK2[hh][rr], p_t5[par][hh].y)) & m23;
                *(uint2*)&As[par][hh][2 * r2 + rr][q * 4] = make_uint2(w01, w23);
            }
        }
        __syncthreads();

#pragma unroll
        for (int ks = 0; ks < 2; ks++) {
            const int k0 = ks * 16;
            const uint32_t a0 = *(const uint32_t*)&As[par][h][rb * 16 + la][k0 + 2 * lb];
            const uint32_t a1 = *(const uint32_t*)&As[par][h][rb * 16 + la + 8][k0 + 2 * lb];
            const uint32_t a2 = *(const uint32_t*)&As[par][h][rb * 16 + la][k0 + 2 * lb + 8];
            const uint32_t a3 = *(const uint32_t*)&As[par][h][rb * 16 + la + 8][k0 + 2 * lb + 8];
#pragma unroll
            for (int cb = 0; cb < 9; cb++) {
                const uint32_t b0 = *(const uint32_t*)&Bs[par][h][cb * 8 + la][k0 + 2 * lb];
                const uint32_t b1 = *(const uint32_t*)&Bs[par][h][cb * 8 + la][k0 + 2 * lb + 8];
                mma16(acc[cb], a0, a1, a2, a3, b0, b1);
            }
        }
    }

    // partial store (no normalization, no shuffles)
    const int rlo = rb * 16 + la, rhi = rlo + 8;
#pragma unroll
    for (int cb = 0; cb < 8; cb++) {
        *(float2*)&g_p1[jh][h][i0 + rlo][cb * 8 + 2 * lb] = make_float2(acc[cb][0], acc[cb][1]);
        *(float2*)&g_p1[jh][h][i0 + rhi][cb * 8 + 2 * lb] = make_float2(acc[cb][2], acc[cb][3]);
    }
    if (lb == 0) {
        g_p1[jh][h][i0 + rlo][64] = acc[8][0];
        g_p1[jh][h][i0 + rhi][64] = acc[8][2];
    }
}

// ---------------- K5b: combine layer-1 halves ----------------
__global__ void k_comb1() {
    const int tid = threadIdx.x;
    const int row = blockIdx.x * 64 + (tid >> 2);
    const int part = tid & 3;
    const int h = part >> 1;
    const int fbase = (part & 1) * 32;
    const float Z = g_p1[0][h][row][64] + g_p1[1][h][row][64];
    const float inv = 1.0f / Z;
#pragma unroll
    for (int i = 0; i < 8; i++) {
        float4 a = *(const float4*)&g_p1[0][h][row][fbase + i * 4];
        float4 b = *(const float4*)&g_p1[1][h][row][fbase + i * 4];
        *(float4*)&g_h[row][h * 64 + fbase + i * 4] =
            make_float4((a.x + b.x) * inv, (a.y + b.y) * inv,
                        (a.z + b.z) * inv, (a.w + b.w) * inv);
    }
}

// ---------------- K6: Wh2 = h @ W_out (+ bf16 transposed) ----------------
__global__ void k_gemm2(const float* __restrict__ W_out) {
    __shared__ float hs[16][128];
    __shared__ float ws[128][16];
    const int tid = threadIdx.x, i0 = blockIdx.x * 16;
#pragma unroll
    for (int it = 0; it < 2; it++)
        ((float4*)hs)[tid + it * 256] = ((const float4*)&g_h[i0][0])[tid + it * 256];
#pragma unroll
    for (int it = 0; it < 2; it++)
        ((float4*)ws)[tid + it * 256] = ((const float4*)W_out)[tid + it * 256];
    __syncthreads();
    const int r = tid >> 4, f = tid & 15;
    float acc = 0.f;
#pragma unroll 8
    for (int k = 0; k < 128; k++) acc = fmaf(hs[r][k], ws[k][f], acc);
    g_Wh2[i0 + r][f] = acc;
    g_Wh2T_bf[f][i0 + r] = __float2bfloat16(acc);
}

// ---------------- K7: u2/v2 ----------------
__global__ void k_uv2(const float* __restrict__ a_out) {
    const int wid = threadIdx.x >> 5, lane = threadIdx.x & 31;
    const int i = blockIdx.x * 8 + wid;
    float pu = 0.f, pv = 0.f;
    if (lane < 16) {
        float wh = g_Wh2[i][lane];
        pu = wh * a_out[lane];
        pv = wh * a_out[16 + lane];
    }
#pragma unroll
    for (int o = 16; o; o >>= 1) {
        pu += __shfl_xor_sync(0xffffffffu, pu, o);
        pv += __shfl_xor_sync(0xffffffffu, pv, o);
    }
    if (lane == 0) { g_u2[i] = pu; g_v2[i] = pv; }
}

// ---------------- K9: output attention, j-split x2, partial output ----------------
__global__ __launch_bounds__(256, 2) void k_attn2() {
    __shared__ __align__(16) unsigned short As2[2][64][40];
    __shared__ __align__(16) unsigned short Bs2[2][24][40];
    __shared__ float psum[4][32][12];

    const int tid = threadIdx.x, lane = tid & 31, warp = tid >> 5;
    const int i0 = blockIdx.x * 64;
    const int jh = blockIdx.y;
    const int r2 = tid >> 3, q = tid & 7;
    const int grow0 = i0 + 2 * r2, grow1 = grow0 + 1;
    const int rb = warp & 3, kh = warp >> 2;
    const int la = lane >> 2, lb = lane & 3;
    const bool ldb = (tid < 64);

    uint32_t rA2[2], rK2[2];
    {
        float a0 = g_A2[grow0], a1 = g_A2[grow1];
        float k0 = g_A5K2[grow0], k1 = g_A5K2[grow1];
        rA2[0] = pack_bf(a0, a0); rA2[1] = pack_bf(a1, a1);
        rK2[0] = pack_bf(k0, k0); rK2[1] = pack_bf(k1, k1);
    }
    for (int i = tid; i < 2 * 8 * 20; i += 256) {
        int b = i / 160, rr = (i % 160) / 20, wi = i % 20;
        ((uint32_t*)&Bs2[b][16 + rr][0])[wi] = (rr == 0) ? 0x3F803F80u : 0u;
    }

    float acc[3][4] = {};

    uint32_t p_mw[2][2];
    uint2 p_tb[2], p_t5[2];
    uint4 p_wh[2];

    {
        const int tt0 = jh * 128, jq = tt0 * 32 + q * 4;
        p_mw[0][0] = g_mask32[grow0][tt0];
        p_mw[0][1] = g_mask32[grow1][tt0];
        p_tb[0] = *(const uint2*)&g_B2bf[jq];
        p_t5[0] = *(const uint2*)&g_B52bf[jq];
        if (ldb) p_wh[0] = *(const uint4*)&g_Wh2T_bf[tid >> 2][tt0 * 32 + (tid & 3) * 8];
    }
    __syncthreads();

#pragma unroll 2
    for (int t = 0; t < 128; t++) {
        const int par = t & 1;
        if (t + 1 < 128) {
            const int ttn = jh * 128 + t + 1, j0n = ttn * 32, jq = j0n + q * 4;
            p_mw[par ^ 1][0] = g_mask32[grow0][ttn];
            p_mw[par ^ 1][1] = g_mask32[grow1][ttn];
            p_tb[par ^ 1] = *(const uint2*)&g_B2bf[jq];
            p_t5[par ^ 1] = *(const uint2*)&g_B52bf[jq];
            if (ldb) p_wh[par ^ 1] = *(const uint4*)&g_Wh2T_bf[tid >> 2][j0n + (tid & 3) * 8];
        }
        if (ldb) *(uint4*)&Bs2[par][tid >> 2][(tid & 3) * 8] = p_wh[par];
#pragma unroll
        for (int rr = 0; rr < 2; rr++) {
            const unsigned nib = (p_mw[par][rr] >> (q * 4)) & 0xFu;
            const uint32_t m01 = ((nib & 1u) ? 0x0000FFFFu : 0u) | ((nib & 2u) ? 0xFFFF0000u : 0u);
            const uint32_t m23 = ((nib & 4u) ? 0x0000FFFFu : 0u) | ((nib & 8u) ? 0xFFFF0000u : 0u);
            uint32_t w01 = bfmax(bfmul(rA2[rr], p_tb[par].x), bfmul(rK2[rr], p_t5[par].x)) & m01;
            uint32_t w23 = bfmax(bfmul(rA2[rr], p_tb[par].y), bfmul(rK2[rr], p_t5[par].y)) & m23;
            *(uint2*)&As2[par][2 * r2 + rr][q * 4] = make_uint2(w01, w23);
        }
        __syncthreads();

        {
            const int k0 = kh * 16;
            const uint32_t a0 = *(const uint32_t*)&As2[par][rb * 16 + la][k0 + 2 * lb];
            const uint32_t a1 = *(const uint32_t*)&As2[par][rb * 16 + la + 8][k0 + 2 * lb];
            const uint32_t a2 = *(const uint32_t*)&As2[par][rb * 16 + la][k0 + 2 * lb + 8];
            const uint32_t a3 = *(const uint32_t*)&As2[par][rb * 16 + la + 8][k0 + 2 * lb + 8];
#pragma unroll
            for (int cb = 0; cb < 3; cb++) {
                const uint32_t b0 = *(const uint32_t*)&Bs2[par][cb * 8 + la][k0 + 2 * lb];
                const uint32_t b1 = *(const uint32_t*)&Bs2[par][cb * 8 + la][k0 + 2 * lb + 8];
                mma16(acc[cb], a0, a1, a2, a3, b0, b1);
            }
        }
    }

    if (kh == 1) {
#pragma unroll
        for (int cb = 0; cb < 3; cb++)
#pragma unroll
            for (int i = 0; i < 4; i++) psum[rb][lane][cb * 4 + i] = acc[cb][i];
    }
    __syncthreads();

    if (kh == 0) {
        float c[3][4];
#pragma unroll
        for (int cb = 0; cb < 3; cb++)
#pragma unroll
            for (int i = 0; i < 4; i++) c[cb][i] = acc[cb][i] + psum[rb][lane][cb * 4 + i];
        const int rlo = rb * 16 + la, rhi = rlo + 8;
#pragma unroll
        for (int cb = 0; cb < 2; cb++) {
            *(float2*)&g_p2[jh][i0 + rlo][cb * 8 + 2 * lb] = make_float2(c[cb][0], c[cb][1]);
            *(float2*)&g_p2[jh][i0 + rhi][cb * 8 + 2 * lb] = make_float2(c[cb][2], c[cb][3]);
        }
        if (lb == 0) {
            g_p2[jh][i0 + rlo][16] = c[2][0];
            g_p2[jh][i0 + rhi][16] = c[2][2];
        }
    }
}

// ---------------- K10: combine + elu + log_softmax ----------------
__global__ void k_fin2(float* __restrict__ out) {
    const int tid = threadIdx.x;
    const int row = blockIdx.x * 64 + (tid >> 2);
    const int qq = tid & 3;
    const float Z = g_p2[0][row][16] + g_p2[1][row][16];
    const float inv = 1.0f / Z;
    float4 a = *(const float4*)&g_p2[0][row][qq * 4];
    float4 b = *(const float4*)&g_p2[1][row][qq * 4];
    float v[4] = {(a.x + b.x) * inv, (a.y + b.y) * inv,
                  (a.z + b.z) * inv, (a.w + b.w) * inv};
    float mx = -3.0e38f;
#pragma unroll
    for (int i = 0; i < 4; i++) {
        v[i] = (v[i] > 0.f) ? v[i] : expm1f(v[i]);
        mx = fmaxf(mx, v[i]);
    }
    mx = fmaxf(mx, __shfl_xor_sync(0xffffffffu, mx, 1));
    mx = fmaxf(mx, __shfl_xor_sync(0xffffffffu, mx, 2));
    float s = 0.f;
#pragma unroll
    for (int i = 0; i < 4; i++) s += expf(v[i] - mx);
    s += __shfl_xor_sync(0xffffffffu, s, 1);
    s += __shfl_xor_sync(0xffffffffu, s, 2);
    const float lse = mx + logf(s);
    *(float4*)&out[(size_t)row * 16 + qq * 4] =
        make_float4(v[0] - lse, v[1] - lse, v[2] - lse, v[3] - lse);
}

// ---------------- launch ----------------
extern "C" void kernel_launch(void* const* d_in, const int* in_sizes, int n_in,
                              void* d_out, int out_size) {
    const float* x       = (const float*)d_in[0];
    const int*   adj     = (const int*)  d_in[1];
    const float* W_heads = (const float*)d_in[2];
    const float* a_heads = (const float*)d_in[3];
    const float* W_out   = (const float*)d_in[4];
    const float* a_out   = (const float*)d_in[5];
    float* out = (float*)d_out;

    k_pack<<<65536, 256>>>(adj);
    k_gemm1<<<dim3(N8 / 64, 2), 256>>>(x, W_heads);
    k_uv1<<<dim3(N8 / 8, 2), 256>>>(a_heads);
    k_max<<<4, 1024>>>(0);
    k_exp1<<<dim3(N8 / 256, 2), 256>>>();
    k_attn1<<<dim3(N8 / 64, 2), 256>>>();
    k_comb1<<<N8 / 64, 256>>>();
    k_gemm2<<<N8 / 16, 256>>>(W_out);
    k_uv2<<<N8 / 8, 256>>>(a_out);
    k_max<<<2, 1024>>>(4);
    k_exp2<<<N8 / 256, 256>>>();
    k_attn2<<<dim3(N8 / 64, 2), 256>>>();
    k_fin2<<<N8 / 64, 256>>>(out);
}

// round 13
// speedup vs baseline: 4.4775x; 1.0678x over previous
#include <cuda_runtime.h>
#include <cuda_bf16.h>
#include <math.h>
#include <stdint.h>

#define N8   8192
#define FIN  64
#define HID  64

// ---------------- device scratch ----------------
__device__ float g_Wh[2][N8][HID];
__device__ __align__(16) __nv_bfloat16 g_WhT_bf[2][HID][N8];
__device__ float g_u[2][N8], g_v[2][N8];
__device__ float g_A[2][N8], g_A5K[2][N8];
__device__ __align__(16) __nv_bfloat16 g_Bbf[2][N8];
__device__ __align__(16) __nv_bfloat16 g_B5bf[2][N8];
__device__ __align__(16) float g_p1[4][2][N8][72];   // [jh*2+ks][h][row][0..63 acc, 64 Z]
__device__ float g_Wh2[N8][16];
__device__ __align__(16) __nv_bfloat16 g_Wh2T_bf[16][N8];
__device__ float g_u2[N8], g_v2[N8];
__device__ float g_A2[N8], g_A5K2[N8];
__device__ __align__(16) __nv_bfloat16 g_B2bf[N8];
__device__ __align__(16) __nv_bfloat16 g_B52bf[N8];
__device__ __align__(16) float g_p2[4][N8][20];      // [jh*2+ks][row][0..15 acc, 16 Z]
__device__ __align__(16) uint32_t g_mask32[N8][256];
__device__ float g_max[8];

// ---------------- helpers ----------------
__device__ __forceinline__ uint32_t pack_bf(float hi, float lo) {
    uint32_t d; asm("cvt.rn.bf16x2.f32 %0, %1, %2;" : "=r"(d) : "f"(hi), "f"(lo));
    return d;
}
__device__ __forceinline__ uint32_t bfmul(uint32_t a, uint32_t b) {
    uint32_t d; asm("mul.rn.bf16x2 %0, %1, %2;" : "=r"(d) : "r"(a), "r"(b)); return d;
}
__device__ __forceinline__ uint32_t bfmax(uint32_t a, uint32_t b) {
    uint32_t d; asm("max.bf16x2 %0, %1, %2;" : "=r"(d) : "r"(a), "r"(b)); return d;
}
// expand 2 mask bits (at position sh, sh+1) to a bf16x2 lane mask
__device__ __forceinline__ uint32_t mexp(uint32_t mw, int sh) {
    uint32_t b = mw >> sh;
    return ((b & 1u) ? 0x0000FFFFu : 0u) | ((b & 2u) ? 0xFFFF0000u : 0u);
}
__device__ __forceinline__ void mma16(float* d, uint32_t a0, uint32_t a1, uint32_t a2,
                                      uint32_t a3, uint32_t b0, uint32_t b1) {
    asm volatile("mma.sync.aligned.m16n8k16.row.col.f32.bf16.bf16.f32 "
                 "{%0,%1,%2,%3}, {%4,%5,%6,%7}, {%8,%9}, {%0,%1,%2,%3};"
                 : "+f"(d[0]), "+f"(d[1]), "+f"(d[2]), "+f"(d[3])
                 : "r"(a0), "r"(a1), "r"(a2), "r"(a3), "r"(b0), "r"(b1));
}
__device__ __forceinline__ int4 ldcs4(const int* p) {
    int4 v;
    asm volatile("ld.global.cs.v4.s32 {%0,%1,%2,%3}, [%4];"
                 : "=r"(v.x), "=r"(v.y), "=r"(v.z), "=r"(v.w) : "l"(p));
    return v;
}

// ---------------- K0: pack adj -> bitmask ----------------
__global__ void k_pack(const int* __restrict__ adj) {
    const size_t g = (size_t)blockIdx.x * 256 + threadIdx.x;
    const int lane = threadIdx.x & 31;
    int4 a = ldcs4(adj + g * 4);
    unsigned nib = (unsigned)(a.x != 0) | ((unsigned)(a.y != 0) << 1) |
                   ((unsigned)(a.z != 0) << 2) | ((unsigned)(a.w != 0) << 3);
    unsigned w = nib << ((lane & 7) * 4);
    w |= __shfl_xor_sync(0xffffffffu, w, 1);
    w |= __shfl_xor_sync(0xffffffffu, w, 2);
    w |= __shfl_xor_sync(0xffffffffu, w, 4);
    if ((lane & 7) == 0) ((uint32_t*)g_mask32)[g >> 3] = w;
}

// ---------------- K1: Wh = x @ W_h (+ bf16 transposed copy) ----------------
__global__ void k_gemm1(const float* __restrict__ x, const float* __restrict__ W_heads) {
    __shared__ float xs[64][FIN];
    __shared__ float ws[FIN][HID];
    const int h = blockIdx.y, i0 = blockIdx.x * 64, tid = threadIdx.x;
    const float4* xg = (const float4*)(x + (size_t)i0 * FIN);
    const float4* wg = (const float4*)(W_heads + (size_t)h * FIN * HID);
#pragma unroll
    for (int it = 0; it < 4; it++) ((float4*)xs)[tid + it * 256] = xg[tid + it * 256];
#pragma unroll
    for (int it = 0; it < 4; it++) ((float4*)ws)[tid + it * 256] = wg[tid + it * 256];
    __syncthreads();
    const int f = (tid & 15) * 4, ig = tid >> 4;
    float acc[4][4] = {};
#pragma unroll 4
    for (int k = 0; k < FIN; k++) {
        float4 wv = *(const float4*)&ws[k][f];
#pragma unroll
        for (int r = 0; r < 4; r++) {
            float xv = xs[ig * 4 + r][k];
            acc[r][0] = fmaf(xv, wv.x, acc[r][0]);
            acc[r][1] = fmaf(xv, wv.y, acc[r][1]);
            acc[r][2] = fmaf(xv, wv.z, acc[r][2]);
            acc[r][3] = fmaf(xv, wv.w, acc[r][3]);
        }
    }
#pragma unroll
    for (int r = 0; r < 4; r++) {
        const int row = i0 + ig * 4 + r;
        *(float4*)&g_Wh[h][row][f] = make_float4(acc[r][0], acc[r][1], acc[r][2], acc[r][3]);
#pragma unroll
        for (int c = 0; c < 4; c++) g_WhT_bf[h][f + c][row] = __float2bfloat16(acc[r][c]);
    }
}

// ---------------- K2: u, v ----------------
__global__ void k_uv1(const float* __restrict__ a_heads) {
    const int h = blockIdx.y, wid = threadIdx.x >> 5, lane = threadIdx.x & 31;
    const int i = blockIdx.x * 8 + wid;
    const float* a = a_heads + (size_t)h * 2 * HID;
    const float* w = &g_Wh[h][i][0];
    float pu = fmaf(w[lane], a[lane], w[lane + 32] * a[lane + 32]);
    float pv = fmaf(w[lane], a[HID + lane], w[lane + 32] * a[HID + lane + 32]);
#pragma unroll
    for (int o = 16; o; o >>= 1) {
        pu += __shfl_xor_sync(0xffffffffu, pu, o);
        pv += __shfl_xor_sync(0xffffffffu, pv, o);
    }
    if (lane == 0) { g_u[h][i] = pu; g_v[h][i] = pv; }
}

// ---------------- K3: global max ----------------
__global__ void k_max(int base) {
    const int which = base + blockIdx.x;
    const float* src = (which == 0) ? g_u[0] : (which == 1) ? g_v[0] :
                       (which == 2) ? g_u[1] : (which == 3) ? g_v[1] :
                       (which == 4) ? g_u2 : g_v2;
    __shared__ float red[32];
    float m = -3.0e38f;
    for (int i = threadIdx.x; i < N8; i += blockDim.x) m = fmaxf(m, src[i]);
#pragma unroll
    for (int o = 16; o; o >>= 1) m = fmaxf(m, __shfl_xor_sync(0xffffffffu, m, o));
    if ((threadIdx.x & 31) == 0) red[threadIdx.x >> 5] = m;
    __syncthreads();
    if (threadIdx.x < 32) {
        float mm = red[threadIdx.x];
#pragma unroll
        for (int o = 16; o; o >>= 1) mm = fmaxf(mm, __shfl_xor_sync(0xffffffffu, mm, o));
        if (threadIdx.x == 0) g_max[which] = mm;
    }
}

// ---------------- K4: exp tables ----------------
__global__ void k_exp1() {
    const int i = blockIdx.x * 256 + threadIdx.x, h = blockIdx.y;
    const float um = g_max[h * 2], vm = g_max[h * 2 + 1], c = um + vm;
    const float u = g_u[h][i], v = g_v[h][i];
    g_A[h][i]    = expf(u - um);
    g_A5K[h][i]  = expf(0.2f * (u - um) - 0.8f * c);
    g_Bbf[h][i]  = __float2bfloat16(expf(v - vm));
    g_B5bf[h][i] = __float2bfloat16(expf(0.2f * (v - vm)));
}
__global__ void k_exp2() {
    const int i = blockIdx.x * 256 + threadIdx.x;
    const float um = g_max[4], vm = g_max[5], c = um + vm;
    const float u = g_u2[i], v = g_v2[i];
    g_A2[i]    = expf(u - um);
    g_A5K2[i]  = expf(0.2f * (u - um) - 0.8f * c);
    g_B2bf[i]  = __float2bfloat16(expf(v - vm));
    g_B52bf[i] = __float2bfloat16(expf(0.2f * (v - vm)));
}

// ---------------- K5: layer-1 attention, fused w-gen + mma ----------------
// CTA = 64 rows, 8 warps: h = warp>>2, p = (warp>>1)&1 (row half), ks = warp&1.
// Thread computes its own A fragments in registers; B staged in SMEM.
__global__ __launch_bounds__(256, 2) void k_attn1() {
    __shared__ __align__(16) unsigned short Bs[2][2][72][40];  // [buf][h][feat][k], 64=ones
    __shared__ uint32_t mk[2][64];

    const int tid = threadIdx.x, lane = tid & 31, warp = tid >> 5;
    const int i0 = blockIdx.x * 64;
    const int jh = blockIdx.y;
    const int h = warp >> 2, p = (warp >> 1) & 1, ks = warp & 1;
    const int la = lane >> 2, lb = lane & 3;
    const int koff = ks * 16;
    const int shlo = koff + 2 * lb, shhi = shlo + 8;

    // row set for this thread's A fragments (tile-local)
    const int R0 = 32 * p + la, R1 = R0 + 8, R2 = R0 + 16, R3 = R0 + 24;
    uint32_t fA[4], fK[4];
    {
        float a0 = g_A[h][i0 + R0], a1 = g_A[h][i0 + R1];
        float a2 = g_A[h][i0 + R2], a3 = g_A[h][i0 + R3];
        float k0 = g_A5K[h][i0 + R0], k1 = g_A5K[h][i0 + R1];
        float k2 = g_A5K[h][i0 + R2], k3 = g_A5K[h][i0 + R3];
        fA[0] = pack_bf(a0, a0); fA[1] = pack_bf(a1, a1);
        fA[2] = pack_bf(a2, a2); fA[3] = pack_bf(a3, a3);
        fK[0] = pack_bf(k0, k0); fK[1] = pack_bf(k1, k1);
        fK[2] = pack_bf(k2, k2); fK[3] = pack_bf(k3, k3);
    }

    // ones / zero rows of Bs (rows 64..71), both buffers & heads
    for (int i = tid; i < 2 * 2 * 8 * 20; i += 256) {
        int b = i / 320, rem = i % 320, hh = rem / 160, rr = (rem % 160) / 20, wi = rem % 20;
        ((uint32_t*)&Bs[b][hh][64 + rr][0])[wi] = (rr == 0) ? 0x3F803F80u : 0u;
    }

    float acc[2][9][4] = {};

    uint4 p_wh[2];
    uint32_t p_mk;

    {
        const int tt0 = jh * 128, jb = tt0 * 32;
#pragma unroll
        for (int it = 0; it < 2; it++) {
            int g = tid + it * 256;
            int cc = g & 3, ff = (g >> 2) & 63, hh = g >> 8;
            p_wh[it] = *(const uint4*)&g_WhT_bf[hh][ff][jb + cc * 8];
        }
        if (tid < 64) p_mk = g_mask32[i0 + tid][tt0];
    }
    __syncthreads();

    for (int t = 0; t < 128; t++) {
        const int par = t & 1;
        const int jbase = (jh * 128 + t) * 32;

        // stage B + masks for this tile
#pragma unroll
        for (int it = 0; it < 2; it++) {
            int g = tid + it * 256;
            int cc = g & 3, ff = (g >> 2) & 63, hh = g >> 8;
            *(uint4*)&Bs[par][hh][ff][cc * 8] = p_wh[it];
        }
        if (tid < 64) mk[par][tid] = p_mk;

        // prefetch t+1
        if (t + 1 < 128) {
            const int ttn = jh * 128 + t + 1, jbn = ttn * 32;
#pragma unroll
            for (int it = 0; it < 2; it++) {
                int g = tid + it * 256;
                int cc = g & 3, ff = (g >> 2) & 63, hh = g >> 8;
                p_wh[it] = *(const uint4*)&g_WhT_bf[hh][ff][jbn + cc * 8];
            }
            if (tid < 64) p_mk = g_mask32[i0 + tid][ttn];
        }
        __syncthreads();

        // ---- w-gen: A fragments in registers ----
        const uint32_t mw0 = mk[par][R0], mw1 = mk[par][R1];
        const uint32_t mw2 = mk[par][R2], mw3 = mk[par][R3];
        const int jb2 = jbase + shlo;
        const uint32_t tb0 = *(const uint32_t*)&g_Bbf[h][jb2];
        const uint32_t tb1 = *(const uint32_t*)&g_Bbf[h][jb2 + 8];
        const uint32_t t50 = *(const uint32_t*)&g_B5bf[h][jb2];
        const uint32_t t51 = *(const uint32_t*)&g_B5bf[h][jb2 + 8];

        uint32_t a0[4], a1[4];
        a0[0] = bfmax(bfmul(fA[0], tb0), bfmul(fK[0], t50)) & mexp(mw0, shlo);
        a0[1] = bfmax(bfmul(fA[1], tb0), bfmul(fK[1], t50)) & mexp(mw1, shlo);
        a0[2] = bfmax(bfmul(fA[0], tb1), bfmul(fK[0], t51)) & mexp(mw0, shhi);
        a0[3] = bfmax(bfmul(fA[1], tb1), bfmul(fK[1], t51)) & mexp(mw1, shhi);
        a1[0] = bfmax(bfmul(fA[2], tb0), bfmul(fK[2], t50)) & mexp(mw2, shlo);
        a1[1] = bfmax(bfmul(fA[3], tb0), bfmul(fK[3], t50)) & mexp(mw3, shlo);
        a1[2] = bfmax(bfmul(fA[2], tb1), bfmul(fK[2], t51)) & mexp(mw2, shhi);
        a1[3] = bfmax(bfmul(fA[3], tb1), bfmul(fK[3], t51)) & mexp(mw3, shhi);

        // ---- MMA: 9 colblocks, 2 m-blocks, this warp's k-slice ----
#pragma unroll
        for (int cb = 0; cb < 9; cb++) {
            const uint32_t b0 = *(const uint32_t*)&Bs[par][h][cb * 8 + la][shlo];
            const uint32_t b1 = *(const uint32_t*)&Bs[par][h][cb * 8 + la][shhi];
            mma16(acc[0][cb], a0[0], a0[1], a0[2], a0[3], b0, b1);
            mma16(acc[1][cb], a1[0], a1[1], a1[2], a1[3], b0, b1);
        }
    }

    // ---- partial store (per k-slice buffer) ----
    const int pi = jh * 2 + ks;
#pragma unroll
    for (int mb = 0; mb < 2; mb++) {
        const int rlo = i0 + 32 * p + mb * 16 + la, rhi = rlo + 8;
#pragma unroll
        for (int cb = 0; cb < 8; cb++) {
            *(float2*)&g_p1[pi][h][rlo][cb * 8 + 2 * lb] =
                make_float2(acc[mb][cb][0], acc[mb][cb][1]);
            *(float2*)&g_p1[pi][h][rhi][cb * 8 + 2 * lb] =
                make_float2(acc[mb][cb][2], acc[mb][cb][3]);
        }
        if (lb == 0) {
            g_p1[pi][h][rlo][64] = acc[mb][8][0];
            g_p1[pi][h][rhi][64] = acc[mb][8][2];
        }
    }
}

// ---------------- K6: combine layer-1 + Wh2 = h @ W_out ----------------
__global__ void k_gemm2(const float* __restrict__ W_out) {
    __shared__ float zi[16][2];
    __shared__ float hs[16][128];
    __shared__ float ws[128][16];
    const int tid = threadIdx.x, i0 = blockIdx.x * 16;

    if (tid < 32) {
        const int r = tid >> 1, h = tid & 1;
        float Z = 0.f;
#pragma unroll
        for (int pi = 0; pi < 4; pi++) Z += g_p1[pi][h][i0 + r][64];
        zi[r][h] = 1.0f / Z;
    }
#pragma unroll
    for (int it = 0; it < 2; it++)
        ((float4*)ws)[tid + it * 256] = ((const float4*)W_out)[tid + it * 256];
    __syncthreads();

#pragma unroll
    for (int it = 0; it < 2; it++) {
        int idx = tid + it * 256;
        int r = idx >> 5, c4 = (idx & 31) * 4;
        int h = c4 >> 6, f = c4 & 63;
        float4 s = make_float4(0.f, 0.f, 0.f, 0.f);
#pragma unroll
        for (int pi = 0; pi < 4; pi++) {
            float4 v = *(const float4*)&g_p1[pi][h][i0 + r][f];
            s.x += v.x; s.y += v.y; s.z += v.z; s.w += v.w;
        }
        const float iv = zi[r][h];
        *(float4*)&hs[r][c4] = make_float4(s.x * iv, s.y * iv, s.z * iv, s.w * iv);
    }
    __syncthreads();

    const int r = tid >> 4, f = tid & 15;
    float acc = 0.f;
#pragma unroll 8
    for (int k = 0; k < 128; k++) acc = fmaf(hs[r][k], ws[k][f], acc);
    g_Wh2[i0 + r][f] = acc;
    g_Wh2T_bf[f][i0 + r] = __float2bfloat16(acc);
}

// ---------------- K7: u2/v2 ----------------
__global__ void k_uv2(const float* __restrict__ a_out) {
    const int wid = threadIdx.x >> 5, lane = threadIdx.x & 31;
    const int i = blockIdx.x * 8 + wid;
    float pu = 0.f, pv = 0.f;
    if (lane < 16) {
        float wh = g_Wh2[i][lane];
        pu = wh * a_out[lane];
        pv = wh * a_out[16 + lane];
    }
#pragma unroll
    for (int o = 16; o; o >>= 1) {
        pu += __shfl_xor_sync(0xffffffffu, pu, o);
        pv += __shfl_xor_sync(0xffffffffu, pv, o);
    }
    if (lane == 0) { g_u2[i] = pu; g_v2[i] = pv; }
}

// ---------------- K9: output attention, fused w-gen + mma ----------------
// 8 warps: mb = warp>>1 (0..3), ks = warp&1.
__global__ __launch_bounds__(256, 2) void k_attn2() {
    __shared__ __align__(16) unsigned short Bs2[2][24][40];  // row 16 = ones
    __shared__ uint32_t mk2[2][64];

    const int tid = threadIdx.x, lane = tid & 31, warp = tid >> 5;
    const int i0 = blockIdx.x * 64;
    const int jh = blockIdx.y;
    const int mb = warp >> 1, ks = warp & 1;
    const int la = lane >> 2, lb = lane & 3;
    const int koff = ks * 16;
    const int shlo = koff + 2 * lb, shhi = shlo + 8;

    const int R0 = mb * 16 + la, R1 = R0 + 8;
    uint32_t fA[2], fK[2];
    {
        float a0 = g_A2[i0 + R0], a1 = g_A2[i0 + R1];
        float k0 = g_A5K2[i0 + R0], k1 = g_A5K2[i0 + R1];
        fA[0] = pack_bf(a0, a0); fA[1] = pack_bf(a1, a1);
        fK[0] = pack_bf(k0, k0); fK[1] = pack_bf(k1, k1);
    }
    for (int i = tid; i < 2 * 8 * 20; i += 256) {
        int b = i / 160, rr = (i % 160) / 20, wi = i % 20;
        ((uint32_t*)&Bs2[b][16 + rr][0])[wi] = (rr == 0) ? 0x3F803F80u : 0u;
    }

    float acc[3][4] = {};

    uint4 p_wh;
    uint32_t p_mk;
    const bool ldb = (tid < 64);

    {
        const int tt0 = jh * 128, jb = tt0 * 32;
        if (ldb) {
            p_wh = *(const uint4*)&g_Wh2T_bf[tid >> 2][jb + (tid & 3) * 8];
            p_mk = g_mask32[i0 + tid][tt0];
        }
    }
    __syncthreads();

    for (int t = 0; t < 128; t++) {
        const int par = t & 1;
        const int jbase = (jh * 128 + t) * 32;

        if (ldb) {
            *(uint4*)&Bs2[par][tid >> 2][(tid & 3) * 8] = p_wh;
            mk2[par][tid] = p_mk;
        }
        if (t + 1 < 128) {
            const int ttn = jh * 128 + t + 1, jbn = ttn * 32;
            if (ldb) {
                p_wh = *(const uint4*)&g_Wh2T_bf[tid >> 2][jbn + (tid & 3) * 8];
                p_mk = g_mask32[i0 + tid][ttn];
            }
        }
        __syncthreads();

        const uint32_t mw0 = mk2[par][R0], mw1 = mk2[par][R1];
        const int jb2 = jbase + shlo;
        const uint32_t tb0 = *(const uint32_t*)&g_B2bf[jb2];
        const uint32_t tb1 = *(const uint32_t*)&g_B2bf[jb2 + 8];
        const uint32_t t50 = *(const uint32_t*)&g_B52bf[jb2];
        const uint32_t t51 = *(const uint32_t*)&g_B52bf[jb2 + 8];

        uint32_t a0, a1, a2, a3;
        a0 = bfmax(bfmul(fA[0], tb0), bfmul(fK[0], t50)) & mexp(mw0, shlo);
        a1 = bfmax(bfmul(fA[1], tb0), bfmul(fK[1], t50)) & mexp(mw1, shlo);
        a2 = bfmax(bfmul(fA[0], tb1), bfmul(fK[0], t51)) & mexp(mw0, shhi);
        a3 = bfmax(bfmul(fA[1], tb1), bfmul(fK[1], t51)) & mexp(mw1, shhi);

#pragma unroll
        for (int cb = 0; cb < 3; cb++) {
            const uint32_t b0 = *(const uint32_t*)&Bs2[par][cb * 8 + la][shlo];
            const uint32_t b1 = *(const uint32_t*)&Bs2[par][cb * 8 + la][shhi];
            mma16(acc[cb], a0, a1, a2, a3, b0, b1);
        }
    }

    const int pi = jh * 2 + ks;
    const int rlo = i0 + R0, rhi = i0 + R1;
#pragma unroll
    for (int cb = 0; cb < 2; cb++) {
        *(float2*)&g_p2[pi][rlo][cb * 8 + 2 * lb] = make_float2(acc[cb][0], acc[cb][1]);
        *(float2*)&g_p2[pi][rhi][cb * 8 + 2 * lb] = make_float2(acc[cb][2], acc[cb][3]);
    }
    if (lb == 0) {
        g_p2[pi][rlo][16] = acc[2][0];
        g_p2[pi][rhi][16] = acc[2][2];
    }
}

// ---------------- K10: combine + elu + log_softmax ----------------
__global__ void k_fin2(float* __restrict__ out) {
    const int tid = threadIdx.x;
    const int row = blockIdx.x * 64 + (tid >> 2);
    const int qq = tid & 3;
    float Z = 0.f;
#pragma unroll
    for (int pi = 0; pi < 4; pi++) Z += g_p2[pi][row][16];
    const float inv = 1.0f / Z;
    float v[4] = {0.f, 0.f, 0.f, 0.f};
#pragma unroll
    for (int pi = 0; pi < 4; pi++) {
        float4 a = *(const float4*)&g_p2[pi][row][qq * 4];
        v[0] += a.x; v[1] += a.y; v[2] += a.z; v[3] += a.w;
    }
    float mx = -3.0e38f;
#pragma unroll
    for (int i = 0; i < 4; i++) {
        v[i] *= inv;
        v[i] = (v[i] > 0.f) ? v[i] : expm1f(v[i]);
        mx = fmaxf(mx, v[i]);
    }
    mx = fmaxf(mx, __shfl_xor_sync(0xffffffffu, mx, 1));
    mx = fmaxf(mx, __shfl_xor_sync(0xffffffffu, mx, 2));
    float s = 0.f;
#pragma unroll
    for (int i = 0; i < 4; i++) s += expf(v[i] - mx);
    s += __shfl_xor_sync(0xffffffffu, s, 1);
    s += __shfl_xor_sync(0xffffffffu, s, 2);
    const float lse = mx + logf(s);
    *(float4*)&out[(size_t)row * 16 + qq * 4] =
        make_float4(v[0] - lse, v[1] - lse, v[2] - lse, v[3] - lse);
}

// ---------------- launch ----------------
extern "C" void kernel_launch(void* const* d_in, const int* in_sizes, int n_in,
                              void* d_out, int out_size) {
    const float* x       = (const float*)d_in[0];
    const int*   adj     = (const int*)  d_in[1];
    const float* W_heads = (const float*)d_in[2];
    const float* a_heads = (const float*)d_in[3];
    const float* W_out   = (const float*)d_in[4];
    const float* a_out   = (const float*)d_in[5];
    float* out = (float*)d_out;

    k_pack<<<65536, 256>>>(adj);
    k_gemm1<<<dim3(N8 / 64, 2), 256>>>(x, W_heads);
    k_uv1<<<dim3(N8 / 8, 2), 256>>>(a_heads);
    k_max<<<4, 1024>>>(0);
    k_exp1<<<dim3(N8 / 256, 2), 256>>>();
    k_attn1<<<dim3(N8 / 64, 2), 256>>>();
    k_gemm2<<<N8 / 16, 256>>>(W_out);
    k_uv2<<<N8 / 8, 256>>>(a_out);
    k_max<<<2, 1024>>>(4);
    k_exp2<<<N8 / 256, 256>>>();
    k_attn2<<<dim3(N8 / 64, 2), 256>>>();
    k_fin2<<<N8 / 64, 256>>>(out);
}

// round 14
// speedup vs baseline: 5.0455x; 1.1269x over previous
#include <cuda_runtime.h>
#include <cuda_bf16.h>
#include <math.h>
#include <stdint.h>

#define N8   8192
#define FIN  64
#define HID  64

// ---------------- device scratch ----------------
__device__ float g_Wh[2][N8][HID];
__device__ __align__(16) __nv_bfloat16 g_WhT_bf[2][HID][N8];
__device__ float g_u[2][N8], g_v[2][N8];
__device__ float g_A[2][N8], g_A5K[2][N8];
__device__ __align__(16) __nv_bfloat16 g_Bbf[2][N8];
__device__ __align__(16) __nv_bfloat16 g_B5bf[2][N8];
__device__ __align__(16) float g_p1[4][2][N8][72];   // [jh*2+ks][h][row][0..63 acc, 64 Z]
__device__ float g_Wh2[N8][16];
__device__ __align__(16) __nv_bfloat16 g_Wh2T_bf[16][N8];
__device__ float g_u2[N8], g_v2[N8];
__device__ float g_A2[N8], g_A5K2[N8];
__device__ __align__(16) __nv_bfloat16 g_B2bf[N8];
__device__ __align__(16) __nv_bfloat16 g_B52bf[N8];
__device__ __align__(16) float g_p2[4][N8][20];      // [jh*2+ks][row][0..15 acc, 16 Z]
__device__ __align__(16) uint32_t g_mask32[N8][256];
__device__ float g_max[8];

// ---------------- helpers ----------------
__device__ __forceinline__ uint32_t pack_bf(float hi, float lo) {
    uint32_t d; asm("cvt.rn.bf16x2.f32 %0, %1, %2;" : "=r"(d) : "f"(hi), "f"(lo));
    return d;
}
__device__ __forceinline__ uint32_t bfmul(uint32_t a, uint32_t b) {
    uint32_t d; asm("mul.rn.bf16x2 %0, %1, %2;" : "=r"(d) : "r"(a), "r"(b)); return d;
}
__device__ __forceinline__ uint32_t bfmax(uint32_t a, uint32_t b) {
    uint32_t d; asm("max.bf16x2 %0, %1, %2;" : "=r"(d) : "r"(a), "r"(b)); return d;
}
__device__ __forceinline__ uint32_t mexp(uint32_t mw, int sh) {
    uint32_t b = mw >> sh;
    return ((b & 1u) ? 0x0000FFFFu : 0u) | ((b & 2u) ? 0xFFFF0000u : 0u);
}
__device__ __forceinline__ void mma16(float* d, uint32_t a0, uint32_t a1, uint32_t a2,
                                      uint32_t a3, uint32_t b0, uint32_t b1) {
    asm volatile("mma.sync.aligned.m16n8k16.row.col.f32.bf16.bf16.f32 "
                 "{%0,%1,%2,%3}, {%4,%5,%6,%7}, {%8,%9}, {%0,%1,%2,%3};"
                 : "+f"(d[0]), "+f"(d[1]), "+f"(d[2]), "+f"(d[3])
                 : "r"(a0), "r"(a1), "r"(a2), "r"(a3), "r"(b0), "r"(b1));
}
__device__ __forceinline__ int4 ldcs4(const int* p) {
    int4 v;
    asm volatile("ld.global.cs.v4.s32 {%0,%1,%2,%3}, [%4];"
                 : "=r"(v.x), "=r"(v.y), "=r"(v.z), "=r"(v.w) : "l"(p));
    return v;
}

// ---------------- K0: pack adj -> bitmask ----------------
__global__ void k_pack(const int* __restrict__ adj) {
    const size_t g = (size_t)blockIdx.x * 256 + threadIdx.x;
    const int lane = threadIdx.x & 31;
    int4 a = ldcs4(adj + g * 4);
    unsigned nib = (unsigned)(a.x != 0) | ((unsigned)(a.y != 0) << 1) |
                   ((unsigned)(a.z != 0) << 2) | ((unsigned)(a.w != 0) << 3);
    unsigned w = nib << ((lane & 7) * 4);
    w |= __shfl_xor_sync(0xffffffffu, w, 1);
    w |= __shfl_xor_sync(0xffffffffu, w, 2);
    w |= __shfl_xor_sync(0xffffffffu, w, 4);
    if ((lane & 7) == 0) ((uint32_t*)g_mask32)[g >> 3] = w;
}

// ---------------- K1: Wh = x @ W_h (+ bf16 T copy + fused u/v) ----------------
__global__ void k_gemm1(const float* __restrict__ x, const float* __restrict__ W_heads,
                        const float* __restrict__ a_heads) {
    __shared__ float xs[64][FIN];
    __shared__ float ws[FIN][HID];
    const int h = blockIdx.y, i0 = blockIdx.x * 64, tid = threadIdx.x;
    const float4* xg = (const float4*)(x + (size_t)i0 * FIN);
    const float4* wg = (const float4*)(W_heads + (size_t)h * FIN * HID);
#pragma unroll
    for (int it = 0; it < 4; it++) ((float4*)xs)[tid + it * 256] = xg[tid + it * 256];
#pragma unroll
    for (int it = 0; it < 4; it++) ((float4*)ws)[tid + it * 256] = wg[tid + it * 256];
    __syncthreads();
    const int f = (tid & 15) * 4, ig = tid >> 4;
    float acc[4][4] = {};
#pragma unroll 4
    for (int k = 0; k < FIN; k++) {
        float4 wv = *(const float4*)&ws[k][f];
#pragma unroll
        for (int r = 0; r < 4; r++) {
            float xv = xs[ig * 4 + r][k];
            acc[r][0] = fmaf(xv, wv.x, acc[r][0]);
            acc[r][1] = fmaf(xv, wv.y, acc[r][1]);
            acc[r][2] = fmaf(xv, wv.z, acc[r][2]);
            acc[r][3] = fmaf(xv, wv.w, acc[r][3]);
        }
    }
#pragma unroll
    for (int r = 0; r < 4; r++) {
        const int row = i0 + ig * 4 + r;
        *(float4*)&g_Wh[h][row][f] = make_float4(acc[r][0], acc[r][1], acc[r][2], acc[r][3]);
#pragma unroll
        for (int c = 0; c < 4; c++) g_WhT_bf[h][f + c][row] = __float2bfloat16(acc[r][c]);
    }
    // fused u/v: reduce over the 16 threads sharing rows ig*4..ig*4+3
    const float* a = a_heads + (size_t)h * 2 * HID;
    const float4 au = *(const float4*)&a[f];
    const float4 av = *(const float4*)&a[HID + f];
    float pu[4], pv[4];
#pragma unroll
    for (int r = 0; r < 4; r++) {
        pu[r] = acc[r][0] * au.x + acc[r][1] * au.y + acc[r][2] * au.z + acc[r][3] * au.w;
        pv[r] = acc[r][0] * av.x + acc[r][1] * av.y + acc[r][2] * av.z + acc[r][3] * av.w;
    }
#pragma unroll
    for (int o = 8; o; o >>= 1)
#pragma unroll
        for (int r = 0; r < 4; r++) {
            pu[r] += __shfl_xor_sync(0xffffffffu, pu[r], o);
            pv[r] += __shfl_xor_sync(0xffffffffu, pv[r], o);
        }
    if ((tid & 15) == 0)
#pragma unroll
        for (int r = 0; r < 4; r++) {
            g_u[h][i0 + ig * 4 + r] = pu[r];
            g_v[h][i0 + ig * 4 + r] = pv[r];
        }
}

// ---------------- K3: global max ----------------
__global__ void k_max(int base) {
    const int which = base + blockIdx.x;
    const float* src = (which == 0) ? g_u[0] : (which == 1) ? g_v[0] :
                       (which == 2) ? g_u[1] : (which == 3) ? g_v[1] :
                       (which == 4) ? g_u2 : g_v2;
    __shared__ float red[32];
    float m = -3.0e38f;
    for (int i = threadIdx.x; i < N8; i += blockDim.x) m = fmaxf(m, src[i]);
#pragma unroll
    for (int o = 16; o; o >>= 1) m = fmaxf(m, __shfl_xor_sync(0xffffffffu, m, o));
    if ((threadIdx.x & 31) == 0) red[threadIdx.x >> 5] = m;
    __syncthreads();
    if (threadIdx.x < 32) {
        float mm = red[threadIdx.x];
#pragma unroll
        for (int o = 16; o; o >>= 1) mm = fmaxf(mm, __shfl_xor_sync(0xffffffffu, mm, o));
        if (threadIdx.x == 0) g_max[which] = mm;
    }
}

// ---------------- K4: exp tables ----------------
__global__ void k_exp1() {
    const int i = blockIdx.x * 256 + threadIdx.x, h = blockIdx.y;
    const float um = g_max[h * 2], vm = g_max[h * 2 + 1], c = um + vm;
    const float u = g_u[h][i], v = g_v[h][i];
    g_A[h][i]    = expf(u - um);
    g_A5K[h][i]  = expf(0.2f * (u - um) - 0.8f * c);
    g_Bbf[h][i]  = __float2bfloat16(expf(v - vm));
    g_B5bf[h][i] = __float2bfloat16(expf(0.2f * (v - vm)));
}
__global__ void k_exp2() {
    const int i = blockIdx.x * 256 + threadIdx.x;
    const float um = g_max[4], vm = g_max[5], c = um + vm;
    const float u = g_u2[i], v = g_v2[i];
    g_A2[i]    = expf(u - um);
    g_A5K2[i]  = expf(0.2f * (u - um) - 0.8f * c);
    g_B2bf[i]  = __float2bfloat16(expf(v - vm));
    g_B52bf[i] = __float2bfloat16(expf(0.2f * (v - vm)));
}

// ---------------- K5: layer-1 attention, Kt=64, fused w-gen + mma ----------------
// 8 warps: h = warp>>2, p = (warp>>1)&1 (row half), ks = warp&1 (k half).
__global__ __launch_bounds__(256, 2) void k_attn1() {
    __shared__ __align__(16) unsigned short Bs[2][2][72][72];  // [buf][h][feat][k], 64=ones
    __shared__ uint32_t mk[2][64][2];

    const int tid = threadIdx.x, lane = tid & 31, warp = tid >> 5;
    const int i0 = blockIdx.x * 64;
    const int jh = blockIdx.y;
    const int h = warp >> 2, p = (warp >> 1) & 1, ks = warp & 1;
    const int la = lane >> 2, lb = lane & 3;

    const int R0 = 32 * p + la, R1 = R0 + 8, R2 = R0 + 16, R3 = R0 + 24;
    uint32_t fA[4], fK[4];
    {
        float a0 = g_A[h][i0 + R0], a1 = g_A[h][i0 + R1];
        float a2 = g_A[h][i0 + R2], a3 = g_A[h][i0 + R3];
        float k0 = g_A5K[h][i0 + R0], k1 = g_A5K[h][i0 + R1];
        float k2 = g_A5K[h][i0 + R2], k3 = g_A5K[h][i0 + R3];
        fA[0] = pack_bf(a0, a0); fA[1] = pack_bf(a1, a1);
        fA[2] = pack_bf(a2, a2); fA[3] = pack_bf(a3, a3);
        fK[0] = pack_bf(k0, k0); fK[1] = pack_bf(k1, k1);
        fK[2] = pack_bf(k2, k2); fK[3] = pack_bf(k3, k3);
    }

    // ones / zero rows (64..71), both buffers & heads; 36 words per 72-short row
    for (int i = tid; i < 2 * 2 * 8 * 36; i += 256) {
        int b = i / 576, rem = i % 576, hh = rem / 288, rr = (rem % 288) / 36, wi = i % 36;
        ((uint32_t*)&Bs[b][hh][64 + rr][0])[wi] = (rr == 0) ? 0x3F803F80u : 0u;
    }

    float acc[2][9][4] = {};

    uint4 p_wh[4];
    uint32_t p_mk;

    {
        const int jb = jh * 4096;
#pragma unroll
        for (int it = 0; it < 4; it++) {
            int g = tid + it * 256;
            int hh = g >> 9, rem = g & 511, ff = rem >> 3, cc = rem & 7;
            p_wh[it] = *(const uint4*)&g_WhT_bf[hh][ff][jb + cc * 8];
        }
        if (tid < 128) p_mk = g_mask32[i0 + (tid >> 1)][jh * 128 + (tid & 1)];
    }
    __syncthreads();

    for (int t = 0; t < 64; t++) {
        const int par = t & 1;
        const int jbase = (jh * 64 + t) * 64;

#pragma unroll
        for (int it = 0; it < 4; it++) {
            int g = tid + it * 256;
            int hh = g >> 9, rem = g & 511, ff = rem >> 3, cc = rem & 7;
            *(uint4*)&Bs[par][hh][ff][cc * 8] = p_wh[it];
        }
        if (tid < 128) mk[par][tid >> 1][tid & 1] = p_mk;

        if (t + 1 < 64) {
            const int jbn = (jh * 64 + t + 1) * 64;
#pragma unroll
            for (int it = 0; it < 4; it++) {
                int g = tid + it * 256;
                int hh = g >> 9, rem = g & 511, ff = rem >> 3, cc = rem & 7;
                p_wh[it] = *(const uint4*)&g_WhT_bf[hh][ff][jbn + cc * 8];
            }
            if (tid < 128)
                p_mk = g_mask32[i0 + (tid >> 1)][(jh * 64 + t + 1) * 2 + (tid & 1)];
        }
        __syncthreads();

        const uint32_t mw0 = mk[par][R0][ks], mw1 = mk[par][R1][ks];
        const uint32_t mw2 = mk[par][R2][ks], mw3 = mk[par][R3][ks];

#pragma unroll
        for (int kk = 0; kk < 2; kk++) {
            const int base = ks * 32 + kk * 16;
            const int shlo = base + 2 * lb, shhi = shlo + 8;
            const int blo = kk * 16 + 2 * lb, bhi = blo + 8;
            const int jb2 = jbase + shlo;
            const uint32_t tb0 = *(const uint32_t*)&g_Bbf[h][jb2];
            const uint32_t tb1 = *(const uint32_t*)&g_Bbf[h][jb2 + 8];
            const uint32_t t50 = *(const uint32_t*)&g_B5bf[h][jb2];
            const uint32_t t51 = *(const uint32_t*)&g_B5bf[h][jb2 + 8];

            uint32_t a0[4], a1[4];
            a0[0] = bfmax(bfmul(fA[0], tb0), bfmul(fK[0], t50)) & mexp(mw0, blo);
            a0[1] = bfmax(bfmul(fA[1], tb0), bfmul(fK[1], t50)) & mexp(mw1, blo);
            a0[2] = bfmax(bfmul(fA[0], tb1), bfmul(fK[0], t51)) & mexp(mw0, bhi);
            a0[3] = bfmax(bfmul(fA[1], tb1), bfmul(fK[1], t51)) & mexp(mw1, bhi);
            a1[0] = bfmax(bfmul(fA[2], tb0), bfmul(fK[2], t50)) & mexp(mw2, blo);
            a1[1] = bfmax(bfmul(fA[3], tb0), bfmul(fK[3], t50)) & mexp(mw3, blo);
            a1[2] = bfmax(bfmul(fA[2], tb1), bfmul(fK[2], t51)) & mexp(mw2, bhi);
            a1[3] = bfmax(bfmul(fA[3], tb1), bfmul(fK[3], t51)) & mexp(mw3, bhi);

#pragma unroll
            for (int cb = 0; cb < 9; cb++) {
                const uint32_t b0 = *(const uint32_t*)&Bs[par][h][cb * 8 + la][shlo];
                const uint32_t b1 = *(const uint32_t*)&Bs[par][h][cb * 8 + la][shhi];
                mma16(acc[0][cb], a0[0], a0[1], a0[2], a0[3], b0, b1);
                mma16(acc[1][cb], a1[0], a1[1], a1[2], a1[3], b0, b1);
            }
        }
    }

    const int pi = jh * 2 + ks;
#pragma unroll
    for (int mb = 0; mb < 2; mb++) {
        const int rlo = i0 + 32 * p + mb * 16 + la, rhi = rlo + 8;
#pragma unroll
        for (int cb = 0; cb < 8; cb++) {
            *(float2*)&g_p1[pi][h][rlo][cb * 8 + 2 * lb] =
                make_float2(acc[mb][cb][0], acc[mb][cb][1]);
            *(float2*)&g_p1[pi][h][rhi][cb * 8 + 2 * lb] =
                make_float2(acc[mb][cb][2], acc[mb][cb][3]);
        }
        if (lb == 0) {
            g_p1[pi][h][rlo][64] = acc[mb][8][0];
            g_p1[pi][h][rhi][64] = acc[mb][8][2];
        }
    }
}

// ---------------- K6: combine layer-1 + Wh2 = h @ W_out + fused u2/v2 ----------------
__global__ void k_gemm2(const float* __restrict__ W_out, const float* __restrict__ a_out) {
    __shared__ float zi[16][2];
    __shared__ float hs[16][128];
    __shared__ float ws[128][16];
    const int tid = threadIdx.x, i0 = blockIdx.x * 16;

    if (tid < 32) {
        const int r = tid >> 1, h = tid & 1;
        float Z = 0.f;
#pragma unroll
        for (int pi = 0; pi < 4; pi++) Z += g_p1[pi][h][i0 + r][64];
        zi[r][h] = 1.0f / Z;
    }
#pragma unroll
    for (int it = 0; it < 2; it++)
        ((float4*)ws)[tid + it * 256] = ((const float4*)W_out)[tid + it * 256];
    __syncthreads();

#pragma unroll
    for (int it = 0; it < 2; it++) {
        int idx = tid + it * 256;
        int r = idx >> 5, c4 = (idx & 31) * 4;
        int h = c4 >> 6, f = c4 & 63;
        float4 s = make_float4(0.f, 0.f, 0.f, 0.f);
#pragma unroll
        for (int pi = 0; pi < 4; pi++) {
            float4 v = *(const float4*)&g_p1[pi][h][i0 + r][f];
            s.x += v.x; s.y += v.y; s.z += v.z; s.w += v.w;
        }
        const float iv = zi[r][h];
        *(float4*)&hs[r][c4] = make_float4(s.x * iv, s.y * iv, s.z * iv, s.w * iv);
    }
    __syncthreads();

    const int r = tid >> 4, f = tid & 15;
    float acc = 0.f;
#pragma unroll 8
    for (int k = 0; k < 128; k++) acc = fmaf(hs[r][k], ws[k][f], acc);
    g_Wh2[i0 + r][f] = acc;
    g_Wh2T_bf[f][i0 + r] = __float2bfloat16(acc);

    float pu = acc * a_out[f];
    float pv = acc * a_out[16 + f];
#pragma unroll
    for (int o = 8; o; o >>= 1) {
        pu += __shfl_xor_sync(0xffffffffu, pu, o);
        pv += __shfl_xor_sync(0xffffffffu, pv, o);
    }
    if ((tid & 15) == 0) { g_u2[i0 + r] = pu; g_v2[i0 + r] = pv; }
}

// ---------------- K9: output attention, Kt=64, fused w-gen + mma ----------------
// 8 warps: mb = warp>>1 (0..3), ks = warp&1.
__global__ __launch_bounds__(256, 2) void k_attn2() {
    __shared__ __align__(16) unsigned short Bs2[2][24][72];  // row 16 = ones
    __shared__ uint32_t mk2[2][64][2];

    const int tid = threadIdx.x, lane = tid & 31, warp = tid >> 5;
    const int i0 = blockIdx.x * 64;
    const int jh = blockIdx.y;
    const int mb = warp >> 1, ks = warp & 1;
    const int la = lane >> 2, lb = lane & 3;

    const int R0 = mb * 16 + la, R1 = R0 + 8;
    uint32_t fA[2], fK[2];
    {
        float a0 = g_A2[i0 + R0], a1 = g_A2[i0 + R1];
        float k0 = g_A5K2[i0 + R0], k1 = g_A5K2[i0 + R1];
        fA[0] = pack_bf(a0, a0); fA[1] = pack_bf(a1, a1);
        fK[0] = pack_bf(k0, k0); fK[1] = pack_bf(k1, k1);
    }
    for (int i = tid; i < 2 * 8 * 36; i += 256) {
        int b = i / 288, rr = (i % 288) / 36, wi = i % 36;
        ((uint32_t*)&Bs2[b][16 + rr][0])[wi] = (rr == 0) ? 0x3F803F80u : 0u;
    }

    float acc[3][4] = {};

    uint4 p_wh;
    uint32_t p_mk;

    {
        const int jb = jh * 4096;
        if (tid < 128) {
            p_wh = *(const uint4*)&g_Wh2T_bf[tid >> 3][jb + (tid & 7) * 8];
            p_mk = g_mask32[i0 + (tid >> 1)][jh * 128 + (tid & 1)];
        }
    }
    __syncthreads();

    for (int t = 0; t < 64; t++) {
        const int par = t & 1;
        const int jbase = (jh * 64 + t) * 64;

        if (tid < 128) {
            *(uint4*)&Bs2[par][tid >> 3][(tid & 7) * 8] = p_wh;
            mk2[par][tid >> 1][tid & 1] = p_mk;
        }
        if (t + 1 < 64) {
            const int jbn = (jh * 64 + t + 1) * 64;
            if (tid < 128) {
                p_wh = *(const uint4*)&g_Wh2T_bf[tid >> 3][jbn + (tid & 7) * 8];
                p_mk = g_mask32[i0 + (tid >> 1)][(jh * 64 + t + 1) * 2 + (tid & 1)];
            }
        }
        __syncthreads();

        const uint32_t mw0 = mk2[par][R0][ks], mw1 = mk2[par][R1][ks];

#pragma unroll
        for (int kk = 0; kk < 2; kk++) {
            const int base = ks * 32 + kk * 16;
            const int shlo = base + 2 * lb, shhi = shlo + 8;
            const int blo = kk * 16 + 2 * lb, bhi = blo + 8;
            const int jb2 = jbase + shlo;
            const uint32_t tb0 = *(const uint32_t*)&g_B2bf[jb2];
            const uint32_t tb1 = *(const uint32_t*)&g_B2bf[jb2 + 8];
            const uint32_t t50 = *(const uint32_t*)&g_B52bf[jb2];
            const uint32_t t51 = *(const uint32_t*)&g_B52bf[jb2 + 8];

            uint32_t a0, a1, a2, a3;
            a0 = bfmax(bfmul(fA[0], tb0), bfmul(fK[0], t50)) & mexp(mw0, blo);
            a1 = bfmax(bfmul(fA[1], tb0), bfmul(fK[1], t50)) & mexp(mw1, blo);
            a2 = bfmax(bfmul(fA[0], tb1), bfmul(fK[0], t51)) & mexp(mw0, bhi);
            a3 = bfmax(bfmul(fA[1], tb1), bfmul(fK[1], t51)) & mexp(mw1, bhi);

#pragma unroll
            for (int cb = 0; cb < 3; cb++) {
                const uint32_t b0 = *(const uint32_t*)&Bs2[par][cb * 8 + la][shlo];
                const uint32_t b1 = *(const uint32_t*)&Bs2[par][cb * 8 + la][shhi];
                mma16(acc[cb], a0, a1, a2, a3, b0, b1);
            }
        }
    }

    const int pi = jh * 2 + ks;
    const int rlo = i0 + R0, rhi = i0 + R1;
#pragma unroll
    for (int cb = 0; cb < 2; cb++) {
        *(float2*)&g_p2[pi][rlo][cb * 8 + 2 * lb] = make_float2(acc[cb][0], acc[cb][1]);
        *(float2*)&g_p2[pi][rhi][cb * 8 + 2 * lb] = make_float2(acc[cb][2], acc[cb][3]);
    }
    if (lb == 0) {
        g_p2[pi][rlo][16] = acc[2][0];
        g_p2[pi][rhi][16] = acc[2][2];
    }
}

// ---------------- K10: combine + elu + log_softmax ----------------
__global__ void k_fin2(float* __restrict__ out) {
    const int tid = threadIdx.x;
    const int row = blockIdx.x * 64 + (tid >> 2);
    const int qq = tid & 3;
    float Z = 0.f;
#pragma unroll
    for (int pi = 0; pi < 4; pi++) Z += g_p2[pi][row][16];
    const float inv = 1.0f / Z;
    float v[4] = {0.f, 0.f, 0.f, 0.f};
#pragma unroll
    for (int pi = 0; pi < 4; pi++) {
        float4 a = *(const float4*)&g_p2[pi][row][qq * 4];
        v[0] += a.x; v[1] += a.y; v[2] += a.z; v[3] += a.w;
    }
    float mx = -3.0e38f;
#pragma unroll
    for (int i = 0; i < 4; i++) {
        v[i] *= inv;
        v[i] = (v[i] > 0.f) ? v[i] : expm1f(v[i]);
        mx = fmaxf(mx, v[i]);
    }
    mx = fmaxf(mx, __shfl_xor_sync(0xffffffffu, mx, 1));
    mx = fmaxf(mx, __shfl_xor_sync(0xffffffffu, mx, 2));
    float s = 0.f;
#pragma unroll
    for (int i = 0; i < 4; i++) s += expf(v[i] - mx);
    s += __shfl_xor_sync(0xffffffffu, s, 1);
    s += __shfl_xor_sync(0xffffffffu, s, 2);
    const float lse = mx + logf(s);
    *(float4*)&out[(size_t)row * 16 + qq * 4] =
        make_float4(v[0] - lse, v[1] - lse, v[2] - lse, v[3] - lse);
}

// ---------------- launch ----------------
extern "C" void kernel_launch(void* const* d_in, const int* in_sizes, int n_in,
                              void* d_out, int out_size) {
    const float* x       = (const float*)d_in[0];
    const int*   adj     = (const int*)  d_in[1];
    const float* W_heads = (const float*)d_in[2];
    const float* a_heads = (const float*)d_in[3];
    const float* W_out   = (const float*)d_in[4];
    const float* a_out   = (const float*)d_in[5];
    float* out = (float*)d_out;

    k_pack<<<65536, 256>>>(adj);                          // 1
    k_gemm1<<<dim3(N8 / 64, 2), 256>>>(x, W_heads, a_heads); // 2 (uv fused)
    k_max<<<4, 1024>>>(0);                                // 3
    k_exp1<<<dim3(N8 / 256, 2), 256>>>();                 // 4
    k_attn1<<<dim3(N8 / 64, 2), 256>>>();                 // 5  <- ncu profiles this
    k_gemm2<<<N8 / 16, 256>>>(W_out, a_out);              // 6 (uv2 fused)
    k_max<<<2, 1024>>>(4);                                // 7
    k_exp2<<<N8 / 256, 256>>>();                          // 8
    k_attn2<<<dim3(N8 / 64, 2), 256>>>();                 // 9
    k_fin2<<<N8 / 64, 256>>>(out);                        // 10
}

// round 15
// speedup vs baseline: 5.2756x; 1.0456x over previous
#include <cuda_runtime.h>
#include <cuda_bf16.h>
#include <math.h>
#include <stdint.h>

#define N8   8192
#define FIN  64
#define HID  64

// ---------------- device scratch ----------------
__device__ float g_Wh[2][N8][HID];
__device__ __align__(16) __nv_bfloat16 g_WhT_bf[2][HID][N8];
__device__ float g_u[2][N8], g_v[2][N8];
__device__ float g_A[2][N8], g_A5K[2][N8];
__device__ __align__(16) __nv_bfloat16 g_Bbf[2][N8];
__device__ __align__(16) __nv_bfloat16 g_B5bf[2][N8];
__device__ __align__(16) float g_p1[4][2][N8][72];   // [jh*2+ks][h][row][0..63 acc, 64 Z]
__device__ float g_Wh2[N8][16];
__device__ __align__(16) __nv_bfloat16 g_Wh2T_bf[16][N8];
__device__ float g_u2[N8], g_v2[N8];
__device__ float g_A2[N8], g_A5K2[N8];
__device__ __align__(16) __nv_bfloat16 g_B2bf[N8];
__device__ __align__(16) __nv_bfloat16 g_B52bf[N8];
__device__ __align__(16) float g_p2[4][N8][20];      // [jh*2+ks][row][0..15 acc, 16 Z]
__device__ __align__(16) uint32_t g_mask32[N8][256];
__device__ float g_max[8];

// ---------------- helpers ----------------
__device__ __forceinline__ uint32_t pack_bf(float hi, float lo) {
    uint32_t d; asm("cvt.rn.bf16x2.f32 %0, %1, %2;" : "=r"(d) : "f"(hi), "f"(lo));
    return d;
}
__device__ __forceinline__ uint32_t bfmul(uint32_t a, uint32_t b) {
    uint32_t d; asm("mul.rn.bf16x2 %0, %1, %2;" : "=r"(d) : "r"(a), "r"(b)); return d;
}
__device__ __forceinline__ uint32_t bfmax(uint32_t a, uint32_t b) {
    uint32_t d; asm("max.bf16x2 %0, %1, %2;" : "=r"(d) : "r"(a), "r"(b)); return d;
}
__device__ __forceinline__ uint32_t mexp(uint32_t mw, int sh) {
    uint32_t b = mw >> sh;
    return ((b & 1u) ? 0x0000FFFFu : 0u) | ((b & 2u) ? 0xFFFF0000u : 0u);
}
__device__ __forceinline__ void mma16(float* d, uint32_t a0, uint32_t a1, uint32_t a2,
                                      uint32_t a3, uint32_t b0, uint32_t b1) {
    asm volatile("mma.sync.aligned.m16n8k16.row.col.f32.bf16.bf16.f32 "
                 "{%0,%1,%2,%3}, {%4,%5,%6,%7}, {%8,%9}, {%0,%1,%2,%3};"
                 : "+f"(d[0]), "+f"(d[1]), "+f"(d[2]), "+f"(d[3])
                 : "r"(a0), "r"(a1), "r"(a2), "r"(a3), "r"(b0), "r"(b1));
}
__device__ __forceinline__ int4 ldcs4(const int* p) {
    int4 v;
    asm volatile("ld.global.cs.v4.s32 {%0,%1,%2,%3}, [%4];"
                 : "=r"(v.x), "=r"(v.y), "=r"(v.z), "=r"(v.w) : "l"(p));
    return v;
}
__device__ __forceinline__ void cpa16(const void* smem, const void* g) {
    uint32_t a = (uint32_t)__cvta_generic_to_shared(smem);
    asm volatile("cp.async.cg.shared.global [%0], [%1], 16;" :: "r"(a), "l"(g));
}
__device__ __forceinline__ void cpa4(const void* smem, const void* g) {
    uint32_t a = (uint32_t)__cvta_generic_to_shared(smem);
    asm volatile("cp.async.ca.shared.global [%0], [%1], 4;" :: "r"(a), "l"(g));
}
__device__ __forceinline__ void cpa_commit() { asm volatile("cp.async.commit_group;" ::: "memory"); }
__device__ __forceinline__ void cpa_wait0()  { asm volatile("cp.async.wait_group 0;" ::: "memory"); }

// ---------------- K0: pack adj -> bitmask ----------------
__global__ void k_pack(const int* __restrict__ adj) {
    const size_t g = (size_t)blockIdx.x * 256 + threadIdx.x;
    const int lane = threadIdx.x & 31;
    int4 a = ldcs4(adj + g * 4);
    unsigned nib = (unsigned)(a.x != 0) | ((unsigned)(a.y != 0) << 1) |
                   ((unsigned)(a.z != 0) << 2) | ((unsigned)(a.w != 0) << 3);
    unsigned w = nib << ((lane & 7) * 4);
    w |= __shfl_xor_sync(0xffffffffu, w, 1);
    w |= __shfl_xor_sync(0xffffffffu, w, 2);
    w |= __shfl_xor_sync(0xffffffffu, w, 4);
    if ((lane & 7) == 0) ((uint32_t*)g_mask32)[g >> 3] = w;
}

// ---------------- K1: Wh = x @ W_h (+ bf16 T copy + fused u/v) ----------------
__global__ void k_gemm1(const float* __restrict__ x, const float* __restrict__ W_heads,
                        const float* __restrict__ a_heads) {
    __shared__ float xs[64][FIN];
    __shared__ float ws[FIN][HID];
    const int h = blockIdx.y, i0 = blockIdx.x * 64, tid = threadIdx.x;
    const float4* xg = (const float4*)(x + (size_t)i0 * FIN);
    const float4* wg = (const float4*)(W_heads + (size_t)h * FIN * HID);
#pragma unroll
    for (int it = 0; it < 4; it++) ((float4*)xs)[tid + it * 256] = xg[tid + it * 256];
#pragma unroll
    for (int it = 0; it < 4; it++) ((float4*)ws)[tid + it * 256] = wg[tid + it * 256];
    __syncthreads();
    const int f = (tid & 15) * 4, ig = tid >> 4;
    float acc[4][4] = {};
#pragma unroll 4
    for (int k = 0; k < FIN; k++) {
        float4 wv = *(const float4*)&ws[k][f];
#pragma unroll
        for (int r = 0; r < 4; r++) {
            float xv = xs[ig * 4 + r][k];
            acc[r][0] = fmaf(xv, wv.x, acc[r][0]);
            acc[r][1] = fmaf(xv, wv.y, acc[r][1]);
            acc[r][2] = fmaf(xv, wv.z, acc[r][2]);
            acc[r][3] = fmaf(xv, wv.w, acc[r][3]);
        }
    }
#pragma unroll
    for (int r = 0; r < 4; r++) {
        const int row = i0 + ig * 4 + r;
        *(float4*)&g_Wh[h][row][f] = make_float4(acc[r][0], acc[r][1], acc[r][2], acc[r][3]);
#pragma unroll
        for (int c = 0; c < 4; c++) g_WhT_bf[h][f + c][row] = __float2bfloat16(acc[r][c]);
    }
    const float* a = a_heads + (size_t)h * 2 * HID;
    const float4 au = *(const float4*)&a[f];
    const float4 av = *(const float4*)&a[HID + f];
    float pu[4], pv[4];
#pragma unroll
    for (int r = 0; r < 4; r++) {
        pu[r] = acc[r][0] * au.x + acc[r][1] * au.y + acc[r][2] * au.z + acc[r][3] * au.w;
        pv[r] = acc[r][0] * av.x + acc[r][1] * av.y + acc[r][2] * av.z + acc[r][3] * av.w;
    }
#pragma unroll
    for (int o = 8; o; o >>= 1)
#pragma unroll
        for (int r = 0; r < 4; r++) {
            pu[r] += __shfl_xor_sync(0xffffffffu, pu[r], o);
            pv[r] += __shfl_xor_sync(0xffffffffu, pv[r], o);
        }
    if ((tid & 15) == 0)
#pragma unroll
        for (int r = 0; r < 4; r++) {
            g_u[h][i0 + ig * 4 + r] = pu[r];
            g_v[h][i0 + ig * 4 + r] = pv[r];
        }
}

// ---------------- K3: global max ----------------
__global__ void k_max(int base) {
    const int which = base + blockIdx.x;
    const float* src = (which == 0) ? g_u[0] : (which == 1) ? g_v[0] :
                       (which == 2) ? g_u[1] : (which == 3) ? g_v[1] :
                       (which == 4) ? g_u2 : g_v2;
    __shared__ float red[32];
    float m = -3.0e38f;
    for (int i = threadIdx.x; i < N8; i += blockDim.x) m = fmaxf(m, src[i]);
#pragma unroll
    for (int o = 16; o; o >>= 1) m = fmaxf(m, __shfl_xor_sync(0xffffffffu, m, o));
    if ((threadIdx.x & 31) == 0) red[threadIdx.x >> 5] = m;
    __syncthreads();
    if (threadIdx.x < 32) {
        float mm = red[threadIdx.x];
#pragma unroll
        for (int o = 16; o; o >>= 1) mm = fmaxf(mm, __shfl_xor_sync(0xffffffffu, mm, o));
        if (threadIdx.x == 0) g_max[which] = mm;
    }
}

// ---------------- K4: exp tables ----------------
__global__ void k_exp1() {
    const int i = blockIdx.x * 256 + threadIdx.x, h = blockIdx.y;
    const float um = g_max[h * 2], vm = g_max[h * 2 + 1], c = um + vm;
    const float u = g_u[h][i], v = g_v[h][i];
    g_A[h][i]    = expf(u - um);
    g_A5K[h][i]  = expf(0.2f * (u - um) - 0.8f * c);
    g_Bbf[h][i]  = __float2bfloat16(expf(v - vm));
    g_B5bf[h][i] = __float2bfloat16(expf(0.2f * (v - vm)));
}
__global__ void k_exp2() {
    const int i = blockIdx.x * 256 + threadIdx.x;
    const float um = g_max[4], vm = g_max[5], c = um + vm;
    const float u = g_u2[i], v = g_v2[i];
    g_A2[i]    = expf(u - um);
    g_A5K2[i]  = expf(0.2f * (u - um) - 0.8f * c);
    g_B2bf[i]  = __float2bfloat16(expf(v - vm));
    g_B52bf[i] = __float2bfloat16(expf(0.2f * (v - vm)));
}

// ---------------- K5: layer-1 attention, Kt=64, cp.async staging ----------------
// 8 warps: h = warp>>2, p = (warp>>1)&1 (row half), ks = warp&1 (k half).
__global__ __launch_bounds__(256, 2) void k_attn1() {
    __shared__ __align__(16) unsigned short Bs[2][2][72][72];  // [buf][h][feat][k], 64=ones
    __shared__ uint32_t mk[2][64][2];

    const int tid = threadIdx.x, lane = tid & 31, warp = tid >> 5;
    const int i0 = blockIdx.x * 64;
    const int jh = blockIdx.y;
    const int h = warp >> 2, p = (warp >> 1) & 1, ks = warp & 1;
    const int la = lane >> 2, lb = lane & 3;

    const int R0 = 32 * p + la, R1 = R0 + 8, R2 = R0 + 16, R3 = R0 + 24;
    uint32_t fA[4], fK[4];
    {
        float a0 = g_A[h][i0 + R0], a1 = g_A[h][i0 + R1];
        float a2 = g_A[h][i0 + R2], a3 = g_A[h][i0 + R3];
        float k0 = g_A5K[h][i0 + R0], k1 = g_A5K[h][i0 + R1];
        float k2 = g_A5K[h][i0 + R2], k3 = g_A5K[h][i0 + R3];
        fA[0] = pack_bf(a0, a0); fA[1] = pack_bf(a1, a1);
        fA[2] = pack_bf(a2, a2); fA[3] = pack_bf(a3, a3);
        fK[0] = pack_bf(k0, k0); fK[1] = pack_bf(k1, k1);
        fK[2] = pack_bf(k2, k2); fK[3] = pack_bf(k3, k3);
    }

    // ones / zero rows (64..71)
    for (int i = tid; i < 2 * 2 * 8 * 36; i += 256) {
        int b = i / 576, rem = i % 576, hh = rem / 288, rr = (rem % 288) / 36, wi = i % 36;
        ((uint32_t*)&Bs[b][hh][64 + rr][0])[wi] = (rr == 0) ? 0x3F803F80u : 0u;
    }

    float acc[2][9][4] = {};

    // stage tile -> buf via cp.async
    {
        const int jb = jh * 4096;
#pragma unroll
        for (int it = 0; it < 4; it++) {
            int g = tid + it * 256;
            int hh = g >> 9, rem = g & 511, ff = rem >> 3, cc = rem & 7;
            cpa16(&Bs[0][hh][ff][cc * 8], &g_WhT_bf[hh][ff][jb + cc * 8]);
        }
        if (tid < 128)
            cpa4(&mk[0][tid >> 1][tid & 1], &g_mask32[i0 + (tid >> 1)][jh * 128 + (tid & 1)]);
        cpa_commit();
    }

    for (int t = 0; t < 64; t++) {
        const int par = t & 1;
        const int jbase = (jh * 64 + t) * 64;

        cpa_wait0();
        __syncthreads();

        if (t + 1 < 64) {
            const int jbn = (jh * 64 + t + 1) * 64;
#pragma unroll
            for (int it = 0; it < 4; it++) {
                int g = tid + it * 256;
                int hh = g >> 9, rem = g & 511, ff = rem >> 3, cc = rem & 7;
                cpa16(&Bs[par ^ 1][hh][ff][cc * 8], &g_WhT_bf[hh][ff][jbn + cc * 8]);
            }
            if (tid < 128)
                cpa4(&mk[par ^ 1][tid >> 1][tid & 1],
                     &g_mask32[i0 + (tid >> 1)][(jh * 64 + t + 1) * 2 + (tid & 1)]);
            cpa_commit();
        }

        const uint32_t mw0 = mk[par][R0][ks], mw1 = mk[par][R1][ks];
        const uint32_t mw2 = mk[par][R2][ks], mw3 = mk[par][R3][ks];

#pragma unroll
        for (int kk = 0; kk < 2; kk++) {
            const int base = ks * 32 + kk * 16;
            const int shlo = base + 2 * lb, shhi = shlo + 8;
            const int blo = kk * 16 + 2 * lb, bhi = blo + 8;
            const int jb2 = jbase + shlo;
            const uint32_t tb0 = *(const uint32_t*)&g_Bbf[h][jb2];
            const uint32_t tb1 = *(const uint32_t*)&g_Bbf[h][jb2 + 8];
            const uint32_t t50 = *(const uint32_t*)&g_B5bf[h][jb2];
            const uint32_t t51 = *(const uint32_t*)&g_B5bf[h][jb2 + 8];

            uint32_t a0[4], a1[4];
            a0[0] = bfmax(bfmul(fA[0], tb0), bfmul(fK[0], t50)) & mexp(mw0, blo);
            a0[1] = bfmax(bfmul(fA[1], tb0), bfmul(fK[1], t50)) & mexp(mw1, blo);
            a0[2] = bfmax(bfmul(fA[0], tb1), bfmul(fK[0], t51)) & mexp(mw0, bhi);
            a0[3] = bfmax(bfmul(fA[1], tb1), bfmul(fK[1], t51)) & mexp(mw1, bhi);
            a1[0] = bfmax(bfmul(fA[2], tb0), bfmul(fK[2], t50)) & mexp(mw2, blo);
            a1[1] = bfmax(bfmul(fA[3], tb0), bfmul(fK[3], t50)) & mexp(mw3, blo);
            a1[2] = bfmax(bfmul(fA[2], tb1), bfmul(fK[2], t51)) & mexp(mw2, bhi);
            a1[3] = bfmax(bfmul(fA[3], tb1), bfmul(fK[3], t51)) & mexp(mw3, bhi);

#pragma unroll
            for (int cb = 0; cb < 9; cb++) {
                const uint32_t b0 = *(const uint32_t*)&Bs[par][h][cb * 8 + la][shlo];
                const uint32_t b1 = *(const uint32_t*)&Bs[par][h][cb * 8 + la][shhi];
                mma16(acc[0][cb], a0[0], a0[1], a0[2], a0[3], b0, b1);
                mma16(acc[1][cb], a1[0], a1[1], a1[2], a1[3], b0, b1);
            }
        }
    }

    const int pi = jh * 2 + ks;
#pragma unroll
    for (int mb = 0; mb < 2; mb++) {
        const int rlo = i0 + 32 * p + mb * 16 + la, rhi = rlo + 8;
#pragma unroll
        for (int cb = 0; cb < 8; cb++) {
            *(float2*)&g_p1[pi][h][rlo][cb * 8 + 2 * lb] =
                make_float2(acc[mb][cb][0], acc[mb][cb][1]);
            *(float2*)&g_p1[pi][h][rhi][cb * 8 + 2 * lb] =
                make_float2(acc[mb][cb][2], acc[mb][cb][3]);
        }
        if (lb == 0) {
            g_p1[pi][h][rlo][64] = acc[mb][8][0];
            g_p1[pi][h][rhi][64] = acc[mb][8][2];
        }
    }
}

// ---------------- K6: combine layer-1 + Wh2 = h @ W_out + fused u2/v2 ----------------
__global__ void k_gemm2(const float* __restrict__ W_out, const float* __restrict__ a_out) {
    __shared__ float zi[16][2];
    __shared__ float hs[16][128];
    __shared__ float ws[128][16];
    const int tid = threadIdx.x, i0 = blockIdx.x * 16;

    if (tid < 32) {
        const int r = tid >> 1, h = tid & 1;
        float Z = 0.f;
#pragma unroll
        for (int pi = 0; pi < 4; pi++) Z += g_p1[pi][h][i0 + r][64];
        zi[r][h] = 1.0f / Z;
    }
#pragma unroll
    for (int it = 0; it < 2; it++)
        ((float4*)ws)[tid + it * 256] = ((const float4*)W_out)[tid + it * 256];
    __syncthreads();

#pragma unroll
    for (int it = 0; it < 2; it++) {
        int idx = tid + it * 256;
        int r = idx >> 5, c4 = (idx & 31) * 4;
        int h = c4 >> 6, f = c4 & 63;
        float4 s = make_float4(0.f, 0.f, 0.f, 0.f);
#pragma unroll
        for (int pi = 0; pi < 4; pi++) {
            float4 v = *(const float4*)&g_p1[pi][h][i0 + r][f];
            s.x += v.x; s.y += v.y; s.z += v.z; s.w += v.w;
        }
        const float iv = zi[r][h];
        *(float4*)&hs[r][c4] = make_float4(s.x * iv, s.y * iv, s.z * iv, s.w * iv);
    }
    __syncthreads();

    const int r = tid >> 4, f = tid & 15;
    float acc = 0.f;
#pragma unroll 8
    for (int k = 0; k < 128; k++) acc = fmaf(hs[r][k], ws[k][f], acc);
    g_Wh2[i0 + r][f] = acc;
    g_Wh2T_bf[f][i0 + r] = __float2bfloat16(acc);

    float pu = acc * a_out[f];
    float pv = acc * a_out[16 + f];
#pragma unroll
    for (int o = 8; o; o >>= 1) {
        pu += __shfl_xor_sync(0xffffffffu, pu, o);
        pv += __shfl_xor_sync(0xffffffffu, pv, o);
    }
    if ((tid & 15) == 0) { g_u2[i0 + r] = pu; g_v2[i0 + r] = pv; }
}

// ---------------- K9: output attention, Kt=128, cp.async staging ----------------
// 8 warps: mb = warp>>1 (0..3), ks = warp&1 (64-k half).
__global__ __launch_bounds__(256, 2) void k_attn2() {
    __shared__ __align__(16) unsigned short Bs2[2][24][136];  // row 16 = ones
    __shared__ uint32_t mk2[2][64][4];

    const int tid = threadIdx.x, lane = tid & 31, warp = tid >> 5;
    const int i0 = blockIdx.x * 64;
    const int jh = blockIdx.y;
    const int mb = warp >> 1, ks = warp & 1;
    const int la = lane >> 2, lb = lane & 3;

    const int R0 = mb * 16 + la, R1 = R0 + 8;
    uint32_t fA[2], fK[2];
    {
        float a0 = g_A2[i0 + R0], a1 = g_A2[i0 + R1];
        float k0 = g_A5K2[i0 + R0], k1 = g_A5K2[i0 + R1];
        fA[0] = pack_bf(a0, a0); fA[1] = pack_bf(a1, a1);
        fK[0] = pack_bf(k0, k0); fK[1] = pack_bf(k1, k1);
    }
    // ones / zero rows (16..23); 68 words per 136-short row
    for (int i = tid; i < 2 * 8 * 68; i += 256) {
        int b = i / 544, rr = (i % 544) / 68, wi = i % 68;
        ((uint32_t*)&Bs2[b][16 + rr][0])[wi] = (rr == 0) ? 0x3F803F80u : 0u;
    }

    float acc[3][4] = {};

    {
        const int jb = jh * 4096;
        {
            int ff = tid >> 4, cc = tid & 15;
            cpa16(&Bs2[0][ff][cc * 8], &g_Wh2T_bf[ff][jb + cc * 8]);
        }
        cpa4(&mk2[0][tid >> 2][tid & 3], &g_mask32[i0 + (tid >> 2)][jh * 128 + (tid & 3)]);
        cpa_commit();
    }

    for (int t = 0; t < 32; t++) {
        const int par = t & 1;
        const int jbase = (jh * 32 + t) * 128;

        cpa_wait0();
        __syncthreads();

        if (t + 1 < 32) {
            const int jbn = (jh * 32 + t + 1) * 128;
            {
                int ff = tid >> 4, cc = tid & 15;
                cpa16(&Bs2[par ^ 1][ff][cc * 8], &g_Wh2T_bf[ff][jbn + cc * 8]);
            }
            cpa4(&mk2[par ^ 1][tid >> 2][tid & 3],
                 &g_mask32[i0 + (tid >> 2)][(jh * 32 + t + 1) * 4 + (tid & 3)]);
            cpa_commit();
        }

#pragma unroll
        for (int kk = 0; kk < 4; kk++) {
            const int base = ks * 64 + kk * 16;
            const int shlo = base + 2 * lb, shhi = shlo + 8;
            const int mwi = ks * 2 + (kk >> 1);
            const int blo = (kk & 1) * 16 + 2 * lb, bhi = blo + 8;
            const uint32_t mw0 = mk2[par][R0][mwi], mw1 = mk2[par][R1][mwi];
            const int jb2 = jbase + shlo;
            const uint32_t tb0 = *(const uint32_t*)&g_B2bf[jb2];
            const uint32_t tb1 = *(const uint32_t*)&g_B2bf[jb2 + 8];
            const uint32_t t50 = *(const uint32_t*)&g_B52bf[jb2];
            const uint32_t t51 = *(const uint32_t*)&g_B52bf[jb2 + 8];

            uint32_t a0, a1, a2, a3;
            a0 = bfmax(bfmul(fA[0], tb0), bfmul(fK[0], t50)) & mexp(mw0, blo);
            a1 = bfmax(bfmul(fA[1], tb0), bfmul(fK[1], t50)) & mexp(mw1, blo);
            a2 = bfmax(bfmul(fA[0], tb1), bfmul(fK[0], t51)) & mexp(mw0, bhi);
            a3 = bfmax(bfmul(fA[1], tb1), bfmul(fK[1], t51)) & mexp(mw1, bhi);

#pragma unroll
            for (int cb = 0; cb < 3; cb++) {
                const uint32_t b0 = *(const uint32_t*)&Bs2[par][cb * 8 + la][shlo];
                const uint32_t b1 = *(const uint32_t*)&Bs2[par][cb * 8 + la][shhi];
                mma16(acc[cb], a0, a1, a2, a3, b0, b1);
            }
        }
    }

    const int pi = jh * 2 + ks;
    const int rlo = i0 + R0, rhi = i0 + R1;
#pragma unroll
    for (int cb = 0; cb < 2; cb++) {
        *(float2*)&g_p2[pi][rlo][cb * 8 + 2 * lb] = make_float2(acc[cb][0], acc[cb][1]);
        *(float2*)&g_p2[pi][rhi][cb * 8 + 2 * lb] = make_float2(acc[cb][2], acc[cb][3]);
    }
    if (lb == 0) {
        g_p2[pi][rlo][16] = acc[2][0];
        g_p2[pi][rhi][16] = acc[2][2];
    }
}

// ---------------- K10: combine + elu + log_softmax ----------------
__global__ void k_fin2(float* __restrict__ out) {
    const int tid = threadIdx.x;
    const int row = blockIdx.x * 64 + (tid >> 2);
    const int qq = tid & 3;
    float Z = 0.f;
#pragma unroll
    for (int pi = 0; pi < 4; pi++) Z += g_p2[pi][row][16];
    const float inv = 1.0f / Z;
    float v[4] = {0.f, 0.f, 0.f, 0.f};
#pragma unroll
    for (int pi = 0; pi < 4; pi++) {
        float4 a = *(const float4*)&g_p2[pi][row][qq * 4];
        v[0] += a.x; v[1] += a.y; v[2] += a.z; v[3] += a.w;
    }
    float mx = -3.0e38f;
#pragma unroll
    for (int i = 0; i < 4; i++) {
        v[i] *= inv;
        v[i] = (v[i] > 0.f) ? v[i] : expm1f(v[i]);
        mx = fmaxf(mx, v[i]);
    }
    mx = fmaxf(mx, __shfl_xor_sync(0xffffffffu, mx, 1));
    mx = fmaxf(mx, __shfl_xor_sync(0xffffffffu, mx, 2));
    float s = 0.f;
#pragma unroll
    for (int i = 0; i < 4; i++) s += expf(v[i] - mx);
    s += __shfl_xor_sync(0xffffffffu, s, 1);
    s += __shfl_xor_sync(0xffffffffu, s, 2);
    const float lse = mx + logf(s);
    *(float4*)&out[(size_t)row * 16 + qq * 4] =
        make_float4(v[0] - lse, v[1] - lse, v[2] - lse, v[3] - lse);
}

// ---------------- launch ----------------
extern "C" void kernel_launch(void* const* d_in, const int* in_sizes, int n_in,
                              void* d_out, int out_size) {
    const float* x       = (const float*)d_in[0];
    const int*   adj     = (const int*)  d_in[1];
    const float* W_heads = (const float*)d_in[2];
    const float* a_heads = (const float*)d_in[3];
    const float* W_out   = (const float*)d_in[4];
    const float* a_out   = (const float*)d_in[5];
    float* out = (float*)d_out;

    k_pack<<<65536, 256>>>(adj);
    k_gemm1<<<dim3(N8 / 64, 2), 256>>>(x, W_heads, a_heads);
    k_max<<<4, 1024>>>(0);
    k_exp1<<<dim3(N8 / 256, 2), 256>>>();
    k_attn1<<<dim3(N8 / 64, 2), 256>>>();
    k_gemm2<<<N8 / 16, 256>>>(W_out, a_out);
    k_max<<<2, 1024>>>(4);
    k_exp2<<<N8 / 256, 256>>>();
    k_attn2<<<dim3(N8 / 64, 2), 256>>>();
    k_fin2<<<N8 / 64, 256>>>(out);
}

// round 16
// speedup vs baseline: 5.3975x; 1.0231x over previous
#include <cuda_runtime.h>
#include <cuda_bf16.h>
#include <math.h>
#include <stdint.h>

#define N8   8192
#define FIN  64
#define HID  64

// ---------------- device scratch ----------------
__device__ float g_Wh[2][N8][HID];
__device__ __align__(16) __nv_bfloat16 g_WhT_bf[2][HID][N8];
__device__ float g_u[2][N8], g_v[2][N8];
__device__ float g_A[2][N8], g_A5K[2][N8];
__device__ __align__(16) __nv_bfloat16 g_Bbf[2][N8];
__device__ __align__(16) __nv_bfloat16 g_B5bf[2][N8];
__device__ __align__(16) float g_p1[4][2][N8][72];   // [jh*2+ks][h][row][0..63 acc, 64 Z]
__device__ float g_Wh2[N8][16];
__device__ __align__(16) __nv_bfloat16 g_Wh2T_bf[16][N8];
__device__ float g_u2[N8], g_v2[N8];
__device__ float g_A2[N8], g_A5K2[N8];
__device__ __align__(16) __nv_bfloat16 g_B2bf[N8];
__device__ __align__(16) __nv_bfloat16 g_B52bf[N8];
__device__ __align__(16) float g_p2[4][N8][20];      // [jh*2+ks][row][0..15 acc, 16 Z]
__device__ __align__(16) uint32_t g_mask32[N8][256];
__device__ float g_max[8];

// ---------------- helpers ----------------
__device__ __forceinline__ uint32_t pack_bf(float hi, float lo) {
    uint32_t d; asm("cvt.rn.bf16x2.f32 %0, %1, %2;" : "=r"(d) : "f"(hi), "f"(lo));
    return d;
}
__device__ __forceinline__ uint32_t bfmul(uint32_t a, uint32_t b) {
    uint32_t d; asm("mul.rn.bf16x2 %0, %1, %2;" : "=r"(d) : "r"(a), "r"(b)); return d;
}
__device__ __forceinline__ uint32_t bfmax(uint32_t a, uint32_t b) {
    uint32_t d; asm("max.bf16x2 %0, %1, %2;" : "=r"(d) : "r"(a), "r"(b)); return d;
}
__device__ __forceinline__ uint32_t mexp(uint32_t mw, int sh) {
    uint32_t b = mw >> sh;
    return ((b & 1u) ? 0x0000FFFFu : 0u) | ((b & 2u) ? 0xFFFF0000u : 0u);
}
__device__ __forceinline__ void mma16(float* d, uint32_t a0, uint32_t a1, uint32_t a2,
                                      uint32_t a3, uint32_t b0, uint32_t b1) {
    asm volatile("mma.sync.aligned.m16n8k16.row.col.f32.bf16.bf16.f32 "
                 "{%0,%1,%2,%3}, {%4,%5,%6,%7}, {%8,%9}, {%0,%1,%2,%3};"
                 : "+f"(d[0]), "+f"(d[1]), "+f"(d[2]), "+f"(d[3])
                 : "r"(a0), "r"(a1), "r"(a2), "r"(a3), "r"(b0), "r"(b1));
}
__device__ __forceinline__ int4 ldcs4(const int* p) {
    int4 v;
    asm volatile("ld.global.cs.v4.s32 {%0,%1,%2,%3}, [%4];"
                 : "=r"(v.x), "=r"(v.y), "=r"(v.z), "=r"(v.w) : "l"(p));
    return v;
}
__device__ __forceinline__ void cpa16(const void* smem, const void* g) {
    uint32_t a = (uint32_t)__cvta_generic_to_shared(smem);
    asm volatile("cp.async.cg.shared.global [%0], [%1], 16;" :: "r"(a), "l"(g));
}
__device__ __forceinline__ void cpa4(const void* smem, const void* g) {
    uint32_t a = (uint32_t)__cvta_generic_to_shared(smem);
    asm volatile("cp.async.ca.shared.global [%0], [%1], 4;" :: "r"(a), "l"(g));
}
__device__ __forceinline__ void cpa_commit() { asm volatile("cp.async.commit_group;" ::: "memory"); }
__device__ __forceinline__ void cpa_wait0()  { asm volatile("cp.async.wait_group 0;" ::: "memory"); }

// pack 16 adjacency ints -> 16 bits
__device__ __forceinline__ uint32_t pk16(int4 a, int4 b, int4 c, int4 d) {
    uint32_t m = 0;
    m |= (a.x != 0) ? 1u : 0u;       m |= (a.y != 0) ? 2u : 0u;
    m |= (a.z != 0) ? 4u : 0u;       m |= (a.w != 0) ? 8u : 0u;
    m |= (b.x != 0) ? 16u : 0u;      m |= (b.y != 0) ? 32u : 0u;
    m |= (b.z != 0) ? 64u : 0u;      m |= (b.w != 0) ? 128u : 0u;
    m |= (c.x != 0) ? 256u : 0u;     m |= (c.y != 0) ? 512u : 0u;
    m |= (c.z != 0) ? 1024u : 0u;    m |= (c.w != 0) ? 2048u : 0u;
    m |= (d.x != 0) ? 4096u : 0u;    m |= (d.y != 0) ? 8192u : 0u;
    m |= (d.z != 0) ? 16384u : 0u;   m |= (d.w != 0) ? 32768u : 0u;
    return m;
}

// ---------------- K1: Wh = x @ W_h (+ bf16 T copy + fused u/v) ----------------
__global__ void k_gemm1(const float* __restrict__ x, const float* __restrict__ W_heads,
                        const float* __restrict__ a_heads) {
    __shared__ float xs[64][FIN];
    __shared__ float ws[FIN][HID];
    const int h = blockIdx.y, i0 = blockIdx.x * 64, tid = threadIdx.x;
    const float4* xg = (const float4*)(x + (size_t)i0 * FIN);
    const float4* wg = (const float4*)(W_heads + (size_t)h * FIN * HID);
#pragma unroll
    for (int it = 0; it < 4; it++) ((float4*)xs)[tid + it * 256] = xg[tid + it * 256];
#pragma unroll
    for (int it = 0; it < 4; it++) ((float4*)ws)[tid + it * 256] = wg[tid + it * 256];
    __syncthreads();
    const int f = (tid & 15) * 4, ig = tid >> 4;
    float acc[4][4] = {};
#pragma unroll 4
    for (int k = 0; k < FIN; k++) {
        float4 wv = *(const float4*)&ws[k][f];
#pragma unroll
        for (int r = 0; r < 4; r++) {
            float xv = xs[ig * 4 + r][k];
            acc[r][0] = fmaf(xv, wv.x, acc[r][0]);
            acc[r][1] = fmaf(xv, wv.y, acc[r][1]);
            acc[r][2] = fmaf(xv, wv.z, acc[r][2]);
            acc[r][3] = fmaf(xv, wv.w, acc[r][3]);
        }
    }
#pragma unroll
    for (int r = 0; r < 4; r++) {
        const int row = i0 + ig * 4 + r;
        *(float4*)&g_Wh[h][row][f] = make_float4(acc[r][0], acc[r][1], acc[r][2], acc[r][3]);
#pragma unroll
        for (int c = 0; c < 4; c++) g_WhT_bf[h][f + c][row] = __float2bfloat16(acc[r][c]);
    }
    const float* a = a_heads + (size_t)h * 2 * HID;
    const float4 au = *(const float4*)&a[f];
    const float4 av = *(const float4*)&a[HID + f];
    float pu[4], pv[4];
#pragma unroll
    for (int r = 0; r < 4; r++) {
        pu[r] = acc[r][0] * au.x + acc[r][1] * au.y + acc[r][2] * au.z + acc[r][3] * au.w;
        pv[r] = acc[r][0] * av.x + acc[r][1] * av.y + acc[r][2] * av.z + acc[r][3] * av.w;
    }
#pragma unroll
    for (int o = 8; o; o >>= 1)
#pragma unroll
        for (int r = 0; r < 4; r++) {
            pu[r] += __shfl_xor_sync(0xffffffffu, pu[r], o);
            pv[r] += __shfl_xor_sync(0xffffffffu, pv[r], o);
        }
    if ((tid & 15) == 0)
#pragma unroll
        for (int r = 0; r < 4; r++) {
            g_u[h][i0 + ig * 4 + r] = pu[r];
            g_v[h][i0 + ig * 4 + r] = pv[r];
        }
}

// ---------------- K3: global max ----------------
__global__ void k_max(int base) {
    const int which = base + blockIdx.x;
    const float* src = (which == 0) ? g_u[0] : (which == 1) ? g_v[0] :
                       (which == 2) ? g_u[1] : (which == 3) ? g_v[1] :
                       (which == 4) ? g_u2 : g_v2;
    __shared__ float red[32];
    float m = -3.0e38f;
    for (int i = threadIdx.x; i < N8; i += blockDim.x) m = fmaxf(m, src[i]);
#pragma unroll
    for (int o = 16; o; o >>= 1) m = fmaxf(m, __shfl_xor_sync(0xffffffffu, m, o));
    if ((threadIdx.x & 31) == 0) red[threadIdx.x >> 5] = m;
    __syncthreads();
    if (threadIdx.x < 32) {
        float mm = red[threadIdx.x];
#pragma unroll
        for (int o = 16; o; o >>= 1) mm = fmaxf(mm, __shfl_xor_sync(0xffffffffu, mm, o));
        if (threadIdx.x == 0) g_max[which] = mm;
    }
}

// ---------------- K4: exp tables ----------------
__global__ void k_exp1() {
    const int i = blockIdx.x * 256 + threadIdx.x, h = blockIdx.y;
    const float um = g_max[h * 2], vm = g_max[h * 2 + 1], c = um + vm;
    const float u = g_u[h][i], v = g_v[h][i];
    g_A[h][i]    = expf(u - um);
    g_A5K[h][i]  = expf(0.2f * (u - um) - 0.8f * c);
    g_Bbf[h][i]  = __float2bfloat16(expf(v - vm));
    g_B5bf[h][i] = __float2bfloat16(expf(0.2f * (v - vm)));
}
__global__ void k_exp2() {
    const int i = blockIdx.x * 256 + threadIdx.x;
    const float um = g_max[4], vm = g_max[5], c = um + vm;
    const float u = g_u2[i], v = g_v2[i];
    g_A2[i]    = expf(u - um);
    g_A5K2[i]  = expf(0.2f * (u - um) - 0.8f * c);
    g_B2bf[i]  = __float2bfloat16(expf(v - vm));
    g_B52bf[i] = __float2bfloat16(expf(0.2f * (v - vm)));
}

// ---------------- K5: layer-1 attention, fused adj-pack + w-gen + mma ----------------
// 8 warps: h = warp>>2, p = (warp>>1)&1 (row half), ks = warp&1 (k half).
__global__ __launch_bounds__(256, 2) void k_attn1(const int* __restrict__ adj) {
    __shared__ __align__(16) unsigned short Bs[2][2][72][72];  // [buf][h][feat][k], 64=ones
    __shared__ uint32_t mk[2][64][2];

    const int tid = threadIdx.x, lane = tid & 31, warp = tid >> 5;
    const int i0 = blockIdx.x * 64;
    const int jh = blockIdx.y;
    const int h = warp >> 2, p = (warp >> 1) & 1, ks = warp & 1;
    const int la = lane >> 2, lb = lane & 3;

    // packer role: row = tid>>2, 16-j segment = (tid&3)*16
    const int prow = i0 + (tid >> 2);
    const int pseg = (tid & 3) * 16;
    const int mwi  = (tid & 3) >> 1;
    const int hw   = ((tid & 3) & 1) * 16;

    const int R0 = 32 * p + la, R1 = R0 + 8, R2 = R0 + 16, R3 = R0 + 24;
    uint32_t fA[4], fK[4];
    {
        float a0 = g_A[h][i0 + R0], a1 = g_A[h][i0 + R1];
        float a2 = g_A[h][i0 + R2], a3 = g_A[h][i0 + R3];
        float k0 = g_A5K[h][i0 + R0], k1 = g_A5K[h][i0 + R1];
        float k2 = g_A5K[h][i0 + R2], k3 = g_A5K[h][i0 + R3];
        fA[0] = pack_bf(a0, a0); fA[1] = pack_bf(a1, a1);
        fA[2] = pack_bf(a2, a2); fA[3] = pack_bf(a3, a3);
        fK[0] = pack_bf(k0, k0); fK[1] = pack_bf(k1, k1);
        fK[2] = pack_bf(k2, k2); fK[3] = pack_bf(k3, k3);
    }

    // ones / zero rows (64..71)
    for (int i = tid; i < 2 * 2 * 8 * 36; i += 256) {
        int b = i / 576, rem = i % 576, hh = rem / 288, rr = (rem % 288) / 36, wi = i % 36;
        ((uint32_t*)&Bs[b][hh][64 + rr][0])[wi] = (rr == 0) ? 0x3F803F80u : 0u;
    }

    float acc[2][9][4] = {};
    uint32_t pword;

    // tile 0: load + pack adj, stage B via cp.async
    {
        const int jb = jh * 4096;
        const int* ap = adj + (size_t)prow * N8 + jb + pseg;
        int4 q0 = ldcs4(ap), q1 = ldcs4(ap + 4), q2 = ldcs4(ap + 8), q3 = ldcs4(ap + 12);
        uint32_t mw = pk16(q0, q1, q2, q3) << hw;
        pword = mw | __shfl_xor_sync(0xffffffffu, mw, 1);
#pragma unroll
        for (int it = 0; it < 4; it++) {
            int g = tid + it * 256;
            int hh = g >> 9, rem = g & 511, ff = rem >> 3, cc = rem & 7;
            cpa16(&Bs[0][hh][ff][cc * 8], &g_WhT_bf[hh][ff][jb + cc * 8]);
        }
        cpa_commit();
    }

    for (int t = 0; t < 64; t++) {
        const int par = t & 1;
        const int jbase = (jh * 64 + t) * 64;

        // publish masks for tile t (computed last iteration / prolog)
        if ((tid & 1) == 0) {
            mk[par][tid >> 2][mwi] = pword;
            g_mask32[prow][(jbase >> 5) + mwi] = pword;
        }

        cpa_wait0();
        __syncthreads();

        int4 q0, q1, q2, q3;
        bool more = (t + 1 < 64);
        if (more) {
            const int jbn = (jh * 64 + t + 1) * 64;
#pragma unroll
            for (int it = 0; it < 4; it++) {
                int g = tid + it * 256;
                int hh = g >> 9, rem = g & 511, ff = rem >> 3, cc = rem & 7;
                cpa16(&Bs[par ^ 1][hh][ff][cc * 8], &g_WhT_bf[hh][ff][jbn + cc * 8]);
            }
            cpa_commit();
            const int* ap = adj + (size_t)prow * N8 + jbn + pseg;
            q0 = ldcs4(ap); q1 = ldcs4(ap + 4); q2 = ldcs4(ap + 8); q3 = ldcs4(ap + 12);
        }

        const uint32_t mw0 = mk[par][R0][ks], mw1 = mk[par][R1][ks];
        const uint32_t mw2 = mk[par][R2][ks], mw3 = mk[par][R3][ks];

#pragma unroll
        for (int kk = 0; kk < 2; kk++) {
            const int base = ks * 32 + kk * 16;
            const int shlo = base + 2 * lb, shhi = shlo + 8;
            const int blo = kk * 16 + 2 * lb, bhi = blo + 8;
            const int jb2 = jbase + shlo;
            const uint32_t tb0 = *(const uint32_t*)&g_Bbf[h][jb2];
            const uint32_t tb1 = *(const uint32_t*)&g_Bbf[h][jb2 + 8];
            const uint32_t t50 = *(const uint32_t*)&g_B5bf[h][jb2];
            const uint32_t t51 = *(const uint32_t*)&g_B5bf[h][jb2 + 8];

            uint32_t a0[4], a1[4];
            a0[0] = bfmax(bfmul(fA[0], tb0), bfmul(fK[0], t50)) & mexp(mw0, blo);
            a0[1] = bfmax(bfmul(fA[1], tb0), bfmul(fK[1], t50)) & mexp(mw1, blo);
            a0[2] = bfmax(bfmul(fA[0], tb1), bfmul(fK[0], t51)) & mexp(mw0, bhi);
            a0[3] = bfmax(bfmul(fA[1], tb1), bfmul(fK[1], t51)) & mexp(mw1, bhi);
            a1[0] = bfmax(bfmul(fA[2], tb0), bfmul(fK[2], t50)) & mexp(mw2, blo);
            a1[1] = bfmax(bfmul(fA[3], tb0), bfmul(fK[3], t50)) & mexp(mw3, blo);
            a1[2] = bfmax(bfmul(fA[2], tb1), bfmul(fK[2], t51)) & mexp(mw2, bhi);
            a1[3] = bfmax(bfmul(fA[3], tb1), bfmul(fK[3], t51)) & mexp(mw3, bhi);

#pragma unroll
            for (int cb = 0; cb < 9; cb++) {
                const uint32_t b0 = *(const uint32_t*)&Bs[par][h][cb * 8 + la][shlo];
                const uint32_t b1 = *(const uint32_t*)&Bs[par][h][cb * 8 + la][shhi];
                mma16(acc[0][cb], a0[0], a0[1], a0[2], a0[3], b0, b1);
                mma16(acc[1][cb], a1[0], a1[1], a1[2], a1[3], b0, b1);
            }
        }

        // pack next tile's masks (adj loads overlap the mma phase above)
        if (more) {
            uint32_t mw = pk16(q0, q1, q2, q3) << hw;
            pword = mw | __shfl_xor_sync(0xffffffffu, mw, 1);
        }
    }

    const int pi = jh * 2 + ks;
#pragma unroll
    for (int mb = 0; mb < 2; mb++) {
        const int rlo = i0 + 32 * p + mb * 16 + la, rhi = rlo + 8;
#pragma unroll
        for (int cb = 0; cb < 8; cb++) {
            *(float2*)&g_p1[pi][h][rlo][cb * 8 + 2 * lb] =
                make_float2(acc[mb][cb][0], acc[mb][cb][1]);
            *(float2*)&g_p1[pi][h][rhi][cb * 8 + 2 * lb] =
                make_float2(acc[mb][cb][2], acc[mb][cb][3]);
        }
        if (lb == 0) {
            g_p1[pi][h][rlo][64] = acc[mb][8][0];
            g_p1[pi][h][rhi][64] = acc[mb][8][2];
        }
    }
}

// ---------------- K6: combine layer-1 + Wh2 = h @ W_out + fused u2/v2 ----------------
__global__ void k_gemm2(const float* __restrict__ W_out, const float* __restrict__ a_out) {
    __shared__ float zi[16][2];
    __shared__ float hs[16][128];
    __shared__ float ws[128][16];
    const int tid = threadIdx.x, i0 = blockIdx.x * 16;

    if (tid < 32) {
        const int r = tid >> 1, h = tid & 1;
        float Z = 0.f;
#pragma unroll
        for (int pi = 0; pi < 4; pi++) Z += g_p1[pi][h][i0 + r][64];
        zi[r][h] = 1.0f / Z;
    }
#pragma unroll
    for (int it = 0; it < 2; it++)
        ((float4*)ws)[tid + it * 256] = ((const float4*)W_out)[tid + it * 256];
    __syncthreads();

#pragma unroll
    for (int it = 0; it < 2; it++) {
        int idx = tid + it * 256;
        int r = idx >> 5, c4 = (idx & 31) * 4;
        int h = c4 >> 6, f = c4 & 63;
        float4 s = make_float4(0.f, 0.f, 0.f, 0.f);
#pragma unroll
        for (int pi = 0; pi < 4; pi++) {
            float4 v = *(const float4*)&g_p1[pi][h][i0 + r][f];
            s.x += v.x; s.y += v.y; s.z += v.z; s.w += v.w;
        }
        const float iv = zi[r][h];
        *(float4*)&hs[r][c4] = make_float4(s.x * iv, s.y * iv, s.z * iv, s.w * iv);
    }
    __syncthreads();

    const int r = tid >> 4, f = tid & 15;
    float acc = 0.f;
#pragma unroll 8
    for (int k = 0; k < 128; k++) acc = fmaf(hs[r][k], ws[k][f], acc);
    g_Wh2[i0 + r][f] = acc;
    g_Wh2T_bf[f][i0 + r] = __float2bfloat16(acc);

    float pu = acc * a_out[f];
    float pv = acc * a_out[16 + f];
#pragma unroll
    for (int o = 8; o; o >>= 1) {
        pu += __shfl_xor_sync(0xffffffffu, pu, o);
        pv += __shfl_xor_sync(0xffffffffu, pv, o);
    }
    if ((tid & 15) == 0) { g_u2[i0 + r] = pu; g_v2[i0 + r] = pv; }
}

// ---------------- K9: output attention, Kt=128, cp.async staging ----------------
// 8 warps: mb = warp>>1 (0..3), ks = warp&1 (64-k half).
__global__ __launch_bounds__(256, 2) void k_attn2() {
    __shared__ __align__(16) unsigned short Bs2[2][24][136];  // row 16 = ones
    __shared__ uint32_t mk2[2][64][4];

    const int tid = threadIdx.x, lane = tid & 31, warp = tid >> 5;
    const int i0 = blockIdx.x * 64;
    const int jh = blockIdx.y;
    const int mb = warp >> 1, ks = warp & 1;
    const int la = lane >> 2, lb = lane & 3;

    const int R0 = mb * 16 + la, R1 = R0 + 8;
    uint32_t fA[2], fK[2];
    {
        float a0 = g_A2[i0 + R0], a1 = g_A2[i0 + R1];
        float k0 = g_A5K2[i0 + R0], k1 = g_A5K2[i0 + R1];
        fA[0] = pack_bf(a0, a0); fA[1] = pack_bf(a1, a1);
        fK[0] = pack_bf(k0, k0); fK[1] = pack_bf(k1, k1);
    }
    for (int i = tid; i < 2 * 8 * 68; i += 256) {
        int b = i / 544, rr = (i % 544) / 68, wi = i % 68;
        ((uint32_t*)&Bs2[b][16 + rr][0])[wi] = (rr == 0) ? 0x3F803F80u : 0u;
    }

    float acc[3][4] = {};

    {
        const int jb = jh * 4096;
        {
            int ff = tid >> 4, cc = tid & 15;
            cpa16(&Bs2[0][ff][cc * 8], &g_Wh2T_bf[ff][jb + cc * 8]);
        }
        cpa4(&mk2[0][tid >> 2][tid & 3], &g_mask32[i0 + (tid >> 2)][jh * 128 + (tid & 3)]);
        cpa_commit();
    }

    for (int t = 0; t < 32; t++) {
        const int par = t & 1;
        const int jbase = (jh * 32 + t) * 128;

        cpa_wait0();
        __syncthreads();

        if (t + 1 < 32) {
            const int jbn = (jh * 32 + t + 1) * 128;
            {
                int ff = tid >> 4, cc = tid & 15;
                cpa16(&Bs2[par ^ 1][ff][cc * 8], &g_Wh2T_bf[ff][jbn + cc * 8]);
            }
            cpa4(&mk2[par ^ 1][tid >> 2][tid & 3],
                 &g_mask32[i0 + (tid >> 2)][(jh * 32 + t + 1) * 4 + (tid & 3)]);
            cpa_commit();
        }

#pragma unroll
        for (int kk = 0; kk < 4; kk++) {
            const int base = ks * 64 + kk * 16;
            const int shlo = base + 2 * lb, shhi = shlo + 8;
            const int mwi = ks * 2 + (kk >> 1);
            const int blo = (kk & 1) * 16 + 2 * lb, bhi = blo + 8;
            const uint32_t mw0 = mk2[par][R0][mwi], mw1 = mk2[par][R1][mwi];
            const int jb2 = jbase + shlo;
            const uint32_t tb0 = *(const uint32_t*)&g_B2bf[jb2];
            const uint32_t tb1 = *(const uint32_t*)&g_B2bf[jb2 + 8];
            const uint32_t t50 = *(const uint32_t*)&g_B52bf[jb2];
            const uint32_t t51 = *(const uint32_t*)&g_B52bf[jb2 + 8];

            uint32_t a0, a1, a2, a3;
            a0 = bfmax(bfmul(fA[0], tb0), bfmul(fK[0], t50)) & mexp(mw0, blo);
            a1 = bfmax(bfmul(fA[1], tb0), bfmul(fK[1], t50)) & mexp(mw1, blo);
            a2 = bfmax(bfmul(fA[0], tb1), bfmul(fK[0], t51)) & mexp(mw0, bhi);
            a3 = bfmax(bfmul(fA[1], tb1), bfmul(fK[1], t51)) & mexp(mw1, bhi);

#pragma unroll
            for (int cb = 0; cb < 3; cb++) {
                const uint32_t b0 = *(const uint32_t*)&Bs2[par][cb * 8 + la][shlo];
                const uint32_t b1 = *(const uint32_t*)&Bs2[par][cb * 8 + la][shhi];
                mma16(acc[cb], a0, a1, a2, a3, b0, b1);
            }
        }
    }

    const int pi = jh * 2 + ks;
    const int rlo = i0 + R0, rhi = i0 + R1;
#pragma unroll
    for (int cb = 0; cb < 2; cb++) {
        *(float2*)&g_p2[pi][rlo][cb * 8 + 2 * lb] = make_float2(acc[cb][0], acc[cb][1]);
        *(float2*)&g_p2[pi][rhi][cb * 8 + 2 * lb] = make_float2(acc[cb][2], acc[cb][3]);
    }
    if (lb == 0) {
        g_p2[pi][rlo][16] = acc[2][0];
        g_p2[pi][rhi][16] = acc[2][2];
    }
}

// ---------------- K10: combine + elu + log_softmax ----------------
__global__ void k_fin2(float* __restrict__ out) {
    const int tid = threadIdx.x;
    const int row = blockIdx.x * 64 + (tid >> 2);
    const int qq = tid & 3;
    float Z = 0.f;
#pragma unroll
    for (int pi = 0; pi < 4; pi++) Z += g_p2[pi][row][16];
    const float inv = 1.0f / Z;
    float v[4] = {0.f, 0.f, 0.f, 0.f};
#pragma unroll
    for (int pi = 0; pi < 4; pi++) {
        float4 a = *(const float4*)&g_p2[pi][row][qq * 4];
        v[0] += a.x; v[1] += a.y; v[2] += a.z; v[3] += a.w;
    }
    float mx = -3.0e38f;
#pragma unroll
    for (int i = 0; i < 4; i++) {
        v[i] *= inv;
        v[i] = (v[i] > 0.f) ? v[i] : expm1f(v[i]);
        mx = fmaxf(mx, v[i]);
    }
    mx = fmaxf(mx, __shfl_xor_sync(0xffffffffu, mx, 1));
    mx = fmaxf(mx, __shfl_xor_sync(0xffffffffu, mx, 2));
    float s = 0.f;
#pragma unroll
    for (int i = 0; i < 4; i++) s += expf(v[i] - mx);
    s += __shfl_xor_sync(0xffffffffu, s, 1);
    s += __shfl_xor_sync(0xffffffffu, s, 2);
    const float lse = mx + logf(s);
    *(float4*)&out[(size_t)row * 16 + qq * 4] =
        make_float4(v[0] - lse, v[1] - lse, v[2] - lse, v[3] - lse);
}

// ---------------- launch ----------------
extern "C" void kernel_launch(void* const* d_in, const int* in_sizes, int n_in,
                              void* d_out, int out_size) {
    const float* x       = (const float*)d_in[0];
    const int*   adj     = (const int*)  d_in[1];
    const float* W_heads = (const float*)d_in[2];
    const float* a_heads = (const float*)d_in[3];
    const float* W_out   = (const float*)d_in[4];
    const float* a_out   = (const float*)d_in[5];
    float* out = (float*)d_out;

    k_gemm1<<<dim3(N8 / 64, 2), 256>>>(x, W_heads, a_heads);
    k_max<<<4, 1024>>>(0);
    k_exp1<<<dim3(N8 / 256, 2), 256>>>();
    k_attn1<<<dim3(N8 / 64, 2), 256>>>(adj);
    k_gemm2<<<N8 / 16, 256>>>(W_out, a_out);
    k_max<<<2, 1024>>>(4);
    k_exp2<<<N8 / 256, 256>>>();
    k_attn2<<<dim3(N8 / 64, 2), 256>>>();
    k_fin2<<<N8 / 64, 256>>>(out);
}